// round 9
// baseline (speedup 1.0000x reference)
#include <cuda_runtime.h>
#include <cuda_fp16.h>
#include <cstdint>

#define Bb 256
#define Tt 256
#define Hd 1024
#define Ee 256
#define LC 320
#define EIN 576   // E + L + C
#define G3 3072
#define Vv 64

#define NGH 128
#define GRID NGH
#define NTHREADS 256

// stage layout (bytes): A_hi[64x128 f16] A_lo[64x128 f16] W[96x128 f16], rows padded to 272B
#define SROW 272
#define OFF_AH 0
#define OFF_AL 17408
#define OFF_W  34816
#define STG 60928
#define SMEM_TOTAL (2 * STG)   // 121856

// ---------------- persistent device scratch ----------------
__device__ float g_ctxpart[Bb * G3];   // context @ W_ih[:,E:]^T + b_ih
__device__ float g_table[Vv * G3];     // emb @ W_ih[:,:E]^T
// full hidden-state history: slot s = h after step s-1 (slot 0 = h0)
__device__ float g_hall[(size_t)(Tt + 1) * Bb * Hd];
// fp16 hi/lo hidden tiles, row-major [buf][b(256)][k(1024)]
__device__ __align__(16) __half g_ah[2 * Bb * Hd];
__device__ __align__(16) __half g_al[2 * Bb * Hd];
// fp16 W tiles: [nt(32)][p(96)=gate*32+jl][k(1024)]
__device__ __align__(16) __half g_wf[32 * 96 * Hd];
__device__ unsigned g_count = 0;
__device__ unsigned g_phase = 0;

// ---------------- helpers ----------------
__device__ __forceinline__ uint32_t smem_u32_of(const void* p) {
    uint32_t a;
    asm("{ .reg .u64 t; cvta.to.shared.u64 t, %1; cvt.u32.u64 %0, t; }" : "=r"(a) : "l"(p));
    return a;
}
__device__ __forceinline__ unsigned long long pk2(float x, float y) {
    unsigned long long r;
    asm("mov.b64 %0, {%1, %2};" : "=l"(r) : "f"(x), "f"(y));
    return r;
}
__device__ __forceinline__ float2 unpk(unsigned long long v) {
    float2 r;
    asm("mov.b64 {%0, %1}, %2;" : "=f"(r.x), "=f"(r.y) : "l"(v));
    return r;
}
__device__ __forceinline__ void fma2(unsigned long long& d, unsigned long long a, unsigned long long b) {
    asm("fma.rn.f32x2 %0, %1, %2, %0;" : "+l"(d) : "l"(a), "l"(b));
}
__device__ __forceinline__ float sigm(float x) { return 1.f / (1.f + __expf(-x)); }
__device__ __forceinline__ float tanh_f(float x) { return 2.f / (1.f + __expf(-2.f * x)) - 1.f; }

__device__ __forceinline__ void cpa16(uint32_t d, const void* s) {
    asm volatile("cp.async.cg.shared.global [%0], [%1], 16;" :: "r"(d), "l"(s) : "memory");
}
#define CP_COMMIT() asm volatile("cp.async.commit_group;" ::: "memory")
#define CP_WAIT0()  asm volatile("cp.async.wait_group 0;" ::: "memory")

__device__ __forceinline__ void ldsm_x4(uint32_t* r, uint32_t a) {
    asm volatile("ldmatrix.sync.aligned.m8n8.x4.shared.b16 {%0,%1,%2,%3}, [%4];"
                 : "=r"(r[0]), "=r"(r[1]), "=r"(r[2]), "=r"(r[3]) : "r"(a));
}
__device__ __forceinline__ void ldsm_x2(uint32_t* r, uint32_t a) {
    asm volatile("ldmatrix.sync.aligned.m8n8.x2.shared.b16 {%0,%1}, [%2];"
                 : "=r"(r[0]), "=r"(r[1]) : "r"(a));
}
__device__ __forceinline__ void mma16816(float* c, const uint32_t* a, const uint32_t* b) {
    asm volatile("mma.sync.aligned.m16n8k16.row.col.f32.f16.f16.f32 "
                 "{%0,%1,%2,%3}, {%4,%5,%6,%7}, {%8,%9}, {%0,%1,%2,%3};"
                 : "+f"(c[0]), "+f"(c[1]), "+f"(c[2]), "+f"(c[3])
                 : "r"(a[0]), "r"(a[1]), "r"(a[2]), "r"(a[3]), "r"(b[0]), "r"(b[1]));
}

// ---------------- grid barrier ----------------
__device__ __forceinline__ void gbar(unsigned target) {
    __syncthreads();
    if (threadIdx.x == 0) {
        unsigned n;
        asm volatile("atom.add.acq_rel.gpu.u32 %0, [%1], 1;"
                     : "=r"(n) : "l"(&g_count) : "memory");
        if (n == GRID - 1) {
            g_count = 0;
            asm volatile("st.release.gpu.u32 [%0], %1;"
                         :: "l"(&g_phase), "r"(target) : "memory");
        } else {
            unsigned p;
            do {
                asm volatile("ld.acquire.gpu.u32 %0, [%1];"
                             : "=r"(p) : "l"(&g_phase) : "memory");
            } while ((int)(p - target) < 0);
        }
        __threadfence();
    }
    __syncthreads();
}

// ---------------- precompute kernels ----------------
__global__ void ctx_kernel(const float* __restrict__ z, const float* __restrict__ c,
                           const float* __restrict__ Wih, const float* __restrict__ bih) {
    __shared__ float cs[8 * LC];
    int bc = blockIdx.x;
    for (int i = threadIdx.x; i < 8 * LC; i += NTHREADS) {
        int bb = i / LC, ii = i - bb * LC;
        int b = bc * 8 + bb;
        cs[i] = (ii < 256) ? z[b * 256 + ii] : c[b * 64 + (ii - 256)];
    }
    __syncthreads();
    for (int gk = 0; gk < 12; gk++) {
        int g = threadIdx.x + gk * NTHREADS;
        float acc[8];
        float bi = bih[g];
#pragma unroll
        for (int bb = 0; bb < 8; bb++) acc[bb] = bi;
        const float* wr = Wih + (size_t)g * EIN + Ee;
        for (int ii = 0; ii < LC; ii++) {
            float w = wr[ii];
#pragma unroll
            for (int bb = 0; bb < 8; bb++) acc[bb] += w * cs[bb * LC + ii];
        }
#pragma unroll
        for (int bb = 0; bb < 8; bb++) g_ctxpart[(size_t)(bc * 8 + bb) * G3 + g] = acc[bb];
    }
}

__global__ void h0_kernel(const float* __restrict__ z, const float* __restrict__ c,
                          const float* __restrict__ Wfch, const float* __restrict__ bfch) {
    __shared__ float cs[8 * LC];
    int bc = blockIdx.x;
    for (int i = threadIdx.x; i < 8 * LC; i += NTHREADS) {
        int bb = i / LC, ii = i - bb * LC;
        int b = bc * 8 + bb;
        cs[i] = (ii < 256) ? z[b * 256 + ii] : c[b * 64 + (ii - 256)];
    }
    __syncthreads();
    for (int jk = 0; jk < 4; jk++) {
        int j = threadIdx.x + jk * NTHREADS;
        float acc[8];
        float bj = bfch[j];
#pragma unroll
        for (int bb = 0; bb < 8; bb++) acc[bb] = bj;
        const float* wr = Wfch + (size_t)j * LC;
        for (int ii = 0; ii < LC; ii++) {
            float w = wr[ii];
#pragma unroll
            for (int bb = 0; bb < 8; bb++) acc[bb] += w * cs[bb * LC + ii];
        }
#pragma unroll
        for (int bb = 0; bb < 8; bb++) {
            int b = bc * 8 + bb;
            float v = acc[bb];
            g_hall[(size_t)b * Hd + j] = v;              // slot 0 = h0
            __half h = __float2half_rn(v);
            __half l = __float2half_rn(v - __half2float(h));
            g_ah[(size_t)b * Hd + j] = h;                // buf 0
            g_al[(size_t)b * Hd + j] = l;
        }
    }
}

__global__ void table_kernel(const float* __restrict__ emb, const float* __restrict__ Wih) {
    __shared__ float es[Vv * 64];
    int g = blockIdx.x * NTHREADS + threadIdx.x;
    float acc[Vv];
#pragma unroll
    for (int v = 0; v < Vv; v++) acc[v] = 0.f;
    for (int ec = 0; ec < Ee / 64; ec++) {
        __syncthreads();
        for (int i = threadIdx.x; i < Vv * 64; i += NTHREADS) {
            int v = i >> 6, el = i & 63;
            es[i] = emb[(size_t)v * Ee + ec * 64 + el];
        }
        __syncthreads();
        const float* wr = Wih + (size_t)g * EIN + ec * 64;
#pragma unroll 8
        for (int e = 0; e < 64; e++) {
            float w = wr[e];
#pragma unroll
            for (int v = 0; v < Vv; v++) acc[v] += w * es[v * 64 + e];
        }
    }
    for (int v = 0; v < Vv; v++) g_table[(size_t)v * G3 + g] = acc[v];
}

// W_hh -> fp16, layout [nt][p=gate*32+jl][k]
__global__ void wconv_kernel(const float* __restrict__ Whh) {
    const size_t total = (size_t)32 * 96 * Hd;
    size_t stride = (size_t)gridDim.x * NTHREADS;
    for (size_t i = blockIdx.x * (size_t)NTHREADS + threadIdx.x; i < total; i += stride) {
        int k = (int)(i & 1023);
        int rf = (int)(i >> 10);        // nt*96 + p
        int nt = rf / 96, p = rf - nt * 96;
        int gate = p >> 5;
        int j = nt * 32 + (p & 31);
        g_wf[i] = __float2half_rn(Whh[((size_t)gate * Hd + j) * Hd + k]);
    }
}

// ---------------- persistent recurrent kernel (gh only) ----------------
// stage s covers K chunk [s*128, s*128+128)
__device__ __forceinline__ void stage_issue(uint32_t stg, int buf, int b0, int nt, int s) {
    const int tid = threadIdx.x;
    const char* agh = (const char*)(g_ah + ((size_t)(buf * Bb + b0)) * Hd + s * 128);
    const char* agl = (const char*)(g_al + ((size_t)(buf * Bb + b0)) * Hd + s * 128);
    const char* wgf = (const char*)(g_wf + ((size_t)nt * 96) * Hd + s * 128);
#pragma unroll
    for (int i = tid; i < 1024; i += NTHREADS) {
        int r = i >> 4, q = i & 15;
        uint32_t dst = stg + r * SROW + q * 16;
        const size_t so = (size_t)r * 2048 + q * 16;
        cpa16(dst + OFF_AH, agh + so);
        cpa16(dst + OFF_AL, agl + so);
    }
#pragma unroll
    for (int i = tid; i < 1536; i += NTHREADS) {
        int r = i >> 4, q = i & 15;
        cpa16(stg + OFF_W + r * SROW + q * 16, wgf + (size_t)r * 2048 + q * 16);
    }
    CP_COMMIT();
}

__global__ void __launch_bounds__(NTHREADS, 1)
gru_kernel(const int* __restrict__ seq, const float* __restrict__ bhh) {
    extern __shared__ char smem[];
    __shared__ unsigned base_s;
    const int tid = threadIdx.x;
    const int bid = blockIdx.x;
    const int lane = tid & 31, wid = tid >> 5;
    const int mw = wid & 1, nw = wid >> 1;     // warp tile m32 x n24
    const int mt = bid & 3, nt = bid >> 2;
    const int b0 = mt * 64, j0 = nt * 32;
    const uint32_t smem_b = smem_u32_of(smem);

    if (tid == 0) {
        unsigned p;
        asm volatile("ld.acquire.gpu.u32 %0, [%1];" : "=r"(p) : "l"(&g_phase) : "memory");
        base_s = p;
    }

    // ---- preload step-invariant epilogue operands into registers ----
    const int lr = tid >> 2;              // row 0..63 within tile
    const int jq = (tid & 3) * 8;         // 8 j's per thread
    const int b = b0 + lr;
    const int jg = j0 + jq;
    const float* cpb = g_ctxpart + (size_t)b * G3;
    float cpr[8], cpz[8], cpn[8], bnv[8];
#pragma unroll
    for (int q = 0; q < 2; q++) {
        float4 c_r = __ldg((const float4*)&cpb[jg + q * 4]);
        float4 c_z = __ldg((const float4*)&cpb[Hd + jg + q * 4]);
        float4 c_n = __ldg((const float4*)&cpb[2 * Hd + jg + q * 4]);
        float4 b_r = __ldg((const float4*)&bhh[jg + q * 4]);
        float4 b_z = __ldg((const float4*)&bhh[Hd + jg + q * 4]);
        float4 b_n = __ldg((const float4*)&bhh[2 * Hd + jg + q * 4]);
#pragma unroll
        for (int e = 0; e < 4; e++) {
            cpr[q * 4 + e] = ((const float*)&c_r)[e] + ((const float*)&b_r)[e];
            cpz[q * 4 + e] = ((const float*)&c_z)[e] + ((const float*)&b_z)[e];
            cpn[q * 4 + e] = ((const float*)&c_n)[e];
            bnv[q * 4 + e] = ((const float*)&b_n)[e];
        }
    }
    __syncthreads();
    const unsigned base = base_s;

    // MMA-loop per-thread constants (R7-proven fragment addressing)
    const int arow = lane & 15;
    const int akoff = (lane >> 4) * 16;
    const int brow = lane & 7;
    const int bkoff = ((lane >> 3) & 1) * 16;
    const uint32_t a_row_off = (uint32_t)(mw * 32 + arow) * SROW + akoff;
    const uint32_t w_row_off = (uint32_t)(nw * 24 + brow) * SROW + bkoff;

    for (int it = 0; it < Tt; ++it) {
        float acc[2][3][4];
#pragma unroll
        for (int mi = 0; mi < 2; mi++)
#pragma unroll
            for (int ni = 0; ni < 3; ni++)
#pragma unroll
                for (int q = 0; q < 4; q++) acc[mi][ni][q] = 0.f;

        const int buf = it & 1;
        stage_issue(smem_b, buf, b0, nt, 0);

        for (int s = 0; s < 8; s++) {
            CP_WAIT0();
            __syncthreads();
            if (s < 7) stage_issue(smem_b + ((s + 1) & 1) * STG, buf, b0, nt, s + 1);
            const uint32_t sb = smem_b + (s & 1) * STG;
            const uint32_t aB = sb + OFF_AH + a_row_off;
            const uint32_t wB = sb + OFF_W + w_row_off;
#pragma unroll
            for (int ks = 0; ks < 8; ks++) {
                uint32_t ah0[4], ah1[4], al0[4], al1[4];
                ldsm_x4(ah0, aB + ks * 32);
                ldsm_x4(ah1, aB + 16 * SROW + ks * 32);
                ldsm_x4(al0, aB + (OFF_AL - OFF_AH) + ks * 32);
                ldsm_x4(al1, aB + (OFF_AL - OFF_AH) + 16 * SROW + ks * 32);
                uint32_t bh[3][2];
#pragma unroll
                for (int ni = 0; ni < 3; ni++)
                    ldsm_x2(bh[ni], wB + ni * 8 * SROW + ks * 32);
#pragma unroll
                for (int ni = 0; ni < 3; ni++) {
                    mma16816(acc[0][ni], ah0, bh[ni]);
                    mma16816(acc[1][ni], ah1, bh[ni]);
                    mma16816(acc[0][ni], al0, bh[ni]);
                    mma16816(acc[1][ni], al1, bh[ni]);
                }
            }
        }

        // ---- epilogue: acc -> smem -> fused GRU gating ----
        __syncthreads();
        float* eg = (float*)smem;   // [64][100], reuses stage area
        {
            const int crow = lane >> 2;
            const int ccol = (lane & 3) * 2;
#pragma unroll
            for (int mi = 0; mi < 2; mi++)
#pragma unroll
                for (int ni = 0; ni < 3; ni++) {
                    int rr = mw * 32 + mi * 16 + crow;
                    int cc = nw * 24 + ni * 8 + ccol;
                    eg[rr * 100 + cc]       = acc[mi][ni][0];
                    eg[rr * 100 + cc + 1]   = acc[mi][ni][1];
                    eg[(rr + 8) * 100 + cc]     = acc[mi][ni][2];
                    eg[(rr + 8) * 100 + cc + 1] = acc[mi][ni][3];
                }
        }
        __syncthreads();

        const int tok = __ldg(&seq[b * Tt + it]);
        const float* tb = g_table + (size_t)tok * G3;
        const float* hold = g_hall + ((size_t)it * Bb + b) * Hd;
        float* hnew = g_hall + ((size_t)(it + 1) * Bb + b) * Hd;
        float hv[8];
#pragma unroll
        for (int q = 0; q < 2; q++) {
            float4 er = *(const float4*)&eg[lr * 100 + jq + q * 4];
            float4 ez = *(const float4*)&eg[lr * 100 + 32 + jq + q * 4];
            float4 en = *(const float4*)&eg[lr * 100 + 64 + jq + q * 4];
            float4 t_r = __ldg((const float4*)&tb[jg + q * 4]);
            float4 t_z = __ldg((const float4*)&tb[Hd + jg + q * 4]);
            float4 t_n = __ldg((const float4*)&tb[2 * Hd + jg + q * 4]);
            float4 h_o = __ldcg((const float4*)&hold[jg + q * 4]);
#pragma unroll
            for (int e = 0; e < 4; e++) {
                int i = q * 4 + e;
                float r = sigm(((const float*)&t_r)[e] + cpr[i] + ((const float*)&er)[e]);
                float u = sigm(((const float*)&t_z)[e] + cpz[i] + ((const float*)&ez)[e]);
                float n = tanh_f(((const float*)&t_n)[e] + cpn[i]
                                 + r * (((const float*)&en)[e] + bnv[i]));
                hv[i] = (1.f - u) * n + u * ((const float*)&h_o)[e];
            }
        }
        *(float4*)&hnew[jg]     = *(float4*)&hv[0];
        *(float4*)&hnew[jg + 4] = *(float4*)&hv[4];
        uint32_t uh[4], ul[4];
#pragma unroll
        for (int q = 0; q < 4; q++) {
            float x0 = hv[q * 2], x1 = hv[q * 2 + 1];
            __half h0 = __float2half_rn(x0), h1 = __float2half_rn(x1);
            __half l0 = __float2half_rn(x0 - __half2float(h0));
            __half l1 = __float2half_rn(x1 - __half2float(h1));
            __half2 ph = __halves2half2(h0, h1);
            __half2 pl = __halves2half2(l0, l1);
            uh[q] = *(uint32_t*)&ph;
            ul[q] = *(uint32_t*)&pl;
        }
        size_t aoff = ((size_t)(((it + 1) & 1) * Bb + b)) * Hd + jg;
        *(uint4*)&g_ah[aoff] = make_uint4(uh[0], uh[1], uh[2], uh[3]);
        *(uint4*)&g_al[aoff] = make_uint4(ul[0], ul[1], ul[2], ul[3]);

        gbar(base + (unsigned)it + 1u);
    }
}

// ---------------- bulk logits GEMM over the full h history ----------------
#define HSS 68
__global__ void __launch_bounds__(NTHREADS)
logits_kernel(const float* __restrict__ Wout, const float* __restrict__ bout,
              float* __restrict__ out) {
    __shared__ float hs[128 * HSS];
    __shared__ float wo[64 * HSS];
    const int cta = blockIdx.x;
    const int t = cta >> 1;
    const int b0 = (cta & 1) * 128;
    const float* hbase = g_hall + ((size_t)(t + 1) * Bb + b0) * Hd;
    const int tid = threadIdx.x;
    const int bl = tid >> 3;
    const int vq = tid & 7;

    unsigned long long acc[4][4];
#pragma unroll
    for (int r = 0; r < 4; r++)
#pragma unroll
        for (int i = 0; i < 4; i++) acc[r][i] = 0ull;

    for (int kc = 0; kc < Hd; kc += 64) {
        __syncthreads();
#pragma unroll
        for (int i = 0; i < 8; i++) {
            int idx = tid + 256 * i;
            int row = idx >> 4, kq = idx & 15;
            *(float4*)&hs[row * HSS + kq * 4] =
                __ldcg((const float4*)&hbase[(size_t)row * Hd + kc + kq * 4]);
        }
#pragma unroll
        for (int i = 0; i < 4; i++) {
            int idx = tid + 256 * i;
            int v = idx >> 4, kq = idx & 15;
            float4 w = __ldg((const float4*)&Wout[(size_t)v * Hd + kc + kq * 4]);
            wo[(kq * 4 + 0) * HSS + v] = w.x;
            wo[(kq * 4 + 1) * HSS + v] = w.y;
            wo[(kq * 4 + 2) * HSS + v] = w.z;
            wo[(kq * 4 + 3) * HSS + v] = w.w;
        }
        __syncthreads();
#pragma unroll 4
        for (int k = 0; k < 64; k++) {
            const float* wr = &wo[k * HSS + vq * 8];
            unsigned long long w0 = *(const unsigned long long*)&wr[0];
            unsigned long long w1 = *(const unsigned long long*)&wr[2];
            unsigned long long w2 = *(const unsigned long long*)&wr[4];
            unsigned long long w3 = *(const unsigned long long*)&wr[6];
#pragma unroll
            for (int r = 0; r < 4; r++) {
                float hvv = hs[(bl + r * 32) * HSS + k];
                unsigned long long hdp = pk2(hvv, hvv);
                fma2(acc[r][0], hdp, w0);
                fma2(acc[r][1], hdp, w1);
                fma2(acc[r][2], hdp, w2);
                fma2(acc[r][3], hdp, w3);
            }
        }
    }
#pragma unroll
    for (int r = 0; r < 4; r++) {
        int b = b0 + bl + r * 32;
        float* op = out + ((size_t)b * Tt + t) * Vv + vq * 8;
#pragma unroll
        for (int i = 0; i < 4; i++) {
            float2 v = unpk(acc[r][i]);
            float2 bo = *(const float2*)&bout[vq * 8 + i * 2];
            op[i * 2 + 0] = v.x + bo.x;
            op[i * 2 + 1] = v.y + bo.y;
        }
    }
}

// ---------------- launch ----------------
extern "C" void kernel_launch(void* const* d_in, const int* in_sizes, int n_in,
                              void* d_out, int out_size) {
    (void)in_sizes; (void)n_in; (void)out_size;
    const float* z    = (const float*)d_in[0];
    const float* c    = (const float*)d_in[1];
    const int*   seq  = (const int*)  d_in[2];
    const float* emb  = (const float*)d_in[3];
    const float* Wfch = (const float*)d_in[4];
    const float* bfch = (const float*)d_in[5];
    const float* Wih  = (const float*)d_in[6];
    const float* bih  = (const float*)d_in[7];
    const float* Whh  = (const float*)d_in[8];
    const float* bhh  = (const float*)d_in[9];
    const float* Wout = (const float*)d_in[10];
    const float* bout = (const float*)d_in[11];
    float* out = (float*)d_out;

    static int smem_set = 0;
    if (!smem_set) {
        cudaFuncSetAttribute(gru_kernel, cudaFuncAttributeMaxDynamicSharedMemorySize, SMEM_TOTAL);
        smem_set = 1;
    }

    ctx_kernel<<<32, NTHREADS>>>(z, c, Wih, bih);
    h0_kernel<<<32, NTHREADS>>>(z, c, Wfch, bfch);
    table_kernel<<<12, NTHREADS>>>(emb, Wih);
    wconv_kernel<<<128, NTHREADS>>>(Whh);
    gru_kernel<<<GRID, NTHREADS, SMEM_TOTAL>>>(seq, bhh);
    logits_kernel<<<Tt * 2, NTHREADS>>>(Wout, bout, out);
}

// round 10
// speedup vs baseline: 1.5385x; 1.5385x over previous
#include <cuda_runtime.h>
#include <cuda_fp16.h>
#include <cstdint>

#define Bb 256
#define Tt 256
#define Hd 1024
#define Ee 256
#define LC 320
#define EIN 576   // E + L + C
#define G3 3072
#define Vv 64

#define NGH 128
#define GRID NGH
#define NTHREADS 256

// stage layout (bytes): A_hi[64x128 f16] A_lo[64x128 f16] W[96x128 f16], rows padded to 272B
#define SROW 272
#define OFF_AH 0
#define OFF_AL 17408
#define OFF_W  34816
#define STG 60928
#define SMEM_TOTAL (2 * STG)   // 121856

// ---------------- persistent device scratch ----------------
__device__ float g_ctxpart[Bb * G3];   // context @ W_ih[:,E:]^T + b_ih
__device__ float g_table[Vv * G3];     // emb @ W_ih[:,:E]^T
// full hidden-state history: slot s = h after step s-1 (slot 0 = h0)
__device__ float g_hall[(size_t)(Tt + 1) * Bb * Hd];
// fp16 hi/lo hidden tiles, row-major [buf][b(256)][k(1024)]
__device__ __align__(16) __half g_ah[2 * Bb * Hd];
__device__ __align__(16) __half g_al[2 * Bb * Hd];
// fp16 W tiles: [nt(32)][p(96)=gate*32+jl][k(1024)]
__device__ __align__(16) __half g_wf[32 * 96 * Hd];
__device__ unsigned g_count = 0;
__device__ unsigned g_phase = 0;

// ---------------- helpers ----------------
__device__ __forceinline__ uint32_t smem_u32_of(const void* p) {
    uint32_t a;
    asm("{ .reg .u64 t; cvta.to.shared.u64 t, %1; cvt.u32.u64 %0, t; }" : "=r"(a) : "l"(p));
    return a;
}
__device__ __forceinline__ unsigned long long pk2(float x, float y) {
    unsigned long long r;
    asm("mov.b64 %0, {%1, %2};" : "=l"(r) : "f"(x), "f"(y));
    return r;
}
__device__ __forceinline__ float2 unpk(unsigned long long v) {
    float2 r;
    asm("mov.b64 {%0, %1}, %2;" : "=f"(r.x), "=f"(r.y) : "l"(v));
    return r;
}
__device__ __forceinline__ void fma2(unsigned long long& d, unsigned long long a, unsigned long long b) {
    asm("fma.rn.f32x2 %0, %1, %2, %0;" : "+l"(d) : "l"(a), "l"(b));
}
__device__ __forceinline__ float sigm(float x) { return 1.f / (1.f + __expf(-x)); }
__device__ __forceinline__ float tanh_f(float x) { return 2.f / (1.f + __expf(-2.f * x)) - 1.f; }

__device__ __forceinline__ void cpa16(uint32_t d, const void* s) {
    asm volatile("cp.async.cg.shared.global [%0], [%1], 16;" :: "r"(d), "l"(s) : "memory");
}
#define CP_COMMIT() asm volatile("cp.async.commit_group;" ::: "memory")
#define CP_WAIT0()  asm volatile("cp.async.wait_group 0;" ::: "memory")

__device__ __forceinline__ void ldsm_x4(uint32_t* r, uint32_t a) {
    asm volatile("ldmatrix.sync.aligned.m8n8.x4.shared.b16 {%0,%1,%2,%3}, [%4];"
                 : "=r"(r[0]), "=r"(r[1]), "=r"(r[2]), "=r"(r[3]) : "r"(a));
}
__device__ __forceinline__ void ldsm_x2(uint32_t* r, uint32_t a) {
    asm volatile("ldmatrix.sync.aligned.m8n8.x2.shared.b16 {%0,%1}, [%2];"
                 : "=r"(r[0]), "=r"(r[1]) : "r"(a));
}
__device__ __forceinline__ void mma16816(float* c, const uint32_t* a, const uint32_t* b) {
    asm volatile("mma.sync.aligned.m16n8k16.row.col.f32.f16.f16.f32 "
                 "{%0,%1,%2,%3}, {%4,%5,%6,%7}, {%8,%9}, {%0,%1,%2,%3};"
                 : "+f"(c[0]), "+f"(c[1]), "+f"(c[2]), "+f"(c[3])
                 : "r"(a[0]), "r"(a[1]), "r"(a[2]), "r"(a[3]), "r"(b[0]), "r"(b[1]));
}

// ---------------- grid barrier ----------------
__device__ __forceinline__ void gbar(unsigned target) {
    __syncthreads();
    if (threadIdx.x == 0) {
        unsigned n;
        asm volatile("atom.add.acq_rel.gpu.u32 %0, [%1], 1;"
                     : "=r"(n) : "l"(&g_count) : "memory");
        if (n == GRID - 1) {
            g_count = 0;
            asm volatile("st.release.gpu.u32 [%0], %1;"
                         :: "l"(&g_phase), "r"(target) : "memory");
        } else {
            unsigned p;
            do {
                asm volatile("ld.acquire.gpu.u32 %0, [%1];"
                             : "=r"(p) : "l"(&g_phase) : "memory");
            } while ((int)(p - target) < 0);
        }
        __threadfence();
    }
    __syncthreads();
}

// ---------------- precompute kernels ----------------
__global__ void ctx_kernel(const float* __restrict__ z, const float* __restrict__ c,
                           const float* __restrict__ Wih, const float* __restrict__ bih) {
    __shared__ float cs[8 * LC];
    int bc = blockIdx.x;
    for (int i = threadIdx.x; i < 8 * LC; i += NTHREADS) {
        int bb = i / LC, ii = i - bb * LC;
        int b = bc * 8 + bb;
        cs[i] = (ii < 256) ? z[b * 256 + ii] : c[b * 64 + (ii - 256)];
    }
    __syncthreads();
    for (int gk = 0; gk < 12; gk++) {
        int g = threadIdx.x + gk * NTHREADS;
        float acc[8];
        float bi = bih[g];
#pragma unroll
        for (int bb = 0; bb < 8; bb++) acc[bb] = bi;
        const float* wr = Wih + (size_t)g * EIN + Ee;
        for (int ii = 0; ii < LC; ii++) {
            float w = wr[ii];
#pragma unroll
            for (int bb = 0; bb < 8; bb++) acc[bb] += w * cs[bb * LC + ii];
        }
#pragma unroll
        for (int bb = 0; bb < 8; bb++) g_ctxpart[(size_t)(bc * 8 + bb) * G3 + g] = acc[bb];
    }
}

__global__ void h0_kernel(const float* __restrict__ z, const float* __restrict__ c,
                          const float* __restrict__ Wfch, const float* __restrict__ bfch) {
    __shared__ float cs[8 * LC];
    int bc = blockIdx.x;
    for (int i = threadIdx.x; i < 8 * LC; i += NTHREADS) {
        int bb = i / LC, ii = i - bb * LC;
        int b = bc * 8 + bb;
        cs[i] = (ii < 256) ? z[b * 256 + ii] : c[b * 64 + (ii - 256)];
    }
    __syncthreads();
    for (int jk = 0; jk < 4; jk++) {
        int j = threadIdx.x + jk * NTHREADS;
        float acc[8];
        float bj = bfch[j];
#pragma unroll
        for (int bb = 0; bb < 8; bb++) acc[bb] = bj;
        const float* wr = Wfch + (size_t)j * LC;
        for (int ii = 0; ii < LC; ii++) {
            float w = wr[ii];
#pragma unroll
            for (int bb = 0; bb < 8; bb++) acc[bb] += w * cs[bb * LC + ii];
        }
#pragma unroll
        for (int bb = 0; bb < 8; bb++) {
            int b = bc * 8 + bb;
            float v = acc[bb];
            g_hall[(size_t)b * Hd + j] = v;              // slot 0 = h0
            __half h = __float2half_rn(v);
            __half l = __float2half_rn(v - __half2float(h));
            g_ah[(size_t)b * Hd + j] = h;                // buf 0
            g_al[(size_t)b * Hd + j] = l;
        }
    }
}

__global__ void table_kernel(const float* __restrict__ emb, const float* __restrict__ Wih) {
    __shared__ float es[Vv * 64];
    int g = blockIdx.x * NTHREADS + threadIdx.x;
    float acc[Vv];
#pragma unroll
    for (int v = 0; v < Vv; v++) acc[v] = 0.f;
    for (int ec = 0; ec < Ee / 64; ec++) {
        __syncthreads();
        for (int i = threadIdx.x; i < Vv * 64; i += NTHREADS) {
            int v = i >> 6, el = i & 63;
            es[i] = emb[(size_t)v * Ee + ec * 64 + el];
        }
        __syncthreads();
        const float* wr = Wih + (size_t)g * EIN + ec * 64;
#pragma unroll 8
        for (int e = 0; e < 64; e++) {
            float w = wr[e];
#pragma unroll
            for (int v = 0; v < Vv; v++) acc[v] += w * es[v * 64 + e];
        }
    }
    for (int v = 0; v < Vv; v++) g_table[(size_t)v * G3 + g] = acc[v];
}

// W_hh -> fp16, layout [nt][p=gate*32+jl][k]
__global__ void wconv_kernel(const float* __restrict__ Whh) {
    const size_t total = (size_t)32 * 96 * Hd;
    size_t stride = (size_t)gridDim.x * NTHREADS;
    for (size_t i = blockIdx.x * (size_t)NTHREADS + threadIdx.x; i < total; i += stride) {
        int k = (int)(i & 1023);
        int rf = (int)(i >> 10);        // nt*96 + p
        int nt = rf / 96, p = rf - nt * 96;
        int gate = p >> 5;
        int j = nt * 32 + (p & 31);
        g_wf[i] = __float2half_rn(Whh[((size_t)gate * Hd + j) * Hd + k]);
    }
}

// ---------------- persistent recurrent kernel (gh only) ----------------
// stage s covers K chunk [s*128, s*128+128)
__device__ __forceinline__ void stage_issue(uint32_t stg, int buf, int b0, int nt, int s) {
    const int tid = threadIdx.x;
    const char* agh = (const char*)(g_ah + ((size_t)(buf * Bb + b0)) * Hd + s * 128);
    const char* agl = (const char*)(g_al + ((size_t)(buf * Bb + b0)) * Hd + s * 128);
    const char* wgf = (const char*)(g_wf + ((size_t)nt * 96) * Hd + s * 128);
#pragma unroll
    for (int i = tid; i < 1024; i += NTHREADS) {
        int r = i >> 4, q = i & 15;
        uint32_t dst = stg + r * SROW + q * 16;
        const size_t so = (size_t)r * 2048 + q * 16;
        cpa16(dst + OFF_AH, agh + so);
        cpa16(dst + OFF_AL, agl + so);
    }
#pragma unroll
    for (int i = tid; i < 1536; i += NTHREADS) {
        int r = i >> 4, q = i & 15;
        cpa16(stg + OFF_W + r * SROW + q * 16, wgf + (size_t)r * 2048 + q * 16);
    }
    CP_COMMIT();
}

__device__ void gh_tile(int t, int mt, int nt, char* smem, uint32_t smem_b,
                        const int* __restrict__ seq, const float* __restrict__ bhh) {
    const int tid = threadIdx.x;
    const int lane = tid & 31, wid = tid >> 5;
    const int mw = wid & 1, nw = wid >> 1;     // warp tile m32 x n24
    const int b0 = mt * 64, j0 = nt * 32;

    float acc[2][3][4];
#pragma unroll
    for (int mi = 0; mi < 2; mi++)
#pragma unroll
        for (int ni = 0; ni < 3; ni++)
#pragma unroll
            for (int q = 0; q < 4; q++) acc[mi][ni][q] = 0.f;

    const int arow = lane & 15;
    const int akoff = (lane >> 4) * 16;
    const int brow = lane & 7;
    const int bkoff = ((lane >> 3) & 1) * 16;

    stage_issue(smem_b, t & 1, b0, nt, 0);

    for (int s = 0; s < 8; s++) {
        CP_WAIT0();
        __syncthreads();
        if (s < 7) stage_issue(smem_b + ((s + 1) & 1) * STG, t & 1, b0, nt, s + 1);
        uint32_t sb = smem_b + (s & 1) * STG;
        uint32_t aB = sb + OFF_AH + (mw * 32 + arow) * SROW + akoff;
        uint32_t wB = sb + OFF_W + (nw * 24 + brow) * SROW + bkoff;
#pragma unroll
        for (int ks = 0; ks < 8; ks++) {
            uint32_t ah0[4], ah1[4], al0[4], al1[4];
            ldsm_x4(ah0, aB + ks * 32);
            ldsm_x4(ah1, aB + 16 * SROW + ks * 32);
            ldsm_x4(al0, aB + (OFF_AL - OFF_AH) + ks * 32);
            ldsm_x4(al1, aB + (OFF_AL - OFF_AH) + 16 * SROW + ks * 32);
            uint32_t bh[3][2];
#pragma unroll
            for (int ni = 0; ni < 3; ni++)
                ldsm_x2(bh[ni], wB + ni * 8 * SROW + ks * 32);
#pragma unroll
            for (int ni = 0; ni < 3; ni++) {
                mma16816(acc[0][ni], ah0, bh[ni]);
                mma16816(acc[1][ni], ah1, bh[ni]);
                mma16816(acc[0][ni], al0, bh[ni]);
                mma16816(acc[1][ni], al1, bh[ni]);
            }
        }
    }

    // ---- epilogue: acc -> smem -> fused GRU gating (R7-identical) ----
    __syncthreads();
    float* eg = (float*)smem;   // [64][100]
    const int crow = lane >> 2;
    const int ccol = (lane & 3) * 2;
#pragma unroll
    for (int mi = 0; mi < 2; mi++)
#pragma unroll
        for (int ni = 0; ni < 3; ni++) {
            int rr = mw * 32 + mi * 16 + crow;
            int cc = nw * 24 + ni * 8 + ccol;
            eg[rr * 100 + cc]       = acc[mi][ni][0];
            eg[rr * 100 + cc + 1]   = acc[mi][ni][1];
            eg[(rr + 8) * 100 + cc]     = acc[mi][ni][2];
            eg[(rr + 8) * 100 + cc + 1] = acc[mi][ni][3];
        }
    __syncthreads();

    const int lr = tid >> 2;
    const int b = b0 + lr;
    const int jq = (tid & 3) * 8;
    const int jg = j0 + jq;
    const int tok = __ldg(&seq[b * Tt + t]);
    const float* tb = g_table + (size_t)tok * G3;
    const float* cp = g_ctxpart + (size_t)b * G3;
    const float* hold = g_hall + ((size_t)t * Bb + b) * Hd;
    float* hnew = g_hall + ((size_t)(t + 1) * Bb + b) * Hd;
    const int bufn = (t + 1) & 1;
    float hv[8];
#pragma unroll
    for (int q = 0; q < 2; q++) {
        float4 er = *(const float4*)&eg[lr * 100 + jq + q * 4];
        float4 ez = *(const float4*)&eg[lr * 100 + 32 + jq + q * 4];
        float4 en = *(const float4*)&eg[lr * 100 + 64 + jq + q * 4];
        float4 t_r = __ldg((const float4*)&tb[jg + q * 4]);
        float4 t_z = __ldg((const float4*)&tb[Hd + jg + q * 4]);
        float4 t_n = __ldg((const float4*)&tb[2 * Hd + jg + q * 4]);
        float4 c_r = __ldg((const float4*)&cp[jg + q * 4]);
        float4 c_z = __ldg((const float4*)&cp[Hd + jg + q * 4]);
        float4 c_n = __ldg((const float4*)&cp[2 * Hd + jg + q * 4]);
        float4 b_r = __ldg((const float4*)&bhh[jg + q * 4]);
        float4 b_z = __ldg((const float4*)&bhh[Hd + jg + q * 4]);
        float4 b_n = __ldg((const float4*)&bhh[2 * Hd + jg + q * 4]);
        float4 h_o = __ldcg((const float4*)&hold[jg + q * 4]);
#pragma unroll
        for (int e = 0; e < 4; e++) {
            float r = sigm(((const float*)&t_r)[e] + ((const float*)&c_r)[e]
                           + ((const float*)&er)[e] + ((const float*)&b_r)[e]);
            float u = sigm(((const float*)&t_z)[e] + ((const float*)&c_z)[e]
                           + ((const float*)&ez)[e] + ((const float*)&b_z)[e]);
            float n = tanh_f(((const float*)&t_n)[e] + ((const float*)&c_n)[e]
                             + r * (((const float*)&en)[e] + ((const float*)&b_n)[e]));
            hv[q * 4 + e] = (1.f - u) * n + u * ((const float*)&h_o)[e];
        }
    }
    *(float4*)&hnew[jg]     = *(float4*)&hv[0];
    *(float4*)&hnew[jg + 4] = *(float4*)&hv[4];
    uint32_t uh[4], ul[4];
#pragma unroll
    for (int q = 0; q < 4; q++) {
        float x0 = hv[q * 2], x1 = hv[q * 2 + 1];
        __half h0 = __float2half_rn(x0), h1 = __float2half_rn(x1);
        __half l0 = __float2half_rn(x0 - __half2float(h0));
        __half l1 = __float2half_rn(x1 - __half2float(h1));
        __half2 ph = __halves2half2(h0, h1);
        __half2 pl = __halves2half2(l0, l1);
        uh[q] = *(uint32_t*)&ph;
        ul[q] = *(uint32_t*)&pl;
    }
    size_t aoff = ((size_t)(bufn * Bb + b)) * Hd + jg;
    *(uint4*)&g_ah[aoff] = make_uint4(uh[0], uh[1], uh[2], uh[3]);
    *(uint4*)&g_al[aoff] = make_uint4(ul[0], ul[1], ul[2], ul[3]);
}

__global__ void __launch_bounds__(NTHREADS, 1)
gru_kernel(const int* __restrict__ seq, const float* __restrict__ bhh) {
    extern __shared__ char smem[];
    __shared__ unsigned base_s;
    const int tid = threadIdx.x;
    const int bid = blockIdx.x;
    const uint32_t smem_b = smem_u32_of(smem);

    if (tid == 0) {
        unsigned p;
        asm volatile("ld.acquire.gpu.u32 %0, [%1];" : "=r"(p) : "l"(&g_phase) : "memory");
        base_s = p;
    }
    __syncthreads();
    const unsigned base = base_s;
    const int mt = bid & 3, nt = bid >> 2;

    for (int it = 0; it < Tt; ++it) {
        gh_tile(it, mt, nt, smem, smem_b, seq, bhh);
        gbar(base + (unsigned)it + 1u);
    }
}

// ---------------- bulk logits GEMM over the full h history ----------------
#define HSS 68
__global__ void __launch_bounds__(NTHREADS)
logits_kernel(const float* __restrict__ Wout, const float* __restrict__ bout,
              float* __restrict__ out) {
    __shared__ float hs[128 * HSS];
    __shared__ float wo[64 * HSS];
    const int cta = blockIdx.x;
    const int t = cta >> 1;
    const int b0 = (cta & 1) * 128;
    const float* hbase = g_hall + ((size_t)(t + 1) * Bb + b0) * Hd;
    const int tid = threadIdx.x;
    const int bl = tid >> 3;
    const int vq = tid & 7;

    unsigned long long acc[4][4];
#pragma unroll
    for (int r = 0; r < 4; r++)
#pragma unroll
        for (int i = 0; i < 4; i++) acc[r][i] = 0ull;

    for (int kc = 0; kc < Hd; kc += 64) {
        __syncthreads();
#pragma unroll
        for (int i = 0; i < 8; i++) {
            int idx = tid + 256 * i;
            int row = idx >> 4, kq = idx & 15;
            *(float4*)&hs[row * HSS + kq * 4] =
                __ldcg((const float4*)&hbase[(size_t)row * Hd + kc + kq * 4]);
        }
#pragma unroll
        for (int i = 0; i < 4; i++) {
            int idx = tid + 256 * i;
            int v = idx >> 4, kq = idx & 15;
            float4 w = __ldg((const float4*)&Wout[(size_t)v * Hd + kc + kq * 4]);
            wo[(kq * 4 + 0) * HSS + v] = w.x;
            wo[(kq * 4 + 1) * HSS + v] = w.y;
            wo[(kq * 4 + 2) * HSS + v] = w.z;
            wo[(kq * 4 + 3) * HSS + v] = w.w;
        }
        __syncthreads();
#pragma unroll 4
        for (int k = 0; k < 64; k++) {
            const float* wr = &wo[k * HSS + vq * 8];
            unsigned long long w0 = *(const unsigned long long*)&wr[0];
            unsigned long long w1 = *(const unsigned long long*)&wr[2];
            unsigned long long w2 = *(const unsigned long long*)&wr[4];
            unsigned long long w3 = *(const unsigned long long*)&wr[6];
#pragma unroll
            for (int r = 0; r < 4; r++) {
                float hvv = hs[(bl + r * 32) * HSS + k];
                unsigned long long hdp = pk2(hvv, hvv);
                fma2(acc[r][0], hdp, w0);
                fma2(acc[r][1], hdp, w1);
                fma2(acc[r][2], hdp, w2);
                fma2(acc[r][3], hdp, w3);
            }
        }
    }
#pragma unroll
    for (int r = 0; r < 4; r++) {
        int b = b0 + bl + r * 32;
        float* op = out + ((size_t)b * Tt + t) * Vv + vq * 8;
#pragma unroll
        for (int i = 0; i < 4; i++) {
            float2 v = unpk(acc[r][i]);
            float2 bo = *(const float2*)&bout[vq * 8 + i * 2];
            op[i * 2 + 0] = v.x + bo.x;
            op[i * 2 + 1] = v.y + bo.y;
        }
    }
}

// ---------------- launch ----------------
extern "C" void kernel_launch(void* const* d_in, const int* in_sizes, int n_in,
                              void* d_out, int out_size) {
    (void)in_sizes; (void)n_in; (void)out_size;
    const float* z    = (const float*)d_in[0];
    const float* c    = (const float*)d_in[1];
    const int*   seq  = (const int*)  d_in[2];
    const float* emb  = (const float*)d_in[3];
    const float* Wfch = (const float*)d_in[4];
    const float* bfch = (const float*)d_in[5];
    const float* Wih  = (const float*)d_in[6];
    const float* bih  = (const float*)d_in[7];
    const float* Whh  = (const float*)d_in[8];
    const float* bhh  = (const float*)d_in[9];
    const float* Wout = (const float*)d_in[10];
    const float* bout = (const float*)d_in[11];
    float* out = (float*)d_out;

    static int smem_set = 0;
    if (!smem_set) {
        cudaFuncSetAttribute(gru_kernel, cudaFuncAttributeMaxDynamicSharedMemorySize, SMEM_TOTAL);
        smem_set = 1;
    }

    ctx_kernel<<<32, NTHREADS>>>(z, c, Wih, bih);
    h0_kernel<<<32, NTHREADS>>>(z, c, Wfch, bfch);
    table_kernel<<<12, NTHREADS>>>(emb, Wih);
    wconv_kernel<<<128, NTHREADS>>>(Whh);
    gru_kernel<<<GRID, NTHREADS, SMEM_TOTAL>>>(seq, bhh);
    logits_kernel<<<Tt * 2, NTHREADS>>>(Wout, bout, out);
}

// round 11
// speedup vs baseline: 1.8930x; 1.2304x over previous
#include <cuda_runtime.h>
#include <cuda_fp16.h>
#include <cstdint>

#define Bb 256
#define Tt 256
#define Hd 1024
#define Ee 256
#define LC 320
#define EIN 576   // E + L + C
#define G3 3072
#define Vv 64

#define NGH 128
#define GRID NGH
#define NTHREADS 256

// stage layout (bytes): A[64x128 f16] W[96x128 f16], rows padded to 272B
#define SROW 272
#define OFF_A 0
#define OFF_W 17408
#define STG 43520
#define SMEM_TOTAL (2 * STG)   // 87040

// ---------------- persistent device scratch ----------------
__device__ float g_ctxpart[Bb * G3];   // context @ W_ih[:,E:]^T + b_ih
__device__ float g_table[Vv * G3];     // emb @ W_ih[:,:E]^T
// full hidden-state history: slot s = h after step s-1 (slot 0 = h0)
__device__ float g_hall[(size_t)(Tt + 1) * Bb * Hd];
// fp16 hidden tiles, row-major [buf][b(256)][k(1024)]
__device__ __align__(16) __half g_ah[2 * Bb * Hd];
// fp16 W tiles: [nt(32)][p(96)=gate*32+jl][k(1024)]
__device__ __align__(16) __half g_wf[32 * 96 * Hd];
__device__ unsigned g_count = 0;
__device__ unsigned g_phase = 0;

// ---------------- helpers ----------------
__device__ __forceinline__ uint32_t smem_u32_of(const void* p) {
    uint32_t a;
    asm("{ .reg .u64 t; cvta.to.shared.u64 t, %1; cvt.u32.u64 %0, t; }" : "=r"(a) : "l"(p));
    return a;
}
__device__ __forceinline__ unsigned long long pk2(float x, float y) {
    unsigned long long r;
    asm("mov.b64 %0, {%1, %2};" : "=l"(r) : "f"(x), "f"(y));
    return r;
}
__device__ __forceinline__ float2 unpk(unsigned long long v) {
    float2 r;
    asm("mov.b64 {%0, %1}, %2;" : "=f"(r.x), "=f"(r.y) : "l"(v));
    return r;
}
__device__ __forceinline__ void fma2(unsigned long long& d, unsigned long long a, unsigned long long b) {
    asm("fma.rn.f32x2 %0, %1, %2, %0;" : "+l"(d) : "l"(a), "l"(b));
}
__device__ __forceinline__ float sigm(float x) { return 1.f / (1.f + __expf(-x)); }
__device__ __forceinline__ float tanh_f(float x) { return 2.f / (1.f + __expf(-2.f * x)) - 1.f; }

__device__ __forceinline__ void cpa16(uint32_t d, const void* s) {
    asm volatile("cp.async.cg.shared.global [%0], [%1], 16;" :: "r"(d), "l"(s) : "memory");
}
#define CP_COMMIT() asm volatile("cp.async.commit_group;" ::: "memory")
#define CP_WAIT0()  asm volatile("cp.async.wait_group 0;" ::: "memory")

__device__ __forceinline__ void ldsm_x4(uint32_t* r, uint32_t a) {
    asm volatile("ldmatrix.sync.aligned.m8n8.x4.shared.b16 {%0,%1,%2,%3}, [%4];"
                 : "=r"(r[0]), "=r"(r[1]), "=r"(r[2]), "=r"(r[3]) : "r"(a));
}
__device__ __forceinline__ void ldsm_x2(uint32_t* r, uint32_t a) {
    asm volatile("ldmatrix.sync.aligned.m8n8.x2.shared.b16 {%0,%1}, [%2];"
                 : "=r"(r[0]), "=r"(r[1]) : "r"(a));
}
__device__ __forceinline__ void mma16816(float* c, const uint32_t* a, const uint32_t* b) {
    asm volatile("mma.sync.aligned.m16n8k16.row.col.f32.f16.f16.f32 "
                 "{%0,%1,%2,%3}, {%4,%5,%6,%7}, {%8,%9}, {%0,%1,%2,%3};"
                 : "+f"(c[0]), "+f"(c[1]), "+f"(c[2]), "+f"(c[3])
                 : "r"(a[0]), "r"(a[1]), "r"(a[2]), "r"(a[3]), "r"(b[0]), "r"(b[1]));
}

// ---------------- grid barrier ----------------
__device__ __forceinline__ void gbar(unsigned target) {
    __syncthreads();
    if (threadIdx.x == 0) {
        unsigned n;
        asm volatile("atom.add.acq_rel.gpu.u32 %0, [%1], 1;"
                     : "=r"(n) : "l"(&g_count) : "memory");
        if (n == GRID - 1) {
            g_count = 0;
            asm volatile("st.release.gpu.u32 [%0], %1;"
                         :: "l"(&g_phase), "r"(target) : "memory");
        } else {
            unsigned p;
            do {
                asm volatile("ld.acquire.gpu.u32 %0, [%1];"
                             : "=r"(p) : "l"(&g_phase) : "memory");
            } while ((int)(p - target) < 0);
        }
        __threadfence();
    }
    __syncthreads();
}

// ---------------- precompute kernels ----------------
__global__ void ctx_kernel(const float* __restrict__ z, const float* __restrict__ c,
                           const float* __restrict__ Wih, const float* __restrict__ bih) {
    __shared__ float cs[8 * LC];
    int bc = blockIdx.x;
    for (int i = threadIdx.x; i < 8 * LC; i += NTHREADS) {
        int bb = i / LC, ii = i - bb * LC;
        int b = bc * 8 + bb;
        cs[i] = (ii < 256) ? z[b * 256 + ii] : c[b * 64 + (ii - 256)];
    }
    __syncthreads();
    for (int gk = 0; gk < 12; gk++) {
        int g = threadIdx.x + gk * NTHREADS;
        float acc[8];
        float bi = bih[g];
#pragma unroll
        for (int bb = 0; bb < 8; bb++) acc[bb] = bi;
        const float* wr = Wih + (size_t)g * EIN + Ee;
        for (int ii = 0; ii < LC; ii++) {
            float w = wr[ii];
#pragma unroll
            for (int bb = 0; bb < 8; bb++) acc[bb] += w * cs[bb * LC + ii];
        }
#pragma unroll
        for (int bb = 0; bb < 8; bb++) g_ctxpart[(size_t)(bc * 8 + bb) * G3 + g] = acc[bb];
    }
}

__global__ void h0_kernel(const float* __restrict__ z, const float* __restrict__ c,
                          const float* __restrict__ Wfch, const float* __restrict__ bfch) {
    __shared__ float cs[8 * LC];
    int bc = blockIdx.x;
    for (int i = threadIdx.x; i < 8 * LC; i += NTHREADS) {
        int bb = i / LC, ii = i - bb * LC;
        int b = bc * 8 + bb;
        cs[i] = (ii < 256) ? z[b * 256 + ii] : c[b * 64 + (ii - 256)];
    }
    __syncthreads();
    for (int jk = 0; jk < 4; jk++) {
        int j = threadIdx.x + jk * NTHREADS;
        float acc[8];
        float bj = bfch[j];
#pragma unroll
        for (int bb = 0; bb < 8; bb++) acc[bb] = bj;
        const float* wr = Wfch + (size_t)j * LC;
        for (int ii = 0; ii < LC; ii++) {
            float w = wr[ii];
#pragma unroll
            for (int bb = 0; bb < 8; bb++) acc[bb] += w * cs[bb * LC + ii];
        }
#pragma unroll
        for (int bb = 0; bb < 8; bb++) {
            int b = bc * 8 + bb;
            float v = acc[bb];
            g_hall[(size_t)b * Hd + j] = v;              // slot 0 = h0
            g_ah[(size_t)b * Hd + j] = __float2half_rn(v);   // buf 0
        }
    }
}

__global__ void table_kernel(const float* __restrict__ emb, const float* __restrict__ Wih) {
    __shared__ float es[Vv * 64];
    int g = blockIdx.x * NTHREADS + threadIdx.x;
    float acc[Vv];
#pragma unroll
    for (int v = 0; v < Vv; v++) acc[v] = 0.f;
    for (int ec = 0; ec < Ee / 64; ec++) {
        __syncthreads();
        for (int i = threadIdx.x; i < Vv * 64; i += NTHREADS) {
            int v = i >> 6, el = i & 63;
            es[i] = emb[(size_t)v * Ee + ec * 64 + el];
        }
        __syncthreads();
        const float* wr = Wih + (size_t)g * EIN + ec * 64;
#pragma unroll 8
        for (int e = 0; e < 64; e++) {
            float w = wr[e];
#pragma unroll
            for (int v = 0; v < Vv; v++) acc[v] += w * es[v * 64 + e];
        }
    }
    for (int v = 0; v < Vv; v++) g_table[(size_t)v * G3 + g] = acc[v];
}

// W_hh -> fp16, layout [nt][p=gate*32+jl][k]
__global__ void wconv_kernel(const float* __restrict__ Whh) {
    const size_t total = (size_t)32 * 96 * Hd;
    size_t stride = (size_t)gridDim.x * NTHREADS;
    for (size_t i = blockIdx.x * (size_t)NTHREADS + threadIdx.x; i < total; i += stride) {
        int k = (int)(i & 1023);
        int rf = (int)(i >> 10);        // nt*96 + p
        int nt = rf / 96, p = rf - nt * 96;
        int gate = p >> 5;
        int j = nt * 32 + (p & 31);
        g_wf[i] = __float2half_rn(Whh[((size_t)gate * Hd + j) * Hd + k]);
    }
}

// ---------------- persistent recurrent kernel (gh only) ----------------
// stage s covers K chunk [s*128, s*128+128)
__device__ __forceinline__ void stage_issue(uint32_t stg, int buf, int b0, int nt, int s) {
    const int tid = threadIdx.x;
    const char* agh = (const char*)(g_ah + ((size_t)(buf * Bb + b0)) * Hd + s * 128);
    const char* wgf = (const char*)(g_wf + ((size_t)nt * 96) * Hd + s * 128);
#pragma unroll
    for (int i = tid; i < 1024; i += NTHREADS) {
        int r = i >> 4, q = i & 15;
        cpa16(stg + OFF_A + r * SROW + q * 16, agh + (size_t)r * 2048 + q * 16);
    }
#pragma unroll
    for (int i = tid; i < 1536; i += NTHREADS) {
        int r = i >> 4, q = i & 15;
        cpa16(stg + OFF_W + r * SROW + q * 16, wgf + (size_t)r * 2048 + q * 16);
    }
    CP_COMMIT();
}

__device__ void gh_tile(int t, int mt, int nt, char* smem, uint32_t smem_b,
                        const int* __restrict__ seq, const float* __restrict__ bhh) {
    const int tid = threadIdx.x;
    const int lane = tid & 31, wid = tid >> 5;
    const int mw = wid & 1, nw = wid >> 1;     // warp tile m32 x n24
    const int b0 = mt * 64, j0 = nt * 32;

    float acc[2][3][4];
#pragma unroll
    for (int mi = 0; mi < 2; mi++)
#pragma unroll
        for (int ni = 0; ni < 3; ni++)
#pragma unroll
            for (int q = 0; q < 4; q++) acc[mi][ni][q] = 0.f;

    const int arow = lane & 15;
    const int akoff = (lane >> 4) * 16;
    const int brow = lane & 7;
    const int bkoff = ((lane >> 3) & 1) * 16;

    stage_issue(smem_b, t & 1, b0, nt, 0);

    for (int s = 0; s < 8; s++) {
        CP_WAIT0();
        __syncthreads();
        if (s < 7) stage_issue(smem_b + ((s + 1) & 1) * STG, t & 1, b0, nt, s + 1);
        uint32_t sb = smem_b + (s & 1) * STG;
        uint32_t aB = sb + OFF_A + (mw * 32 + arow) * SROW + akoff;
        uint32_t wB = sb + OFF_W + (nw * 24 + brow) * SROW + bkoff;
#pragma unroll
        for (int ks = 0; ks < 8; ks++) {
            uint32_t ah0[4], ah1[4];
            ldsm_x4(ah0, aB + ks * 32);
            ldsm_x4(ah1, aB + 16 * SROW + ks * 32);
            uint32_t bh[3][2];
#pragma unroll
            for (int ni = 0; ni < 3; ni++)
                ldsm_x2(bh[ni], wB + ni * 8 * SROW + ks * 32);
#pragma unroll
            for (int ni = 0; ni < 3; ni++) {
                mma16816(acc[0][ni], ah0, bh[ni]);
                mma16816(acc[1][ni], ah1, bh[ni]);
            }
        }
    }

    // ---- epilogue: acc -> smem -> fused GRU gating ----
    __syncthreads();
    float* eg = (float*)smem;   // [64][100]
    const int crow = lane >> 2;
    const int ccol = (lane & 3) * 2;
#pragma unroll
    for (int mi = 0; mi < 2; mi++)
#pragma unroll
        for (int ni = 0; ni < 3; ni++) {
            int rr = mw * 32 + mi * 16 + crow;
            int cc = nw * 24 + ni * 8 + ccol;
            eg[rr * 100 + cc]       = acc[mi][ni][0];
            eg[rr * 100 + cc + 1]   = acc[mi][ni][1];
            eg[(rr + 8) * 100 + cc]     = acc[mi][ni][2];
            eg[(rr + 8) * 100 + cc + 1] = acc[mi][ni][3];
        }
    __syncthreads();

    const int lr = tid >> 2;
    const int b = b0 + lr;
    const int jq = (tid & 3) * 8;
    const int jg = j0 + jq;
    const int tok = __ldg(&seq[b * Tt + t]);
    const float* tb = g_table + (size_t)tok * G3;
    const float* cp = g_ctxpart + (size_t)b * G3;
    const float* hold = g_hall + ((size_t)t * Bb + b) * Hd;
    float* hnew = g_hall + ((size_t)(t + 1) * Bb + b) * Hd;
    const int bufn = (t + 1) & 1;
    float hv[8];
#pragma unroll
    for (int q = 0; q < 2; q++) {
        float4 er = *(const float4*)&eg[lr * 100 + jq + q * 4];
        float4 ez = *(const float4*)&eg[lr * 100 + 32 + jq + q * 4];
        float4 en = *(const float4*)&eg[lr * 100 + 64 + jq + q * 4];
        float4 t_r = __ldg((const float4*)&tb[jg + q * 4]);
        float4 t_z = __ldg((const float4*)&tb[Hd + jg + q * 4]);
        float4 t_n = __ldg((const float4*)&tb[2 * Hd + jg + q * 4]);
        float4 c_r = __ldg((const float4*)&cp[jg + q * 4]);
        float4 c_z = __ldg((const float4*)&cp[Hd + jg + q * 4]);
        float4 c_n = __ldg((const float4*)&cp[2 * Hd + jg + q * 4]);
        float4 b_r = __ldg((const float4*)&bhh[jg + q * 4]);
        float4 b_z = __ldg((const float4*)&bhh[Hd + jg + q * 4]);
        float4 b_n = __ldg((const float4*)&bhh[2 * Hd + jg + q * 4]);
        float4 h_o = __ldcg((const float4*)&hold[jg + q * 4]);
#pragma unroll
        for (int e = 0; e < 4; e++) {
            float r = sigm(((const float*)&t_r)[e] + ((const float*)&c_r)[e]
                           + ((const float*)&er)[e] + ((const float*)&b_r)[e]);
            float u = sigm(((const float*)&t_z)[e] + ((const float*)&c_z)[e]
                           + ((const float*)&ez)[e] + ((const float*)&b_z)[e]);
            float n = tanh_f(((const float*)&t_n)[e] + ((const float*)&c_n)[e]
                             + r * (((const float*)&en)[e] + ((const float*)&b_n)[e]));
            hv[q * 4 + e] = (1.f - u) * n + u * ((const float*)&h_o)[e];
        }
    }
    *(float4*)&hnew[jg]     = *(float4*)&hv[0];
    *(float4*)&hnew[jg + 4] = *(float4*)&hv[4];
    uint32_t uh[4];
#pragma unroll
    for (int q = 0; q < 4; q++) {
        __half2 ph = __halves2half2(__float2half_rn(hv[q * 2]), __float2half_rn(hv[q * 2 + 1]));
        uh[q] = *(uint32_t*)&ph;
    }
    *(uint4*)&g_ah[((size_t)(bufn * Bb + b)) * Hd + jg] = make_uint4(uh[0], uh[1], uh[2], uh[3]);
}

__global__ void __launch_bounds__(NTHREADS, 1)
gru_kernel(const int* __restrict__ seq, const float* __restrict__ bhh) {
    extern __shared__ char smem[];
    __shared__ unsigned base_s;
    const int tid = threadIdx.x;
    const int bid = blockIdx.x;
    const uint32_t smem_b = smem_u32_of(smem);

    if (tid == 0) {
        unsigned p;
        asm volatile("ld.acquire.gpu.u32 %0, [%1];" : "=r"(p) : "l"(&g_phase) : "memory");
        base_s = p;
    }
    __syncthreads();
    const unsigned base = base_s;
    const int mt = bid & 3, nt = bid >> 2;

    for (int it = 0; it < Tt; ++it) {
        gh_tile(it, mt, nt, smem, smem_b, seq, bhh);
        gbar(base + (unsigned)it + 1u);
    }
}

// ---------------- bulk logits GEMM over the full h history ----------------
#define HSS 68
__global__ void __launch_bounds__(NTHREADS)
logits_kernel(const float* __restrict__ Wout, const float* __restrict__ bout,
              float* __restrict__ out) {
    __shared__ float hs[128 * HSS];
    __shared__ float wo[64 * HSS];
    const int cta = blockIdx.x;
    const int t = cta >> 1;
    const int b0 = (cta & 1) * 128;
    const float* hbase = g_hall + ((size_t)(t + 1) * Bb + b0) * Hd;
    const int tid = threadIdx.x;
    const int bl = tid >> 3;
    const int vq = tid & 7;

    unsigned long long acc[4][4];
#pragma unroll
    for (int r = 0; r < 4; r++)
#pragma unroll
        for (int i = 0; i < 4; i++) acc[r][i] = 0ull;

    for (int kc = 0; kc < Hd; kc += 64) {
        __syncthreads();
#pragma unroll
        for (int i = 0; i < 8; i++) {
            int idx = tid + 256 * i;
            int row = idx >> 4, kq = idx & 15;
            *(float4*)&hs[row * HSS + kq * 4] =
                __ldcg((const float4*)&hbase[(size_t)row * Hd + kc + kq * 4]);
        }
#pragma unroll
        for (int i = 0; i < 4; i++) {
            int idx = tid + 256 * i;
            int v = idx >> 4, kq = idx & 15;
            float4 w = __ldg((const float4*)&Wout[(size_t)v * Hd + kc + kq * 4]);
            wo[(kq * 4 + 0) * HSS + v] = w.x;
            wo[(kq * 4 + 1) * HSS + v] = w.y;
            wo[(kq * 4 + 2) * HSS + v] = w.z;
            wo[(kq * 4 + 3) * HSS + v] = w.w;
        }
        __syncthreads();
#pragma unroll 4
        for (int k = 0; k < 64; k++) {
            const float* wr = &wo[k * HSS + vq * 8];
            unsigned long long w0 = *(const unsigned long long*)&wr[0];
            unsigned long long w1 = *(const unsigned long long*)&wr[2];
            unsigned long long w2 = *(const unsigned long long*)&wr[4];
            unsigned long long w3 = *(const unsigned long long*)&wr[6];
#pragma unroll
            for (int r = 0; r < 4; r++) {
                float hvv = hs[(bl + r * 32) * HSS + k];
                unsigned long long hdp = pk2(hvv, hvv);
                fma2(acc[r][0], hdp, w0);
                fma2(acc[r][1], hdp, w1);
                fma2(acc[r][2], hdp, w2);
                fma2(acc[r][3], hdp, w3);
            }
        }
    }
#pragma unroll
    for (int r = 0; r < 4; r++) {
        int b = b0 + bl + r * 32;
        float* op = out + ((size_t)b * Tt + t) * Vv + vq * 8;
#pragma unroll
        for (int i = 0; i < 4; i++) {
            float2 v = unpk(acc[r][i]);
            float2 bo = *(const float2*)&bout[vq * 8 + i * 2];
            op[i * 2 + 0] = v.x + bo.x;
            op[i * 2 + 1] = v.y + bo.y;
        }
    }
}

// ---------------- launch ----------------
extern "C" void kernel_launch(void* const* d_in, const int* in_sizes, int n_in,
                              void* d_out, int out_size) {
    (void)in_sizes; (void)n_in; (void)out_size;
    const float* z    = (const float*)d_in[0];
    const float* c    = (const float*)d_in[1];
    const int*   seq  = (const int*)  d_in[2];
    const float* emb  = (const float*)d_in[3];
    const float* Wfch = (const float*)d_in[4];
    const float* bfch = (const float*)d_in[5];
    const float* Wih  = (const float*)d_in[6];
    const float* bih  = (const float*)d_in[7];
    const float* Whh  = (const float*)d_in[8];
    const float* bhh  = (const float*)d_in[9];
    const float* Wout = (const float*)d_in[10];
    const float* bout = (const float*)d_in[11];
    float* out = (float*)d_out;

    static int smem_set = 0;
    if (!smem_set) {
        cudaFuncSetAttribute(gru_kernel, cudaFuncAttributeMaxDynamicSharedMemorySize, SMEM_TOTAL);
        smem_set = 1;
    }

    ctx_kernel<<<32, NTHREADS>>>(z, c, Wih, bih);
    h0_kernel<<<32, NTHREADS>>>(z, c, Wfch, bfch);
    table_kernel<<<12, NTHREADS>>>(emb, Wih);
    wconv_kernel<<<128, NTHREADS>>>(Whh);
    gru_kernel<<<GRID, NTHREADS, SMEM_TOTAL>>>(seq, bhh);
    logits_kernel<<<Tt * 2, NTHREADS>>>(Wout, bout, out);
}

// round 12
// speedup vs baseline: 2.1176x; 1.1186x over previous
#include <cuda_runtime.h>
#include <cuda_fp16.h>
#include <cstdint>

#define Bb 256
#define Tt 256
#define Hd 1024
#define Ee 256
#define LC 320
#define EIN 576   // E + L + C
#define G3 3072
#define Vv 64

#define NGH 128
#define GRID NGH
#define NTHREADS 256

// smem: W resident [96][2048B] XOR-swizzled, then 2 A stages [64 rows x 272B]
#define W_BYTES 196608
#define SROW 272
#define STG 17408
#define SMEM_TOTAL (W_BYTES + 2 * STG)   // 231424

// ---------------- persistent device scratch ----------------
__device__ float g_ctxpart[Bb * G3];   // context @ W_ih[:,E:]^T + b_ih
__device__ float g_table[Vv * G3];     // emb @ W_ih[:,:E]^T
// full hidden-state history: slot s = h after step s-1 (slot 0 = h0)
__device__ float g_hall[(size_t)(Tt + 1) * Bb * Hd];
// fp16 hidden tiles, row-major [buf][b(256)][k(1024)]
__device__ __align__(16) __half g_ah[2 * Bb * Hd];
// fp16 W tiles: [nt(32)][p(96)=gate*32+jl][k(1024)]
__device__ __align__(16) __half g_wf[32 * 96 * Hd];
__device__ unsigned g_count = 0;
__device__ unsigned g_phase = 0;

// ---------------- helpers ----------------
__device__ __forceinline__ uint32_t smem_u32_of(const void* p) {
    uint32_t a;
    asm("{ .reg .u64 t; cvta.to.shared.u64 t, %1; cvt.u32.u64 %0, t; }" : "=r"(a) : "l"(p));
    return a;
}
__device__ __forceinline__ unsigned long long pk2(float x, float y) {
    unsigned long long r;
    asm("mov.b64 %0, {%1, %2};" : "=l"(r) : "f"(x), "f"(y));
    return r;
}
__device__ __forceinline__ float2 unpk(unsigned long long v) {
    float2 r;
    asm("mov.b64 {%0, %1}, %2;" : "=f"(r.x), "=f"(r.y) : "l"(v));
    return r;
}
__device__ __forceinline__ void fma2(unsigned long long& d, unsigned long long a, unsigned long long b) {
    asm("fma.rn.f32x2 %0, %1, %2, %0;" : "+l"(d) : "l"(a), "l"(b));
}
__device__ __forceinline__ float sigm(float x) { return 1.f / (1.f + __expf(-x)); }
__device__ __forceinline__ float tanh_f(float x) { return 2.f / (1.f + __expf(-2.f * x)) - 1.f; }

__device__ __forceinline__ void cpa16(uint32_t d, const void* s) {
    asm volatile("cp.async.cg.shared.global [%0], [%1], 16;" :: "r"(d), "l"(s) : "memory");
}
#define CP_COMMIT() asm volatile("cp.async.commit_group;" ::: "memory")
#define CP_WAIT0()  asm volatile("cp.async.wait_group 0;" ::: "memory")

__device__ __forceinline__ void ldsm_x4(uint32_t* r, uint32_t a) {
    asm volatile("ldmatrix.sync.aligned.m8n8.x4.shared.b16 {%0,%1,%2,%3}, [%4];"
                 : "=r"(r[0]), "=r"(r[1]), "=r"(r[2]), "=r"(r[3]) : "r"(a));
}
__device__ __forceinline__ void ldsm_x2(uint32_t* r, uint32_t a) {
    asm volatile("ldmatrix.sync.aligned.m8n8.x2.shared.b16 {%0,%1}, [%2];"
                 : "=r"(r[0]), "=r"(r[1]) : "r"(a));
}
__device__ __forceinline__ void mma16816(float* c, const uint32_t* a, const uint32_t* b) {
    asm volatile("mma.sync.aligned.m16n8k16.row.col.f32.f16.f16.f32 "
                 "{%0,%1,%2,%3}, {%4,%5,%6,%7}, {%8,%9}, {%0,%1,%2,%3};"
                 : "+f"(c[0]), "+f"(c[1]), "+f"(c[2]), "+f"(c[3])
                 : "r"(a[0]), "r"(a[1]), "r"(a[2]), "r"(a[3]), "r"(b[0]), "r"(b[1]));
}

// ---------------- grid barrier ----------------
__device__ __forceinline__ void gbar(unsigned target) {
    __syncthreads();
    if (threadIdx.x == 0) {
        unsigned n;
        asm volatile("atom.add.acq_rel.gpu.u32 %0, [%1], 1;"
                     : "=r"(n) : "l"(&g_count) : "memory");
        if (n == GRID - 1) {
            g_count = 0;
            asm volatile("st.release.gpu.u32 [%0], %1;"
                         :: "l"(&g_phase), "r"(target) : "memory");
        } else {
            unsigned p;
            do {
                asm volatile("ld.acquire.gpu.u32 %0, [%1];"
                             : "=r"(p) : "l"(&g_phase) : "memory");
            } while ((int)(p - target) < 0);
        }
        __threadfence();
    }
    __syncthreads();
}

// ---------------- precompute kernels ----------------
__global__ void ctx_kernel(const float* __restrict__ z, const float* __restrict__ c,
                           const float* __restrict__ Wih, const float* __restrict__ bih) {
    __shared__ float cs[8 * LC];
    int bc = blockIdx.x;
    for (int i = threadIdx.x; i < 8 * LC; i += NTHREADS) {
        int bb = i / LC, ii = i - bb * LC;
        int b = bc * 8 + bb;
        cs[i] = (ii < 256) ? z[b * 256 + ii] : c[b * 64 + (ii - 256)];
    }
    __syncthreads();
    for (int gk = 0; gk < 12; gk++) {
        int g = threadIdx.x + gk * NTHREADS;
        float acc[8];
        float bi = bih[g];
#pragma unroll
        for (int bb = 0; bb < 8; bb++) acc[bb] = bi;
        const float* wr = Wih + (size_t)g * EIN + Ee;
        for (int ii = 0; ii < LC; ii++) {
            float w = wr[ii];
#pragma unroll
            for (int bb = 0; bb < 8; bb++) acc[bb] += w * cs[bb * LC + ii];
        }
#pragma unroll
        for (int bb = 0; bb < 8; bb++) g_ctxpart[(size_t)(bc * 8 + bb) * G3 + g] = acc[bb];
    }
}

__global__ void h0_kernel(const float* __restrict__ z, const float* __restrict__ c,
                          const float* __restrict__ Wfch, const float* __restrict__ bfch) {
    __shared__ float cs[8 * LC];
    int bc = blockIdx.x;
    for (int i = threadIdx.x; i < 8 * LC; i += NTHREADS) {
        int bb = i / LC, ii = i - bb * LC;
        int b = bc * 8 + bb;
        cs[i] = (ii < 256) ? z[b * 256 + ii] : c[b * 64 + (ii - 256)];
    }
    __syncthreads();
    for (int jk = 0; jk < 4; jk++) {
        int j = threadIdx.x + jk * NTHREADS;
        float acc[8];
        float bj = bfch[j];
#pragma unroll
        for (int bb = 0; bb < 8; bb++) acc[bb] = bj;
        const float* wr = Wfch + (size_t)j * LC;
        for (int ii = 0; ii < LC; ii++) {
            float w = wr[ii];
#pragma unroll
            for (int bb = 0; bb < 8; bb++) acc[bb] += w * cs[bb * LC + ii];
        }
#pragma unroll
        for (int bb = 0; bb < 8; bb++) {
            int b = bc * 8 + bb;
            float v = acc[bb];
            g_hall[(size_t)b * Hd + j] = v;              // slot 0 = h0
            g_ah[(size_t)b * Hd + j] = __float2half_rn(v);   // buf 0
        }
    }
}

__global__ void table_kernel(const float* __restrict__ emb, const float* __restrict__ Wih) {
    __shared__ float es[Vv * 64];
    int g = blockIdx.x * NTHREADS + threadIdx.x;
    float acc[Vv];
#pragma unroll
    for (int v = 0; v < Vv; v++) acc[v] = 0.f;
    for (int ec = 0; ec < Ee / 64; ec++) {
        __syncthreads();
        for (int i = threadIdx.x; i < Vv * 64; i += NTHREADS) {
            int v = i >> 6, el = i & 63;
            es[i] = emb[(size_t)v * Ee + ec * 64 + el];
        }
        __syncthreads();
        const float* wr = Wih + (size_t)g * EIN + ec * 64;
#pragma unroll 8
        for (int e = 0; e < 64; e++) {
            float w = wr[e];
#pragma unroll
            for (int v = 0; v < Vv; v++) acc[v] += w * es[v * 64 + e];
        }
    }
    for (int v = 0; v < Vv; v++) g_table[(size_t)v * G3 + g] = acc[v];
}

// W_hh -> fp16, layout [nt][p=gate*32+jl][k]
__global__ void wconv_kernel(const float* __restrict__ Whh) {
    const size_t total = (size_t)32 * 96 * Hd;
    size_t stride = (size_t)gridDim.x * NTHREADS;
    for (size_t i = blockIdx.x * (size_t)NTHREADS + threadIdx.x; i < total; i += stride) {
        int k = (int)(i & 1023);
        int rf = (int)(i >> 10);        // nt*96 + p
        int nt = rf / 96, p = rf - nt * 96;
        int gate = p >> 5;
        int j = nt * 32 + (p & 31);
        g_wf[i] = __float2half_rn(Whh[((size_t)gate * Hd + j) * Hd + k]);
    }
}

// ---------------- persistent recurrent kernel (gh only) ----------------
// A stage s covers K chunk [s*128, s*128+128); W resident in swizzled smem.
__device__ __forceinline__ void stage_issue(uint32_t stg, int buf, int b0, int s) {
    const int tid = threadIdx.x;
    const char* agh = (const char*)(g_ah + ((size_t)(buf * Bb + b0)) * Hd + s * 128);
#pragma unroll
    for (int i = tid; i < 1024; i += NTHREADS) {
        int r = i >> 4, q = i & 15;
        cpa16(stg + r * SROW + q * 16, agh + (size_t)r * 2048 + q * 16);
    }
    CP_COMMIT();
}

__device__ void gh_tile(int t, int mt, int nt, char* smem, uint32_t smem_b,
                        const int* __restrict__ seq, const float* __restrict__ bhh) {
    const int tid = threadIdx.x;
    const int lane = tid & 31, wid = tid >> 5;
    const int mw = wid & 1, nw = wid >> 1;     // warp tile m32 x n24
    const int b0 = mt * 64, j0 = nt * 32;

    float acc[2][3][4];
#pragma unroll
    for (int mi = 0; mi < 2; mi++)
#pragma unroll
        for (int ni = 0; ni < 3; ni++)
#pragma unroll
            for (int q = 0; q < 4; q++) acc[mi][ni][q] = 0.f;

    const int arow = lane & 15;
    const int akoff = (lane >> 4) * 16;
    const int brow = lane & 7;
    const int bhalf = (lane >> 3) & 1;
    // resident-W row base addresses (swizzled layout: row p at p*2048)
    uint32_t wrow[3];
#pragma unroll
    for (int ni = 0; ni < 3; ni++)
        wrow[ni] = smem_b + ((uint32_t)(nw * 24 + ni * 8 + brow) << 11);

    const uint32_t stg_base = smem_b + W_BYTES;
    stage_issue(stg_base, t & 1, b0, 0);

    for (int s = 0; s < 8; s++) {
        CP_WAIT0();
        __syncthreads();
        if (s < 7) stage_issue(stg_base + ((s + 1) & 1) * STG, t & 1, b0, s + 1);
        uint32_t aB = stg_base + (s & 1) * STG + (mw * 32 + arow) * SROW + akoff;
#pragma unroll
        for (int ks = 0; ks < 8; ks++) {
            uint32_t ah0[4], ah1[4];
            ldsm_x4(ah0, aB + ks * 32);
            ldsm_x4(ah1, aB + 16 * SROW + ks * 32);
            // W chunk index within resident row: 16B chunks, c = (s*8+ks)*2 + bhalf
            const uint32_t wsw = (uint32_t)((((s * 8 + ks) << 1) | bhalf) ^ brow) << 4;
            uint32_t bh[3][2];
#pragma unroll
            for (int ni = 0; ni < 3; ni++)
                ldsm_x2(bh[ni], wrow[ni] + wsw);
#pragma unroll
            for (int ni = 0; ni < 3; ni++) {
                mma16816(acc[0][ni], ah0, bh[ni]);
                mma16816(acc[1][ni], ah1, bh[ni]);
            }
        }
    }

    // ---- epilogue: acc -> smem (A-stage area) -> fused GRU gating ----
    __syncthreads();
    float* eg = (float*)(smem + W_BYTES);   // [64][100], reuses A stages
    const int crow = lane >> 2;
    const int ccol = (lane & 3) * 2;
#pragma unroll
    for (int mi = 0; mi < 2; mi++)
#pragma unroll
        for (int ni = 0; ni < 3; ni++) {
            int rr = mw * 32 + mi * 16 + crow;
            int cc = nw * 24 + ni * 8 + ccol;
            eg[rr * 100 + cc]       = acc[mi][ni][0];
            eg[rr * 100 + cc + 1]   = acc[mi][ni][1];
            eg[(rr + 8) * 100 + cc]     = acc[mi][ni][2];
            eg[(rr + 8) * 100 + cc + 1] = acc[mi][ni][3];
        }
    __syncthreads();

    const int lr = tid >> 2;
    const int b = b0 + lr;
    const int jq = (tid & 3) * 8;
    const int jg = j0 + jq;
    const int tok = __ldg(&seq[b * Tt + t]);
    const float* tb = g_table + (size_t)tok * G3;
    const float* cp = g_ctxpart + (size_t)b * G3;
    const float* hold = g_hall + ((size_t)t * Bb + b) * Hd;
    float* hnew = g_hall + ((size_t)(t + 1) * Bb + b) * Hd;
    const int bufn = (t + 1) & 1;
    float hv[8];
#pragma unroll
    for (int q = 0; q < 2; q++) {
        float4 er = *(const float4*)&eg[lr * 100 + jq + q * 4];
        float4 ez = *(const float4*)&eg[lr * 100 + 32 + jq + q * 4];
        float4 en = *(const float4*)&eg[lr * 100 + 64 + jq + q * 4];
        float4 t_r = __ldg((const float4*)&tb[jg + q * 4]);
        float4 t_z = __ldg((const float4*)&tb[Hd + jg + q * 4]);
        float4 t_n = __ldg((const float4*)&tb[2 * Hd + jg + q * 4]);
        float4 c_r = __ldg((const float4*)&cp[jg + q * 4]);
        float4 c_z = __ldg((const float4*)&cp[Hd + jg + q * 4]);
        float4 c_n = __ldg((const float4*)&cp[2 * Hd + jg + q * 4]);
        float4 b_r = __ldg((const float4*)&bhh[jg + q * 4]);
        float4 b_z = __ldg((const float4*)&bhh[Hd + jg + q * 4]);
        float4 b_n = __ldg((const float4*)&bhh[2 * Hd + jg + q * 4]);
        float4 h_o = __ldcg((const float4*)&hold[jg + q * 4]);
#pragma unroll
        for (int e = 0; e < 4; e++) {
            float r = sigm(((const float*)&t_r)[e] + ((const float*)&c_r)[e]
                           + ((const float*)&er)[e] + ((const float*)&b_r)[e]);
            float u = sigm(((const float*)&t_z)[e] + ((const float*)&c_z)[e]
                           + ((const float*)&ez)[e] + ((const float*)&b_z)[e]);
            float n = tanh_f(((const float*)&t_n)[e] + ((const float*)&c_n)[e]
                             + r * (((const float*)&en)[e] + ((const float*)&b_n)[e]));
            hv[q * 4 + e] = (1.f - u) * n + u * ((const float*)&h_o)[e];
        }
    }
    *(float4*)&hnew[jg]     = *(float4*)&hv[0];
    *(float4*)&hnew[jg + 4] = *(float4*)&hv[4];
    uint32_t uh[4];
#pragma unroll
    for (int q = 0; q < 4; q++) {
        __half2 ph = __halves2half2(__float2half_rn(hv[q * 2]), __float2half_rn(hv[q * 2 + 1]));
        uh[q] = *(uint32_t*)&ph;
    }
    *(uint4*)&g_ah[((size_t)(bufn * Bb + b)) * Hd + jg] = make_uint4(uh[0], uh[1], uh[2], uh[3]);
}

__global__ void __launch_bounds__(NTHREADS, 1)
gru_kernel(const int* __restrict__ seq, const float* __restrict__ bhh) {
    extern __shared__ char smem[];
    __shared__ unsigned base_s;
    const int tid = threadIdx.x;
    const int bid = blockIdx.x;
    const uint32_t smem_b = smem_u32_of(smem);
    const int mt = bid & 3, nt = bid >> 2;

    // ---- load resident W (once), XOR-swizzled: chunk c of row p at ((c^(p&7))<<4) ----
    {
        const char* wsrc = (const char*)(g_wf + (size_t)nt * 96 * Hd);
        for (int i = tid; i < 12288; i += NTHREADS) {
            int p = i >> 7, c = i & 127;
            cpa16(smem_b + (p << 11) + (((c ^ (p & 7))) << 4), wsrc + (size_t)p * 2048 + c * 16);
        }
        CP_COMMIT();
    }
    if (tid == 0) {
        unsigned p;
        asm volatile("ld.acquire.gpu.u32 %0, [%1];" : "=r"(p) : "l"(&g_phase) : "memory");
        base_s = p;
    }
    CP_WAIT0();
    __syncthreads();
    const unsigned base = base_s;

    for (int it = 0; it < Tt; ++it) {
        gh_tile(it, mt, nt, smem, smem_b, seq, bhh);
        gbar(base + (unsigned)it + 1u);
    }
}

// ---------------- bulk logits GEMM over the full h history ----------------
#define HSS 68
__global__ void __launch_bounds__(NTHREADS)
logits_kernel(const float* __restrict__ Wout, const float* __restrict__ bout,
              float* __restrict__ out) {
    __shared__ float hs[128 * HSS];
    __shared__ float wo[64 * HSS];
    const int cta = blockIdx.x;
    const int t = cta >> 1;
    const int b0 = (cta & 1) * 128;
    const float* hbase = g_hall + ((size_t)(t + 1) * Bb + b0) * Hd;
    const int tid = threadIdx.x;
    const int bl = tid >> 3;
    const int vq = tid & 7;

    unsigned long long acc[4][4];
#pragma unroll
    for (int r = 0; r < 4; r++)
#pragma unroll
        for (int i = 0; i < 4; i++) acc[r][i] = 0ull;

    for (int kc = 0; kc < Hd; kc += 64) {
        __syncthreads();
#pragma unroll
        for (int i = 0; i < 8; i++) {
            int idx = tid + 256 * i;
            int row = idx >> 4, kq = idx & 15;
            *(float4*)&hs[row * HSS + kq * 4] =
                __ldcg((const float4*)&hbase[(size_t)row * Hd + kc + kq * 4]);
        }
#pragma unroll
        for (int i = 0; i < 4; i++) {
            int idx = tid + 256 * i;
            int v = idx >> 4, kq = idx & 15;
            float4 w = __ldg((const float4*)&Wout[(size_t)v * Hd + kc + kq * 4]);
            wo[(kq * 4 + 0) * HSS + v] = w.x;
            wo[(kq * 4 + 1) * HSS + v] = w.y;
            wo[(kq * 4 + 2) * HSS + v] = w.z;
            wo[(kq * 4 + 3) * HSS + v] = w.w;
        }
        __syncthreads();
#pragma unroll 4
        for (int k = 0; k < 64; k++) {
            const float* wr = &wo[k * HSS + vq * 8];
            unsigned long long w0 = *(const unsigned long long*)&wr[0];
            unsigned long long w1 = *(const unsigned long long*)&wr[2];
            unsigned long long w2 = *(const unsigned long long*)&wr[4];
            unsigned long long w3 = *(const unsigned long long*)&wr[6];
#pragma unroll
            for (int r = 0; r < 4; r++) {
                float hvv = hs[(bl + r * 32) * HSS + k];
                unsigned long long hdp = pk2(hvv, hvv);
                fma2(acc[r][0], hdp, w0);
                fma2(acc[r][1], hdp, w1);
                fma2(acc[r][2], hdp, w2);
                fma2(acc[r][3], hdp, w3);
            }
        }
    }
#pragma unroll
    for (int r = 0; r < 4; r++) {
        int b = b0 + bl + r * 32;
        float* op = out + ((size_t)b * Tt + t) * Vv + vq * 8;
#pragma unroll
        for (int i = 0; i < 4; i++) {
            float2 v = unpk(acc[r][i]);
            float2 bo = *(const float2*)&bout[vq * 8 + i * 2];
            op[i * 2 + 0] = v.x + bo.x;
            op[i * 2 + 1] = v.y + bo.y;
        }
    }
}

// ---------------- launch ----------------
extern "C" void kernel_launch(void* const* d_in, const int* in_sizes, int n_in,
                              void* d_out, int out_size) {
    (void)in_sizes; (void)n_in; (void)out_size;
    const float* z    = (const float*)d_in[0];
    const float* c    = (const float*)d_in[1];
    const int*   seq  = (const int*)  d_in[2];
    const float* emb  = (const float*)d_in[3];
    const float* Wfch = (const float*)d_in[4];
    const float* bfch = (const float*)d_in[5];
    const float* Wih  = (const float*)d_in[6];
    const float* bih  = (const float*)d_in[7];
    const float* Whh  = (const float*)d_in[8];
    const float* bhh  = (const float*)d_in[9];
    const float* Wout = (const float*)d_in[10];
    const float* bout = (const float*)d_in[11];
    float* out = (float*)d_out;

    static int smem_set = 0;
    if (!smem_set) {
        cudaFuncSetAttribute(gru_kernel, cudaFuncAttributeMaxDynamicSharedMemorySize, SMEM_TOTAL);
        smem_set = 1;
    }

    ctx_kernel<<<32, NTHREADS>>>(z, c, Wih, bih);
    h0_kernel<<<32, NTHREADS>>>(z, c, Wfch, bfch);
    table_kernel<<<12, NTHREADS>>>(emb, Wih);
    wconv_kernel<<<128, NTHREADS>>>(Whh);
    gru_kernel<<<GRID, NTHREADS, SMEM_TOTAL>>>(seq, bhh);
    logits_kernel<<<Tt * 2, NTHREADS>>>(Wout, bout, out);
}

// round 13
// speedup vs baseline: 2.2133x; 1.0452x over previous
#include <cuda_runtime.h>
#include <cuda_fp16.h>
#include <cstdint>

#define Bb 256
#define Tt 256
#define Hd 1024
#define Ee 256
#define LC 320
#define EIN 576   // E + L + C
#define G3 3072
#define Vv 64

#define NGH 128
#define GRID NGH
#define NTHREADS 256

// smem: W resident [96][2048B] XOR-swizzled, then 2 A stages [64 rows x 272B]
#define W_BYTES 196608
#define SROW 272
#define STG 17408
#define SMEM_TOTAL (W_BYTES + 2 * STG)   // 231424

// ---------------- persistent device scratch ----------------
__device__ float g_ctxpart[Bb * G3];   // context @ W_ih[:,E:]^T + b_ih
__device__ float g_table[Vv * G3];     // emb @ W_ih[:,:E]^T
// full hidden-state history: slot s = h after step s-1 (slot 0 = h0)
__device__ float g_hall[(size_t)(Tt + 1) * Bb * Hd];
// fp16 hidden tiles, row-major [buf][b(256)][k(1024)]
__device__ __align__(16) __half g_ah[2 * Bb * Hd];
// fp16 W tiles: [nt(32)][p(96)=gate*32+jl][k(1024)]
__device__ __align__(16) __half g_wf[32 * 96 * Hd];
// per-mt barrier state, 128B-spaced to avoid cross-group L2 line contention
__device__ unsigned g_cnt[4 * 32];
__device__ unsigned g_ph[4 * 32];

// ---------------- helpers ----------------
__device__ __forceinline__ uint32_t smem_u32_of(const void* p) {
    uint32_t a;
    asm("{ .reg .u64 t; cvta.to.shared.u64 t, %1; cvt.u32.u64 %0, t; }" : "=r"(a) : "l"(p));
    return a;
}
__device__ __forceinline__ unsigned long long pk2(float x, float y) {
    unsigned long long r;
    asm("mov.b64 %0, {%1, %2};" : "=l"(r) : "f"(x), "f"(y));
    return r;
}
__device__ __forceinline__ float2 unpk(unsigned long long v) {
    float2 r;
    asm("mov.b64 {%0, %1}, %2;" : "=f"(r.x), "=f"(r.y) : "l"(v));
    return r;
}
__device__ __forceinline__ void fma2(unsigned long long& d, unsigned long long a, unsigned long long b) {
    asm("fma.rn.f32x2 %0, %1, %2, %0;" : "+l"(d) : "l"(a), "l"(b));
}
__device__ __forceinline__ float sigm(float x) { return 1.f / (1.f + __expf(-x)); }
__device__ __forceinline__ float tanh_f(float x) { return 2.f / (1.f + __expf(-2.f * x)) - 1.f; }

__device__ __forceinline__ void cpa16(uint32_t d, const void* s) {
    asm volatile("cp.async.cg.shared.global [%0], [%1], 16;" :: "r"(d), "l"(s) : "memory");
}
#define CP_COMMIT() asm volatile("cp.async.commit_group;" ::: "memory")
#define CP_WAIT0()  asm volatile("cp.async.wait_group 0;" ::: "memory")

__device__ __forceinline__ void ldsm_x4(uint32_t* r, uint32_t a) {
    asm volatile("ldmatrix.sync.aligned.m8n8.x4.shared.b16 {%0,%1,%2,%3}, [%4];"
                 : "=r"(r[0]), "=r"(r[1]), "=r"(r[2]), "=r"(r[3]) : "r"(a));
}
__device__ __forceinline__ void ldsm_x2(uint32_t* r, uint32_t a) {
    asm volatile("ldmatrix.sync.aligned.m8n8.x2.shared.b16 {%0,%1}, [%2];"
                 : "=r"(r[0]), "=r"(r[1]) : "r"(a));
}
__device__ __forceinline__ void mma16816(float* c, const uint32_t* a, const uint32_t* b) {
    asm volatile("mma.sync.aligned.m16n8k16.row.col.f32.f16.f16.f32 "
                 "{%0,%1,%2,%3}, {%4,%5,%6,%7}, {%8,%9}, {%0,%1,%2,%3};"
                 : "+f"(c[0]), "+f"(c[1]), "+f"(c[2]), "+f"(c[3])
                 : "r"(a[0]), "r"(a[1]), "r"(a[2]), "r"(a[3]), "r"(b[0]), "r"(b[1]));
}

// ---------------- per-mt group barrier (32 CTAs; no L1 flush) ----------------
// Safe without threadfence: all step-varying cross-CTA reads bypass L1
// (cp.async.cg / __ldcg), and acq_rel/release-acquire atomics order the writes.
__device__ __forceinline__ void gbar_grp(unsigned* cnt, unsigned* ph, unsigned target) {
    __syncthreads();
    if (threadIdx.x == 0) {
        unsigned n;
        asm volatile("atom.add.acq_rel.gpu.u32 %0, [%1], 1;"
                     : "=r"(n) : "l"(cnt) : "memory");
        if (n == 31) {
            *cnt = 0;   // ordered before the release-store below
            asm volatile("st.release.gpu.u32 [%0], %1;"
                         :: "l"(ph), "r"(target) : "memory");
        } else {
            unsigned p;
            do {
                asm volatile("ld.acquire.gpu.u32 %0, [%1];"
                             : "=r"(p) : "l"(ph) : "memory");
            } while ((int)(p - target) < 0);
        }
    }
    __syncthreads();
}

// ---------------- precompute kernels ----------------
__global__ void ctx_kernel(const float* __restrict__ z, const float* __restrict__ c,
                           const float* __restrict__ Wih, const float* __restrict__ bih) {
    __shared__ float cs[8 * LC];
    int bc = blockIdx.x;
    for (int i = threadIdx.x; i < 8 * LC; i += NTHREADS) {
        int bb = i / LC, ii = i - bb * LC;
        int b = bc * 8 + bb;
        cs[i] = (ii < 256) ? z[b * 256 + ii] : c[b * 64 + (ii - 256)];
    }
    __syncthreads();
    for (int gk = 0; gk < 12; gk++) {
        int g = threadIdx.x + gk * NTHREADS;
        float acc[8];
        float bi = bih[g];
#pragma unroll
        for (int bb = 0; bb < 8; bb++) acc[bb] = bi;
        const float* wr = Wih + (size_t)g * EIN + Ee;
        for (int ii = 0; ii < LC; ii++) {
            float w = wr[ii];
#pragma unroll
            for (int bb = 0; bb < 8; bb++) acc[bb] += w * cs[bb * LC + ii];
        }
#pragma unroll
        for (int bb = 0; bb < 8; bb++) g_ctxpart[(size_t)(bc * 8 + bb) * G3 + g] = acc[bb];
    }
}

__global__ void h0_kernel(const float* __restrict__ z, const float* __restrict__ c,
                          const float* __restrict__ Wfch, const float* __restrict__ bfch) {
    __shared__ float cs[8 * LC];
    int bc = blockIdx.x;
    for (int i = threadIdx.x; i < 8 * LC; i += NTHREADS) {
        int bb = i / LC, ii = i - bb * LC;
        int b = bc * 8 + bb;
        cs[i] = (ii < 256) ? z[b * 256 + ii] : c[b * 64 + (ii - 256)];
    }
    __syncthreads();
    for (int jk = 0; jk < 4; jk++) {
        int j = threadIdx.x + jk * NTHREADS;
        float acc[8];
        float bj = bfch[j];
#pragma unroll
        for (int bb = 0; bb < 8; bb++) acc[bb] = bj;
        const float* wr = Wfch + (size_t)j * LC;
        for (int ii = 0; ii < LC; ii++) {
            float w = wr[ii];
#pragma unroll
            for (int bb = 0; bb < 8; bb++) acc[bb] += w * cs[bb * LC + ii];
        }
#pragma unroll
        for (int bb = 0; bb < 8; bb++) {
            int b = bc * 8 + bb;
            float v = acc[bb];
            g_hall[(size_t)b * Hd + j] = v;              // slot 0 = h0
            g_ah[(size_t)b * Hd + j] = __float2half_rn(v);   // buf 0
        }
    }
}

__global__ void table_kernel(const float* __restrict__ emb, const float* __restrict__ Wih) {
    __shared__ float es[Vv * 64];
    int g = blockIdx.x * NTHREADS + threadIdx.x;
    float acc[Vv];
#pragma unroll
    for (int v = 0; v < Vv; v++) acc[v] = 0.f;
    for (int ec = 0; ec < Ee / 64; ec++) {
        __syncthreads();
        for (int i = threadIdx.x; i < Vv * 64; i += NTHREADS) {
            int v = i >> 6, el = i & 63;
            es[i] = emb[(size_t)v * Ee + ec * 64 + el];
        }
        __syncthreads();
        const float* wr = Wih + (size_t)g * EIN + ec * 64;
#pragma unroll 8
        for (int e = 0; e < 64; e++) {
            float w = wr[e];
#pragma unroll
            for (int v = 0; v < Vv; v++) acc[v] += w * es[v * 64 + e];
        }
    }
    for (int v = 0; v < Vv; v++) g_table[(size_t)v * G3 + g] = acc[v];
}

// W_hh -> fp16, layout [nt][p=gate*32+jl][k]
__global__ void wconv_kernel(const float* __restrict__ Whh) {
    const size_t total = (size_t)32 * 96 * Hd;
    size_t stride = (size_t)gridDim.x * NTHREADS;
    for (size_t i = blockIdx.x * (size_t)NTHREADS + threadIdx.x; i < total; i += stride) {
        int k = (int)(i & 1023);
        int rf = (int)(i >> 10);        // nt*96 + p
        int nt = rf / 96, p = rf - nt * 96;
        int gate = p >> 5;
        int j = nt * 32 + (p & 31);
        g_wf[i] = __float2half_rn(Whh[((size_t)gate * Hd + j) * Hd + k]);
    }
}

// ---------------- persistent recurrent kernel (gh only) ----------------
// A stage s covers K chunk [s*128, s*128+128); W resident in swizzled smem.
__device__ __forceinline__ void stage_issue(uint32_t stg, int buf, int b0, int s) {
    const int tid = threadIdx.x;
    const char* agh = (const char*)(g_ah + ((size_t)(buf * Bb + b0)) * Hd + s * 128);
#pragma unroll
    for (int i = tid; i < 1024; i += NTHREADS) {
        int r = i >> 4, q = i & 15;
        cpa16(stg + r * SROW + q * 16, agh + (size_t)r * 2048 + q * 16);
    }
    CP_COMMIT();
}

__device__ void gh_tile(int t, int mt, int nt, char* smem, uint32_t smem_b,
                        const int* __restrict__ seq, const float* __restrict__ bhh) {
    const int tid = threadIdx.x;
    const int lane = tid & 31, wid = tid >> 5;
    const int mw = wid & 1, nw = wid >> 1;     // warp tile m32 x n24
    const int b0 = mt * 64, j0 = nt * 32;

    float acc[2][3][4];
#pragma unroll
    for (int mi = 0; mi < 2; mi++)
#pragma unroll
        for (int ni = 0; ni < 3; ni++)
#pragma unroll
            for (int q = 0; q < 4; q++) acc[mi][ni][q] = 0.f;

    const int arow = lane & 15;
    const int akoff = (lane >> 4) * 16;
    const int brow = lane & 7;
    const int bhalf = (lane >> 3) & 1;
    // resident-W row base addresses (swizzled layout: row p at p*2048)
    uint32_t wrow[3];
#pragma unroll
    for (int ni = 0; ni < 3; ni++)
        wrow[ni] = smem_b + ((uint32_t)(nw * 24 + ni * 8 + brow) << 11);

    const uint32_t stg_base = smem_b + W_BYTES;
    stage_issue(stg_base, t & 1, b0, 0);

    for (int s = 0; s < 8; s++) {
        CP_WAIT0();
        __syncthreads();
        if (s < 7) stage_issue(stg_base + ((s + 1) & 1) * STG, t & 1, b0, s + 1);
        uint32_t aB = stg_base + (s & 1) * STG + (mw * 32 + arow) * SROW + akoff;
#pragma unroll
        for (int ks = 0; ks < 8; ks++) {
            uint32_t ah0[4], ah1[4];
            ldsm_x4(ah0, aB + ks * 32);
            ldsm_x4(ah1, aB + 16 * SROW + ks * 32);
            // W chunk index within resident row: 16B chunks, c = (s*8+ks)*2 + bhalf
            const uint32_t wsw = (uint32_t)((((s * 8 + ks) << 1) | bhalf) ^ brow) << 4;
            uint32_t bh[3][2];
#pragma unroll
            for (int ni = 0; ni < 3; ni++)
                ldsm_x2(bh[ni], wrow[ni] + wsw);
#pragma unroll
            for (int ni = 0; ni < 3; ni++) {
                mma16816(acc[0][ni], ah0, bh[ni]);
                mma16816(acc[1][ni], ah1, bh[ni]);
            }
        }
    }

    // ---- epilogue: acc -> smem (A-stage area) -> fused GRU gating ----
    __syncthreads();
    float* eg = (float*)(smem + W_BYTES);   // [64][100], reuses A stages
    const int crow = lane >> 2;
    const int ccol = (lane & 3) * 2;
#pragma unroll
    for (int mi = 0; mi < 2; mi++)
#pragma unroll
        for (int ni = 0; ni < 3; ni++) {
            int rr = mw * 32 + mi * 16 + crow;
            int cc = nw * 24 + ni * 8 + ccol;
            eg[rr * 100 + cc]       = acc[mi][ni][0];
            eg[rr * 100 + cc + 1]   = acc[mi][ni][1];
            eg[(rr + 8) * 100 + cc]     = acc[mi][ni][2];
            eg[(rr + 8) * 100 + cc + 1] = acc[mi][ni][3];
        }
    __syncthreads();

    const int lr = tid >> 2;
    const int b = b0 + lr;
    const int jq = (tid & 3) * 8;
    const int jg = j0 + jq;
    const int tok = __ldg(&seq[b * Tt + t]);
    const float* tb = g_table + (size_t)tok * G3;
    const float* cp = g_ctxpart + (size_t)b * G3;
    const float* hold = g_hall + ((size_t)t * Bb + b) * Hd;
    float* hnew = g_hall + ((size_t)(t + 1) * Bb + b) * Hd;
    const int bufn = (t + 1) & 1;
    float hv[8];
#pragma unroll
    for (int q = 0; q < 2; q++) {
        float4 er = *(const float4*)&eg[lr * 100 + jq + q * 4];
        float4 ez = *(const float4*)&eg[lr * 100 + 32 + jq + q * 4];
        float4 en = *(const float4*)&eg[lr * 100 + 64 + jq + q * 4];
        float4 t_r = __ldg((const float4*)&tb[jg + q * 4]);
        float4 t_z = __ldg((const float4*)&tb[Hd + jg + q * 4]);
        float4 t_n = __ldg((const float4*)&tb[2 * Hd + jg + q * 4]);
        float4 c_r = __ldg((const float4*)&cp[jg + q * 4]);
        float4 c_z = __ldg((const float4*)&cp[Hd + jg + q * 4]);
        float4 c_n = __ldg((const float4*)&cp[2 * Hd + jg + q * 4]);
        float4 b_r = __ldg((const float4*)&bhh[jg + q * 4]);
        float4 b_z = __ldg((const float4*)&bhh[Hd + jg + q * 4]);
        float4 b_n = __ldg((const float4*)&bhh[2 * Hd + jg + q * 4]);
        float4 h_o = __ldcg((const float4*)&hold[jg + q * 4]);
#pragma unroll
        for (int e = 0; e < 4; e++) {
            float r = sigm(((const float*)&t_r)[e] + ((const float*)&c_r)[e]
                           + ((const float*)&er)[e] + ((const float*)&b_r)[e]);
            float u = sigm(((const float*)&t_z)[e] + ((const float*)&c_z)[e]
                           + ((const float*)&ez)[e] + ((const float*)&b_z)[e]);
            float n = tanh_f(((const float*)&t_n)[e] + ((const float*)&c_n)[e]
                             + r * (((const float*)&en)[e] + ((const float*)&b_n)[e]));
            hv[q * 4 + e] = (1.f - u) * n + u * ((const float*)&h_o)[e];
        }
    }
    *(float4*)&hnew[jg]     = *(float4*)&hv[0];
    *(float4*)&hnew[jg + 4] = *(float4*)&hv[4];
    uint32_t uh[4];
#pragma unroll
    for (int q = 0; q < 4; q++) {
        __half2 ph = __halves2half2(__float2half_rn(hv[q * 2]), __float2half_rn(hv[q * 2 + 1]));
        uh[q] = *(uint32_t*)&ph;
    }
    *(uint4*)&g_ah[((size_t)(bufn * Bb + b)) * Hd + jg] = make_uint4(uh[0], uh[1], uh[2], uh[3]);
}

__global__ void __launch_bounds__(NTHREADS, 1)
gru_kernel(const int* __restrict__ seq, const float* __restrict__ bhh) {
    extern __shared__ char smem[];
    __shared__ unsigned base_s;
    const int tid = threadIdx.x;
    const int bid = blockIdx.x;
    const uint32_t smem_b = smem_u32_of(smem);
    const int mt = bid & 3, nt = bid >> 2;
    unsigned* cnt = &g_cnt[mt * 32];
    unsigned* ph = &g_ph[mt * 32];

    // ---- load resident W (once), XOR-swizzled: chunk c of row p at ((c^(p&7))<<4) ----
    {
        const char* wsrc = (const char*)(g_wf + (size_t)nt * 96 * Hd);
        for (int i = tid; i < 12288; i += NTHREADS) {
            int p = i >> 7, c = i & 127;
            cpa16(smem_b + (p << 11) + (((c ^ (p & 7))) << 4), wsrc + (size_t)p * 2048 + c * 16);
        }
        CP_COMMIT();
    }
    if (tid == 0) {
        unsigned p;
        asm volatile("ld.acquire.gpu.u32 %0, [%1];" : "=r"(p) : "l"(ph) : "memory");
        base_s = p;
    }
    CP_WAIT0();
    __syncthreads();
    const unsigned base = base_s;

    for (int it = 0; it < Tt; ++it) {
        gh_tile(it, mt, nt, smem, smem_b, seq, bhh);
        gbar_grp(cnt, ph, base + (unsigned)it + 1u);
    }
}

// ---------------- bulk logits GEMM over the full h history ----------------
#define HSS 68
__global__ void __launch_bounds__(NTHREADS)
logits_kernel(const float* __restrict__ Wout, const float* __restrict__ bout,
              float* __restrict__ out) {
    __shared__ float hs[128 * HSS];
    __shared__ float wo[64 * HSS];
    const int cta = blockIdx.x;
    const int t = cta >> 1;
    const int b0 = (cta & 1) * 128;
    const float* hbase = g_hall + ((size_t)(t + 1) * Bb + b0) * Hd;
    const int tid = threadIdx.x;
    const int bl = tid >> 3;
    const int vq = tid & 7;

    unsigned long long acc[4][4];
#pragma unroll
    for (int r = 0; r < 4; r++)
#pragma unroll
        for (int i = 0; i < 4; i++) acc[r][i] = 0ull;

    for (int kc = 0; kc < Hd; kc += 64) {
        __syncthreads();
#pragma unroll
        for (int i = 0; i < 8; i++) {
            int idx = tid + 256 * i;
            int row = idx >> 4, kq = idx & 15;
            *(float4*)&hs[row * HSS + kq * 4] =
                __ldcg((const float4*)&hbase[(size_t)row * Hd + kc + kq * 4]);
        }
#pragma unroll
        for (int i = 0; i < 4; i++) {
            int idx = tid + 256 * i;
            int v = idx >> 4, kq = idx & 15;
            float4 w = __ldg((const float4*)&Wout[(size_t)v * Hd + kc + kq * 4]);
            wo[(kq * 4 + 0) * HSS + v] = w.x;
            wo[(kq * 4 + 1) * HSS + v] = w.y;
            wo[(kq * 4 + 2) * HSS + v] = w.z;
            wo[(kq * 4 + 3) * HSS + v] = w.w;
        }
        __syncthreads();
#pragma unroll 4
        for (int k = 0; k < 64; k++) {
            const float* wr = &wo[k * HSS + vq * 8];
            unsigned long long w0 = *(const unsigned long long*)&wr[0];
            unsigned long long w1 = *(const unsigned long long*)&wr[2];
            unsigned long long w2 = *(const unsigned long long*)&wr[4];
            unsigned long long w3 = *(const unsigned long long*)&wr[6];
#pragma unroll
            for (int r = 0; r < 4; r++) {
                float hvv = hs[(bl + r * 32) * HSS + k];
                unsigned long long hdp = pk2(hvv, hvv);
                fma2(acc[r][0], hdp, w0);
                fma2(acc[r][1], hdp, w1);
                fma2(acc[r][2], hdp, w2);
                fma2(acc[r][3], hdp, w3);
            }
        }
    }
#pragma unroll
    for (int r = 0; r < 4; r++) {
        int b = b0 + bl + r * 32;
        float* op = out + ((size_t)b * Tt + t) * Vv + vq * 8;
#pragma unroll
        for (int i = 0; i < 4; i++) {
            float2 v = unpk(acc[r][i]);
            float2 bo = *(const float2*)&bout[vq * 8 + i * 2];
            op[i * 2 + 0] = v.x + bo.x;
            op[i * 2 + 1] = v.y + bo.y;
        }
    }
}

// ---------------- launch ----------------
extern "C" void kernel_launch(void* const* d_in, const int* in_sizes, int n_in,
                              void* d_out, int out_size) {
    (void)in_sizes; (void)n_in; (void)out_size;
    const float* z    = (const float*)d_in[0];
    const float* c    = (const float*)d_in[1];
    const int*   seq  = (const int*)  d_in[2];
    const float* emb  = (const float*)d_in[3];
    const float* Wfch = (const float*)d_in[4];
    const float* bfch = (const float*)d_in[5];
    const float* Wih  = (const float*)d_in[6];
    const float* bih  = (const float*)d_in[7];
    const float* Whh  = (const float*)d_in[8];
    const float* bhh  = (const float*)d_in[9];
    const float* Wout = (const float*)d_in[10];
    const float* bout = (const float*)d_in[11];
    float* out = (float*)d_out;

    static int smem_set = 0;
    if (!smem_set) {
        cudaFuncSetAttribute(gru_kernel, cudaFuncAttributeMaxDynamicSharedMemorySize, SMEM_TOTAL);
        smem_set = 1;
    }

    ctx_kernel<<<32, NTHREADS>>>(z, c, Wih, bih);
    h0_kernel<<<32, NTHREADS>>>(z, c, Wfch, bfch);
    table_kernel<<<12, NTHREADS>>>(emb, Wih);
    wconv_kernel<<<128, NTHREADS>>>(Whh);
    gru_kernel<<<GRID, NTHREADS, SMEM_TOTAL>>>(seq, bhh);
    logits_kernel<<<Tt * 2, NTHREADS>>>(Wout, bout, out);
}

// round 14
// speedup vs baseline: 2.3567x; 1.0648x over previous
#include <cuda_runtime.h>
#include <cuda_fp16.h>
#include <cstdint>

#define Bb 256
#define Tt 256
#define Hd 1024
#define Ee 256
#define LC 320
#define EIN 576   // E + L + C
#define G3 3072
#define Vv 64

#define NGH 128
#define GRID NGH
#define NTHREADS 256

// smem: W resident [96][2048B] XOR-swizzled, then per-group double-buffered A stages:
//   group g (mw), buffer b at W_BYTES + (g*2+b)*GSTG; 32 rows x 272B each
#define W_BYTES 196608
#define SROW 272
#define GSTG 8704
#define SMEM_TOTAL (W_BYTES + 4 * GSTG)   // 231424

// ---------------- persistent device scratch ----------------
__device__ float g_ctxpart[Bb * G3];   // context @ W_ih[:,E:]^T + b_ih
__device__ float g_table[Vv * G3];     // emb @ W_ih[:,:E]^T
// full hidden-state history: slot s = h after step s-1 (slot 0 = h0)
__device__ float g_hall[(size_t)(Tt + 1) * Bb * Hd];
// fp16 hidden tiles, row-major [buf][b(256)][k(1024)]
__device__ __align__(16) __half g_ah[2 * Bb * Hd];
// fp16 W tiles: [nt(32)][p(96)=gate*32+jl][k(1024)]
__device__ __align__(16) __half g_wf[32 * 96 * Hd];
// per-mt barrier state, spaced to avoid cross-group line contention
__device__ unsigned g_cnt[4 * 32];
__device__ unsigned g_ph[4 * 32];

// ---------------- helpers ----------------
__device__ __forceinline__ uint32_t smem_u32_of(const void* p) {
    uint32_t a;
    asm("{ .reg .u64 t; cvta.to.shared.u64 t, %1; cvt.u32.u64 %0, t; }" : "=r"(a) : "l"(p));
    return a;
}
__device__ __forceinline__ unsigned long long pk2(float x, float y) {
    unsigned long long r;
    asm("mov.b64 %0, {%1, %2};" : "=l"(r) : "f"(x), "f"(y));
    return r;
}
__device__ __forceinline__ float2 unpk(unsigned long long v) {
    float2 r;
    asm("mov.b64 {%0, %1}, %2;" : "=f"(r.x), "=f"(r.y) : "l"(v));
    return r;
}
__device__ __forceinline__ void fma2(unsigned long long& d, unsigned long long a, unsigned long long b) {
    asm("fma.rn.f32x2 %0, %1, %2, %0;" : "+l"(d) : "l"(a), "l"(b));
}
__device__ __forceinline__ float sigm(float x) { return 1.f / (1.f + __expf(-x)); }
__device__ __forceinline__ float tanh_f(float x) { return 2.f / (1.f + __expf(-2.f * x)) - 1.f; }

__device__ __forceinline__ void cpa16(uint32_t d, const void* s) {
    asm volatile("cp.async.cg.shared.global [%0], [%1], 16;" :: "r"(d), "l"(s) : "memory");
}
#define CP_COMMIT() asm volatile("cp.async.commit_group;" ::: "memory")
#define CP_WAIT0()  asm volatile("cp.async.wait_group 0;" ::: "memory")
#define GBAR_SYNC(id) asm volatile("bar.sync %0, 128;" :: "r"(id) : "memory")

__device__ __forceinline__ void ldsm_x4(uint32_t* r, uint32_t a) {
    asm volatile("ldmatrix.sync.aligned.m8n8.x4.shared.b16 {%0,%1,%2,%3}, [%4];"
                 : "=r"(r[0]), "=r"(r[1]), "=r"(r[2]), "=r"(r[3]) : "r"(a));
}
__device__ __forceinline__ void ldsm_x2(uint32_t* r, uint32_t a) {
    asm volatile("ldmatrix.sync.aligned.m8n8.x2.shared.b16 {%0,%1}, [%2];"
                 : "=r"(r[0]), "=r"(r[1]) : "r"(a));
}
__device__ __forceinline__ void mma16816(float* c, const uint32_t* a, const uint32_t* b) {
    asm volatile("mma.sync.aligned.m16n8k16.row.col.f32.f16.f16.f32 "
                 "{%0,%1,%2,%3}, {%4,%5,%6,%7}, {%8,%9}, {%0,%1,%2,%3};"
                 : "+f"(c[0]), "+f"(c[1]), "+f"(c[2]), "+f"(c[3])
                 : "r"(a[0]), "r"(a[1]), "r"(a[2]), "r"(a[3]), "r"(b[0]), "r"(b[1]));
}

// ---------------- per-mt group barrier (32 CTAs; no L1 flush) ----------------
__device__ __forceinline__ void gbar_grp(unsigned* cnt, unsigned* ph, unsigned target) {
    __syncthreads();
    if (threadIdx.x == 0) {
        unsigned n;
        asm volatile("atom.add.acq_rel.gpu.u32 %0, [%1], 1;"
                     : "=r"(n) : "l"(cnt) : "memory");
        if (n == 31) {
            *cnt = 0;
            asm volatile("st.release.gpu.u32 [%0], %1;"
                         :: "l"(ph), "r"(target) : "memory");
        } else {
            unsigned p;
            do {
                asm volatile("ld.acquire.gpu.u32 %0, [%1];"
                             : "=r"(p) : "l"(ph) : "memory");
            } while ((int)(p - target) < 0);
        }
    }
    __syncthreads();
}

// ---------------- precompute kernels ----------------
__global__ void ctx_kernel(const float* __restrict__ z, const float* __restrict__ c,
                           const float* __restrict__ Wih, const float* __restrict__ bih) {
    __shared__ float cs[8 * LC];
    int bc = blockIdx.x;
    for (int i = threadIdx.x; i < 8 * LC; i += NTHREADS) {
        int bb = i / LC, ii = i - bb * LC;
        int b = bc * 8 + bb;
        cs[i] = (ii < 256) ? z[b * 256 + ii] : c[b * 64 + (ii - 256)];
    }
    __syncthreads();
    for (int gk = 0; gk < 12; gk++) {
        int g = threadIdx.x + gk * NTHREADS;
        float acc[8];
        float bi = bih[g];
#pragma unroll
        for (int bb = 0; bb < 8; bb++) acc[bb] = bi;
        const float* wr = Wih + (size_t)g * EIN + Ee;
        for (int ii = 0; ii < LC; ii++) {
            float w = wr[ii];
#pragma unroll
            for (int bb = 0; bb < 8; bb++) acc[bb] += w * cs[bb * LC + ii];
        }
#pragma unroll
        for (int bb = 0; bb < 8; bb++) g_ctxpart[(size_t)(bc * 8 + bb) * G3 + g] = acc[bb];
    }
}

__global__ void h0_kernel(const float* __restrict__ z, const float* __restrict__ c,
                          const float* __restrict__ Wfch, const float* __restrict__ bfch) {
    __shared__ float cs[8 * LC];
    int bc = blockIdx.x;
    for (int i = threadIdx.x; i < 8 * LC; i += NTHREADS) {
        int bb = i / LC, ii = i - bb * LC;
        int b = bc * 8 + bb;
        cs[i] = (ii < 256) ? z[b * 256 + ii] : c[b * 64 + (ii - 256)];
    }
    __syncthreads();
    for (int jk = 0; jk < 4; jk++) {
        int j = threadIdx.x + jk * NTHREADS;
        float acc[8];
        float bj = bfch[j];
#pragma unroll
        for (int bb = 0; bb < 8; bb++) acc[bb] = bj;
        const float* wr = Wfch + (size_t)j * LC;
        for (int ii = 0; ii < LC; ii++) {
            float w = wr[ii];
#pragma unroll
            for (int bb = 0; bb < 8; bb++) acc[bb] += w * cs[bb * LC + ii];
        }
#pragma unroll
        for (int bb = 0; bb < 8; bb++) {
            int b = bc * 8 + bb;
            float v = acc[bb];
            g_hall[(size_t)b * Hd + j] = v;              // slot 0 = h0
            g_ah[(size_t)b * Hd + j] = __float2half_rn(v);   // buf 0
        }
    }
}

__global__ void table_kernel(const float* __restrict__ emb, const float* __restrict__ Wih) {
    __shared__ float es[Vv * 64];
    int g = blockIdx.x * NTHREADS + threadIdx.x;
    float acc[Vv];
#pragma unroll
    for (int v = 0; v < Vv; v++) acc[v] = 0.f;
    for (int ec = 0; ec < Ee / 64; ec++) {
        __syncthreads();
        for (int i = threadIdx.x; i < Vv * 64; i += NTHREADS) {
            int v = i >> 6, el = i & 63;
            es[i] = emb[(size_t)v * Ee + ec * 64 + el];
        }
        __syncthreads();
        const float* wr = Wih + (size_t)g * EIN + ec * 64;
#pragma unroll 8
        for (int e = 0; e < 64; e++) {
            float w = wr[e];
#pragma unroll
            for (int v = 0; v < Vv; v++) acc[v] += w * es[v * 64 + e];
        }
    }
    for (int v = 0; v < Vv; v++) g_table[(size_t)v * G3 + g] = acc[v];
}

// W_hh -> fp16, layout [nt][p=gate*32+jl][k]
__global__ void wconv_kernel(const float* __restrict__ Whh) {
    const size_t total = (size_t)32 * 96 * Hd;
    size_t stride = (size_t)gridDim.x * NTHREADS;
    for (size_t i = blockIdx.x * (size_t)NTHREADS + threadIdx.x; i < total; i += stride) {
        int k = (int)(i & 1023);
        int rf = (int)(i >> 10);        // nt*96 + p
        int nt = rf / 96, p = rf - nt * 96;
        int gate = p >> 5;
        int j = nt * 32 + (p & 31);
        g_wf[i] = __float2half_rn(Whh[((size_t)gate * Hd + j) * Hd + k]);
    }
}

// ---------------- persistent recurrent kernel (gh only) ----------------
// Per-group A stage: group mw loads rows [b0+mw*32, +32), K chunk [s*128, +128).
__device__ __forceinline__ void stage_issue_grp(uint32_t stg, int buf, int browg, int s, int gtid) {
    const char* agh = (const char*)(g_ah + ((size_t)(buf * Bb + browg)) * Hd + s * 128);
#pragma unroll
    for (int i = gtid; i < 512; i += 128) {
        int r = i >> 4, q = i & 15;
        cpa16(stg + r * SROW + q * 16, agh + (size_t)r * 2048 + q * 16);
    }
    CP_COMMIT();
}

__device__ void gh_tile(int t, int mt, int nt, char* smem, uint32_t smem_b,
                        const int* __restrict__ seq, const float* __restrict__ bhh) {
    const int tid = threadIdx.x;
    const int lane = tid & 31, wid = tid >> 5;
    const int mw = wid >> 2, nw = wid & 3;     // contiguous warp-groups: warps 0-3=mw0, 4-7=mw1
    const int gtid = tid & 127;                // thread id within warp-group
    const int b0 = mt * 64, j0 = nt * 32;
    const int browg = b0 + mw * 32;            // this group's A rows
    const uint32_t grpA = smem_b + W_BYTES + (uint32_t)mw * 2 * GSTG;

    float acc[2][3][4];
#pragma unroll
    for (int mi = 0; mi < 2; mi++)
#pragma unroll
        for (int ni = 0; ni < 3; ni++)
#pragma unroll
            for (int q = 0; q < 4; q++) acc[mi][ni][q] = 0.f;

    const int arow = lane & 15;
    const int akoff = (lane >> 4) * 16;
    const int brow = lane & 7;
    const int bhalf = (lane >> 3) & 1;
    // resident-W row base addresses (swizzled layout: row p at p*2048)
    uint32_t wrow[3];
#pragma unroll
    for (int ni = 0; ni < 3; ni++)
        wrow[ni] = smem_b + ((uint32_t)(nw * 24 + ni * 8 + brow) << 11);

    stage_issue_grp(grpA, t & 1, browg, 0, gtid);

    for (int s = 0; s < 8; s++) {
        CP_WAIT0();
        GBAR_SYNC(1 + mw);
        if (s < 7) stage_issue_grp(grpA + ((s + 1) & 1) * GSTG, t & 1, browg, s + 1, gtid);
        uint32_t aB = grpA + (s & 1) * GSTG + arow * SROW + akoff;
#pragma unroll
        for (int ks = 0; ks < 8; ks++) {
            uint32_t ah0[4], ah1[4];
            ldsm_x4(ah0, aB + ks * 32);
            ldsm_x4(ah1, aB + 16 * SROW + ks * 32);
            // W chunk index within resident row: 16B chunks, c = (s*8+ks)*2 + bhalf
            const uint32_t wsw = (uint32_t)((((s * 8 + ks) << 1) | bhalf) ^ brow) << 4;
            uint32_t bh[3][2];
#pragma unroll
            for (int ni = 0; ni < 3; ni++)
                ldsm_x2(bh[ni], wrow[ni] + wsw);
#pragma unroll
            for (int ni = 0; ni < 3; ni++) {
                mma16816(acc[0][ni], ah0, bh[ni]);
                mma16816(acc[1][ni], ah1, bh[ni]);
            }
        }
    }

    // ---- epilogue: acc -> smem (A-stage area) -> fused GRU gating ----
    __syncthreads();
    float* eg = (float*)(smem + W_BYTES);   // [64][100], reuses A stage area
    const int crow = lane >> 2;
    const int ccol = (lane & 3) * 2;
#pragma unroll
    for (int mi = 0; mi < 2; mi++)
#pragma unroll
        for (int ni = 0; ni < 3; ni++) {
            int rr = mw * 32 + mi * 16 + crow;
            int cc = nw * 24 + ni * 8 + ccol;
            eg[rr * 100 + cc]       = acc[mi][ni][0];
            eg[rr * 100 + cc + 1]   = acc[mi][ni][1];
            eg[(rr + 8) * 100 + cc]     = acc[mi][ni][2];
            eg[(rr + 8) * 100 + cc + 1] = acc[mi][ni][3];
        }
    __syncthreads();

    const int lr = tid >> 2;
    const int b = b0 + lr;
    const int jq = (tid & 3) * 8;
    const int jg = j0 + jq;
    const int tok = __ldg(&seq[b * Tt + t]);
    const float* tb = g_table + (size_t)tok * G3;
    const float* cp = g_ctxpart + (size_t)b * G3;
    const float* hold = g_hall + ((size_t)t * Bb + b) * Hd;
    float* hnew = g_hall + ((size_t)(t + 1) * Bb + b) * Hd;
    const int bufn = (t + 1) & 1;
    float hv[8];
#pragma unroll
    for (int q = 0; q < 2; q++) {
        float4 er = *(const float4*)&eg[lr * 100 + jq + q * 4];
        float4 ez = *(const float4*)&eg[lr * 100 + 32 + jq + q * 4];
        float4 en = *(const float4*)&eg[lr * 100 + 64 + jq + q * 4];
        float4 t_r = __ldg((const float4*)&tb[jg + q * 4]);
        float4 t_z = __ldg((const float4*)&tb[Hd + jg + q * 4]);
        float4 t_n = __ldg((const float4*)&tb[2 * Hd + jg + q * 4]);
        float4 c_r = __ldg((const float4*)&cp[jg + q * 4]);
        float4 c_z = __ldg((const float4*)&cp[Hd + jg + q * 4]);
        float4 c_n = __ldg((const float4*)&cp[2 * Hd + jg + q * 4]);
        float4 b_r = __ldg((const float4*)&bhh[jg + q * 4]);
        float4 b_z = __ldg((const float4*)&bhh[Hd + jg + q * 4]);
        float4 b_n = __ldg((const float4*)&bhh[2 * Hd + jg + q * 4]);
        float4 h_o = __ldcg((const float4*)&hold[jg + q * 4]);
#pragma unroll
        for (int e = 0; e < 4; e++) {
            float r = sigm(((const float*)&t_r)[e] + ((const float*)&c_r)[e]
                           + ((const float*)&er)[e] + ((const float*)&b_r)[e]);
            float u = sigm(((const float*)&t_z)[e] + ((const float*)&c_z)[e]
                           + ((const float*)&ez)[e] + ((const float*)&b_z)[e]);
            float n = tanh_f(((const float*)&t_n)[e] + ((const float*)&c_n)[e]
                             + r * (((const float*)&en)[e] + ((const float*)&b_n)[e]));
            hv[q * 4 + e] = (1.f - u) * n + u * ((const float*)&h_o)[e];
        }
    }
    *(float4*)&hnew[jg]     = *(float4*)&hv[0];
    *(float4*)&hnew[jg + 4] = *(float4*)&hv[4];
    uint32_t uh[4];
#pragma unroll
    for (int q = 0; q < 4; q++) {
        __half2 ph = __halves2half2(__float2half_rn(hv[q * 2]), __float2half_rn(hv[q * 2 + 1]));
        uh[q] = *(uint32_t*)&ph;
    }
    *(uint4*)&g_ah[((size_t)(bufn * Bb + b)) * Hd + jg] = make_uint4(uh[0], uh[1], uh[2], uh[3]);
}

__global__ void __launch_bounds__(NTHREADS, 1)
gru_kernel(const int* __restrict__ seq, const float* __restrict__ bhh) {
    extern __shared__ char smem[];
    __shared__ unsigned base_s;
    const int tid = threadIdx.x;
    const int bid = blockIdx.x;
    const uint32_t smem_b = smem_u32_of(smem);
    const int mt = bid & 3, nt = bid >> 2;
    unsigned* cnt = &g_cnt[mt * 32];
    unsigned* ph = &g_ph[mt * 32];

    // ---- load resident W (once), XOR-swizzled: chunk c of row p at ((c^(p&7))<<4) ----
    {
        const char* wsrc = (const char*)(g_wf + (size_t)nt * 96 * Hd);
        for (int i = tid; i < 12288; i += NTHREADS) {
            int p = i >> 7, c = i & 127;
            cpa16(smem_b + (p << 11) + (((c ^ (p & 7))) << 4), wsrc + (size_t)p * 2048 + c * 16);
        }
        CP_COMMIT();
    }
    if (tid == 0) {
        unsigned p;
        asm volatile("ld.acquire.gpu.u32 %0, [%1];" : "=r"(p) : "l"(ph) : "memory");
        base_s = p;
    }
    CP_WAIT0();
    __syncthreads();
    const unsigned base = base_s;

    for (int it = 0; it < Tt; ++it) {
        gh_tile(it, mt, nt, smem, smem_b, seq, bhh);
        gbar_grp(cnt, ph, base + (unsigned)it + 1u);
    }
}

// ---------------- bulk logits GEMM over the full h history ----------------
#define HSS 68
__global__ void __launch_bounds__(NTHREADS)
logits_kernel(const float* __restrict__ Wout, const float* __restrict__ bout,
              float* __restrict__ out) {
    __shared__ float hs[128 * HSS];
    __shared__ float wo[64 * HSS];
    const int cta = blockIdx.x;
    const int t = cta >> 1;
    const int b0 = (cta & 1) * 128;
    const float* hbase = g_hall + ((size_t)(t + 1) * Bb + b0) * Hd;
    const int tid = threadIdx.x;
    const int bl = tid >> 3;
    const int vq = tid & 7;

    unsigned long long acc[4][4];
#pragma unroll
    for (int r = 0; r < 4; r++)
#pragma unroll
        for (int i = 0; i < 4; i++) acc[r][i] = 0ull;

    for (int kc = 0; kc < Hd; kc += 64) {
        __syncthreads();
#pragma unroll
        for (int i = 0; i < 8; i++) {
            int idx = tid + 256 * i;
            int row = idx >> 4, kq = idx & 15;
            *(float4*)&hs[row * HSS + kq * 4] =
                __ldcg((const float4*)&hbase[(size_t)row * Hd + kc + kq * 4]);
        }
#pragma unroll
        for (int i = 0; i < 4; i++) {
            int idx = tid + 256 * i;
            int v = idx >> 4, kq = idx & 15;
            float4 w = __ldg((const float4*)&Wout[(size_t)v * Hd + kc + kq * 4]);
            wo[(kq * 4 + 0) * HSS + v] = w.x;
            wo[(kq * 4 + 1) * HSS + v] = w.y;
            wo[(kq * 4 + 2) * HSS + v] = w.z;
            wo[(kq * 4 + 3) * HSS + v] = w.w;
        }
        __syncthreads();
#pragma unroll 4
        for (int k = 0; k < 64; k++) {
            const float* wr = &wo[k * HSS + vq * 8];
            unsigned long long w0 = *(const unsigned long long*)&wr[0];
            unsigned long long w1 = *(const unsigned long long*)&wr[2];
            unsigned long long w2 = *(const unsigned long long*)&wr[4];
            unsigned long long w3 = *(const unsigned long long*)&wr[6];
#pragma unroll
            for (int r = 0; r < 4; r++) {
                float hvv = hs[(bl + r * 32) * HSS + k];
                unsigned long long hdp = pk2(hvv, hvv);
                fma2(acc[r][0], hdp, w0);
                fma2(acc[r][1], hdp, w1);
                fma2(acc[r][2], hdp, w2);
                fma2(acc[r][3], hdp, w3);
            }
        }
    }
#pragma unroll
    for (int r = 0; r < 4; r++) {
        int b = b0 + bl + r * 32;
        float* op = out + ((size_t)b * Tt + t) * Vv + vq * 8;
#pragma unroll
        for (int i = 0; i < 4; i++) {
            float2 v = unpk(acc[r][i]);
            float2 bo = *(const float2*)&bout[vq * 8 + i * 2];
            op[i * 2 + 0] = v.x + bo.x;
            op[i * 2 + 1] = v.y + bo.y;
        }
    }
}

// ---------------- launch ----------------
extern "C" void kernel_launch(void* const* d_in, const int* in_sizes, int n_in,
                              void* d_out, int out_size) {
    (void)in_sizes; (void)n_in; (void)out_size;
    const float* z    = (const float*)d_in[0];
    const float* c    = (const float*)d_in[1];
    const int*   seq  = (const int*)  d_in[2];
    const float* emb  = (const float*)d_in[3];
    const float* Wfch = (const float*)d_in[4];
    const float* bfch = (const float*)d_in[5];
    const float* Wih  = (const float*)d_in[6];
    const float* bih  = (const float*)d_in[7];
    const float* Whh  = (const float*)d_in[8];
    const float* bhh  = (const float*)d_in[9];
    const float* Wout = (const float*)d_in[10];
    const float* bout = (const float*)d_in[11];
    float* out = (float*)d_out;

    static int smem_set = 0;
    if (!smem_set) {
        cudaFuncSetAttribute(gru_kernel, cudaFuncAttributeMaxDynamicSharedMemorySize, SMEM_TOTAL);
        smem_set = 1;
    }

    ctx_kernel<<<32, NTHREADS>>>(z, c, Wih, bih);
    h0_kernel<<<32, NTHREADS>>>(z, c, Wfch, bfch);
    table_kernel<<<12, NTHREADS>>>(emb, Wih);
    wconv_kernel<<<128, NTHREADS>>>(Whh);
    gru_kernel<<<GRID, NTHREADS, SMEM_TOTAL>>>(seq, bhh);
    logits_kernel<<<Tt * 2, NTHREADS>>>(Wout, bout, out);
}

// round 15
// speedup vs baseline: 2.5479x; 1.0811x over previous
#include <cuda_runtime.h>
#include <cuda_fp16.h>
#include <cstdint>

#define Bb 256
#define Tt 256
#define Hd 1024
#define Ee 256
#define LC 320
#define EIN 576   // E + L + C
#define G3 3072
#define Vv 64

#define NGH 128
#define GRID NGH
#define NTHREADS 256

// smem: W resident [96][2048B] XOR-swizzled, then per-group double-buffered A stages.
// Per-group epilogue staging (32 rows x 100 floats = 12.8KB) aliases that group's OWN
// A-stage region only (safe: group's MMA reads complete before its epilogue writes).
#define W_BYTES 196608
#define SROW 272
#define GSTG 8704
#define SMEM_TOTAL (W_BYTES + 4 * GSTG)   // 231424

// ---------------- persistent device scratch ----------------
__device__ float g_ctxpart[Bb * G3];   // context @ W_ih[:,E:]^T + b_ih
__device__ float g_table[Vv * G3];     // emb @ W_ih[:,:E]^T
__device__ float g_hall[(size_t)(Tt + 1) * Bb * Hd];   // h history (slot 0 = h0)
__device__ __align__(16) __half g_ah[2 * Bb * Hd];     // fp16 h tiles [buf][b][k]
__device__ __align__(16) __half g_wf[32 * 96 * Hd];    // fp16 W [nt][p=gate*32+jl][k]
__device__ unsigned g_cnt[4 * 32];
__device__ unsigned g_ph[4 * 32];

// ---------------- helpers ----------------
__device__ __forceinline__ uint32_t smem_u32_of(const void* p) {
    uint32_t a;
    asm("{ .reg .u64 t; cvta.to.shared.u64 t, %1; cvt.u32.u64 %0, t; }" : "=r"(a) : "l"(p));
    return a;
}
__device__ __forceinline__ unsigned long long pk2(float x, float y) {
    unsigned long long r;
    asm("mov.b64 %0, {%1, %2};" : "=l"(r) : "f"(x), "f"(y));
    return r;
}
__device__ __forceinline__ float2 unpk(unsigned long long v) {
    float2 r;
    asm("mov.b64 {%0, %1}, %2;" : "=f"(r.x), "=f"(r.y) : "l"(v));
    return r;
}
__device__ __forceinline__ void fma2(unsigned long long& d, unsigned long long a, unsigned long long b) {
    asm("fma.rn.f32x2 %0, %1, %2, %0;" : "+l"(d) : "l"(a), "l"(b));
}
__device__ __forceinline__ float sigm(float x) { return 1.f / (1.f + __expf(-x)); }
__device__ __forceinline__ float tanh_f(float x) { return 2.f / (1.f + __expf(-2.f * x)) - 1.f; }

__device__ __forceinline__ void cpa16(uint32_t d, const void* s) {
    asm volatile("cp.async.cg.shared.global [%0], [%1], 16;" :: "r"(d), "l"(s) : "memory");
}
#define CP_COMMIT() asm volatile("cp.async.commit_group;" ::: "memory")
#define CP_WAIT0()  asm volatile("cp.async.wait_group 0;" ::: "memory")
#define GBAR_SYNC(id) asm volatile("bar.sync %0, 128;" :: "r"(id) : "memory")

__device__ __forceinline__ void ldsm_x4(uint32_t* r, uint32_t a) {
    asm volatile("ldmatrix.sync.aligned.m8n8.x4.shared.b16 {%0,%1,%2,%3}, [%4];"
                 : "=r"(r[0]), "=r"(r[1]), "=r"(r[2]), "=r"(r[3]) : "r"(a));
}
__device__ __forceinline__ void ldsm_x2(uint32_t* r, uint32_t a) {
    asm volatile("ldmatrix.sync.aligned.m8n8.x2.shared.b16 {%0,%1}, [%2];"
                 : "=r"(r[0]), "=r"(r[1]) : "r"(a));
}
__device__ __forceinline__ void mma16816(float* c, const uint32_t* a, const uint32_t* b) {
    asm volatile("mma.sync.aligned.m16n8k16.row.col.f32.f16.f16.f32 "
                 "{%0,%1,%2,%3}, {%4,%5,%6,%7}, {%8,%9}, {%0,%1,%2,%3};"
                 : "+f"(c[0]), "+f"(c[1]), "+f"(c[2]), "+f"(c[3])
                 : "r"(a[0]), "r"(a[1]), "r"(a[2]), "r"(a[3]), "r"(b[0]), "r"(b[1]));
}

// ---------------- per-mt group barrier (32 CTAs; no L1 flush) ----------------
__device__ __forceinline__ void gbar_grp(unsigned* cnt, unsigned* ph, unsigned target) {
    __syncthreads();
    if (threadIdx.x == 0) {
        unsigned n;
        asm volatile("atom.add.acq_rel.gpu.u32 %0, [%1], 1;"
                     : "=r"(n) : "l"(cnt) : "memory");
        if (n == 31) {
            *cnt = 0;
            asm volatile("st.release.gpu.u32 [%0], %1;"
                         :: "l"(ph), "r"(target) : "memory");
        } else {
            unsigned p;
            do {
                asm volatile("ld.acquire.gpu.u32 %0, [%1];"
                             : "=r"(p) : "l"(ph) : "memory");
            } while ((int)(p - target) < 0);
        }
    }
    __syncthreads();
}

// ---------------- merged precompute kernel ----------------
// 204 blocks: [0,32) ctx, [32,64) h0, [64,76) table, [76,204) wconv
__global__ void pre_kernel(const float* __restrict__ z, const float* __restrict__ c,
                           const float* __restrict__ emb,
                           const float* __restrict__ Wfch, const float* __restrict__ bfch,
                           const float* __restrict__ Wih, const float* __restrict__ bih,
                           const float* __restrict__ Whh) {
    __shared__ float sh[4096];
    const int bidx = blockIdx.x;
    const int tid = threadIdx.x;

    if (bidx < 32) {
        // ---- ctx: ctxpart[b][g] ----
        int bc = bidx;
        for (int i = tid; i < 8 * LC; i += NTHREADS) {
            int bb = i / LC, ii = i - bb * LC;
            int b = bc * 8 + bb;
            sh[i] = (ii < 256) ? z[b * 256 + ii] : c[b * 64 + (ii - 256)];
        }
        __syncthreads();
        for (int gk = 0; gk < 12; gk++) {
            int g = tid + gk * NTHREADS;
            float acc[8];
            float bi = bih[g];
#pragma unroll
            for (int bb = 0; bb < 8; bb++) acc[bb] = bi;
            const float* wr = Wih + (size_t)g * EIN + Ee;
            for (int ii = 0; ii < LC; ii++) {
                float w = wr[ii];
#pragma unroll
                for (int bb = 0; bb < 8; bb++) acc[bb] += w * sh[bb * LC + ii];
            }
#pragma unroll
            for (int bb = 0; bb < 8; bb++) g_ctxpart[(size_t)(bc * 8 + bb) * G3 + g] = acc[bb];
        }
    } else if (bidx < 64) {
        // ---- h0 ----
        int bc = bidx - 32;
        for (int i = tid; i < 8 * LC; i += NTHREADS) {
            int bb = i / LC, ii = i - bb * LC;
            int b = bc * 8 + bb;
            sh[i] = (ii < 256) ? z[b * 256 + ii] : c[b * 64 + (ii - 256)];
        }
        __syncthreads();
        for (int jk = 0; jk < 4; jk++) {
            int j = tid + jk * NTHREADS;
            float acc[8];
            float bj = bfch[j];
#pragma unroll
            for (int bb = 0; bb < 8; bb++) acc[bb] = bj;
            const float* wr = Wfch + (size_t)j * LC;
            for (int ii = 0; ii < LC; ii++) {
                float w = wr[ii];
#pragma unroll
                for (int bb = 0; bb < 8; bb++) acc[bb] += w * sh[bb * LC + ii];
            }
#pragma unroll
            for (int bb = 0; bb < 8; bb++) {
                int b = bc * 8 + bb;
                float v = acc[bb];
                g_hall[(size_t)b * Hd + j] = v;
                g_ah[(size_t)b * Hd + j] = __float2half_rn(v);
            }
        }
    } else if (bidx < 76) {
        // ---- table ----
        int g = (bidx - 64) * NTHREADS + tid;
        float acc[Vv];
#pragma unroll
        for (int v = 0; v < Vv; v++) acc[v] = 0.f;
        for (int ec = 0; ec < Ee / 64; ec++) {
            __syncthreads();
            for (int i = tid; i < Vv * 64; i += NTHREADS) {
                int v = i >> 6, el = i & 63;
                sh[i] = emb[(size_t)v * Ee + ec * 64 + el];
            }
            __syncthreads();
            const float* wr = Wih + (size_t)g * EIN + ec * 64;
#pragma unroll 8
            for (int e = 0; e < 64; e++) {
                float w = wr[e];
#pragma unroll
                for (int v = 0; v < Vv; v++) acc[v] += w * sh[v * 64 + e];
            }
        }
        for (int v = 0; v < Vv; v++) g_table[(size_t)v * G3 + g] = acc[v];
    } else {
        // ---- wconv: 128 blocks ----
        const size_t total = (size_t)32 * 96 * Hd;
        size_t stride = (size_t)128 * NTHREADS;
        for (size_t i = (size_t)(bidx - 76) * NTHREADS + tid; i < total; i += stride) {
            int k = (int)(i & 1023);
            int rf = (int)(i >> 10);
            int nt = rf / 96, p = rf - nt * 96;
            int gate = p >> 5;
            int j = nt * 32 + (p & 31);
            g_wf[i] = __float2half_rn(Whh[((size_t)gate * Hd + j) * Hd + k]);
        }
    }
}

// ---------------- persistent recurrent kernel (gh only) ----------------
__device__ __forceinline__ void stage_issue_grp(uint32_t stg, int buf, int browg, int s, int gtid) {
    const char* agh = (const char*)(g_ah + ((size_t)(buf * Bb + browg)) * Hd + s * 128);
#pragma unroll
    for (int i = gtid; i < 512; i += 128) {
        int r = i >> 4, q = i & 15;
        cpa16(stg + r * SROW + q * 16, agh + (size_t)r * 2048 + q * 16);
    }
    CP_COMMIT();
}

__device__ void gh_tile(int t, int mt, int nt, char* smem, uint32_t smem_b,
                        const int* __restrict__ seq, const float* __restrict__ bhh) {
    const int tid = threadIdx.x;
    const int lane = tid & 31, wid = tid >> 5;
    const int mw = wid >> 2, nw = wid & 3;     // warp-groups: warps 0-3=mw0, 4-7=mw1
    const int gtid = tid & 127;
    const int b0 = mt * 64, j0 = nt * 32;
    const int browg = b0 + mw * 32;
    const uint32_t grpA = smem_b + W_BYTES + (uint32_t)mw * 2 * GSTG;
    const int barid = 1 + mw;

    float acc[2][3][4];
#pragma unroll
    for (int mi = 0; mi < 2; mi++)
#pragma unroll
        for (int ni = 0; ni < 3; ni++)
#pragma unroll
            for (int q = 0; q < 4; q++) acc[mi][ni][q] = 0.f;

    const int arow = lane & 15;
    const int akoff = (lane >> 4) * 16;
    const int brow = lane & 7;
    const int bhalf = (lane >> 3) & 1;
    // x4 W fragment: lanes 0-15 -> rows nw*24+0..7 (k lo/hi), lanes 16-31 -> rows +8..15
    const int wrow4 = nw * 24 + ((lane >> 4) << 3) + brow;
    const uint32_t wrow4_b = smem_b + ((uint32_t)wrow4 << 11);
    const uint32_t wrow2_b = smem_b + ((uint32_t)(nw * 24 + 16 + brow) << 11);

    stage_issue_grp(grpA, t & 1, browg, 0, gtid);

    for (int s = 0; s < 8; s++) {
        CP_WAIT0();
        GBAR_SYNC(barid);
        if (s < 7) stage_issue_grp(grpA + ((s + 1) & 1) * GSTG, t & 1, browg, s + 1, gtid);
        uint32_t aB = grpA + (s & 1) * GSTG + arow * SROW + akoff;
#pragma unroll
        for (int ks = 0; ks < 8; ks++) {
            uint32_t ah0[4], ah1[4];
            ldsm_x4(ah0, aB + ks * 32);
            ldsm_x4(ah1, aB + 16 * SROW + ks * 32);
            const uint32_t chunk = (uint32_t)(((s * 8 + ks) << 1) | bhalf);
            uint32_t bh01[4], bh2[2];
            ldsm_x4(bh01, wrow4_b + (uint32_t)((chunk ^ (uint32_t)(wrow4 & 7)) << 4));
            ldsm_x2(bh2, wrow2_b + (uint32_t)((chunk ^ (uint32_t)brow) << 4));
            mma16816(acc[0][0], ah0, bh01);
            mma16816(acc[1][0], ah1, bh01);
            mma16816(acc[0][1], ah0, bh01 + 2);
            mma16816(acc[1][1], ah1, bh01 + 2);
            mma16816(acc[0][2], ah0, bh2);
            mma16816(acc[1][2], ah1, bh2);
        }
    }

    // ---- per-group epilogue: acc -> group eg -> fused GRU gating ----
    GBAR_SYNC(barid);
    float* eg = (float*)(smem + W_BYTES + mw * 2 * GSTG);   // 32 rows x 100 floats (12.8KB < 17.4KB)
    const int crow = lane >> 2;
    const int ccol = (lane & 3) * 2;
#pragma unroll
    for (int mi = 0; mi < 2; mi++)
#pragma unroll
        for (int ni = 0; ni < 3; ni++) {
            int rr = mi * 16 + crow;               // group-local row 0..31
            int cc = nw * 24 + ni * 8 + ccol;
            eg[rr * 100 + cc]       = acc[mi][ni][0];
            eg[rr * 100 + cc + 1]   = acc[mi][ni][1];
            eg[(rr + 8) * 100 + cc]     = acc[mi][ni][2];
            eg[(rr + 8) * 100 + cc + 1] = acc[mi][ni][3];
        }
    GBAR_SYNC(barid);

    const int lrow = gtid >> 2;            // group-local row 0..31
    const int b = browg + lrow;
    const int jq = (tid & 3) * 8;
    const int jg = j0 + jq;
    const int tok = __ldg(&seq[b * Tt + t]);
    const float* tb = g_table + (size_t)tok * G3;
    const float* cp = g_ctxpart + (size_t)b * G3;
    const float* hold = g_hall + ((size_t)t * Bb + b) * Hd;
    float* hnew = g_hall + ((size_t)(t + 1) * Bb + b) * Hd;
    const int bufn = (t + 1) & 1;
    float hv[8];
#pragma unroll
    for (int q = 0; q < 2; q++) {
        float4 er = *(const float4*)&eg[lrow * 100 + jq + q * 4];
        float4 ez = *(const float4*)&eg[lrow * 100 + 32 + jq + q * 4];
        float4 en = *(const float4*)&eg[lrow * 100 + 64 + jq + q * 4];
        float4 t_r = __ldg((const float4*)&tb[jg + q * 4]);
        float4 t_z = __ldg((const float4*)&tb[Hd + jg + q * 4]);
        float4 t_n = __ldg((const float4*)&tb[2 * Hd + jg + q * 4]);
        float4 c_r = __ldg((const float4*)&cp[jg + q * 4]);
        float4 c_z = __ldg((const float4*)&cp[Hd + jg + q * 4]);
        float4 c_n = __ldg((const float4*)&cp[2 * Hd + jg + q * 4]);
        float4 b_r = __ldg((const float4*)&bhh[jg + q * 4]);
        float4 b_z = __ldg((const float4*)&bhh[Hd + jg + q * 4]);
        float4 b_n = __ldg((const float4*)&bhh[2 * Hd + jg + q * 4]);
        float4 h_o = __ldcg((const float4*)&hold[jg + q * 4]);
#pragma unroll
        for (int e = 0; e < 4; e++) {
            float r = sigm(((const float*)&t_r)[e] + ((const float*)&c_r)[e]
                           + ((const float*)&er)[e] + ((const float*)&b_r)[e]);
            float u = sigm(((const float*)&t_z)[e] + ((const float*)&c_z)[e]
                           + ((const float*)&ez)[e] + ((const float*)&b_z)[e]);
            float n = tanh_f(((const float*)&t_n)[e] + ((const float*)&c_n)[e]
                             + r * (((const float*)&en)[e] + ((const float*)&b_n)[e]));
            hv[q * 4 + e] = (1.f - u) * n + u * ((const float*)&h_o)[e];
        }
    }
    *(float4*)&hnew[jg]     = *(float4*)&hv[0];
    *(float4*)&hnew[jg + 4] = *(float4*)&hv[4];
    uint32_t uh[4];
#pragma unroll
    for (int q = 0; q < 4; q++) {
        __half2 ph = __halves2half2(__float2half_rn(hv[q * 2]), __float2half_rn(hv[q * 2 + 1]));
        uh[q] = *(uint32_t*)&ph;
    }
    *(uint4*)&g_ah[((size_t)(bufn * Bb + b)) * Hd + jg] = make_uint4(uh[0], uh[1], uh[2], uh[3]);
}

__global__ void __launch_bounds__(NTHREADS, 1)
gru_kernel(const int* __restrict__ seq, const float* __restrict__ bhh) {
    extern __shared__ char smem[];
    __shared__ unsigned base_s;
    const int tid = threadIdx.x;
    const int bid = blockIdx.x;
    const uint32_t smem_b = smem_u32_of(smem);
    const int mt = bid & 3, nt = bid >> 2;
    unsigned* cnt = &g_cnt[mt * 32];
    unsigned* ph = &g_ph[mt * 32];

    // ---- load resident W (once), XOR-swizzled: chunk c of row p at ((c^(p&7))<<4) ----
    {
        const char* wsrc = (const char*)(g_wf + (size_t)nt * 96 * Hd);
        for (int i = tid; i < 12288; i += NTHREADS) {
            int p = i >> 7, c = i & 127;
            cpa16(smem_b + (p << 11) + (((c ^ (p & 7))) << 4), wsrc + (size_t)p * 2048 + c * 16);
        }
        CP_COMMIT();
    }
    if (tid == 0) {
        unsigned p;
        asm volatile("ld.acquire.gpu.u32 %0, [%1];" : "=r"(p) : "l"(ph) : "memory");
        base_s = p;
    }
    CP_WAIT0();
    __syncthreads();
    const unsigned base = base_s;

    for (int it = 0; it < Tt; ++it) {
        gh_tile(it, mt, nt, smem, smem_b, seq, bhh);
        gbar_grp(cnt, ph, base + (unsigned)it + 1u);
    }
}

// ---------------- bulk logits GEMM over the full h history ----------------
#define HSS 68
__global__ void __launch_bounds__(NTHREADS)
logits_kernel(const float* __restrict__ Wout, const float* __restrict__ bout,
              float* __restrict__ out) {
    __shared__ float hs[128 * HSS];
    __shared__ float wo[64 * HSS];
    const int cta = blockIdx.x;
    const int t = cta >> 1;
    const int b0 = (cta & 1) * 128;
    const float* hbase = g_hall + ((size_t)(t + 1) * Bb + b0) * Hd;
    const int tid = threadIdx.x;
    const int bl = tid >> 3;
    const int vq = tid & 7;

    unsigned long long acc[4][4];
#pragma unroll
    for (int r = 0; r < 4; r++)
#pragma unroll
        for (int i = 0; i < 4; i++) acc[r][i] = 0ull;

    for (int kc = 0; kc < Hd; kc += 64) {
        __syncthreads();
#pragma unroll
        for (int i = 0; i < 8; i++) {
            int idx = tid + 256 * i;
            int row = idx >> 4, kq = idx & 15;
            *(float4*)&hs[row * HSS + kq * 4] =
                __ldcg((const float4*)&hbase[(size_t)row * Hd + kc + kq * 4]);
        }
#pragma unroll
        for (int i = 0; i < 4; i++) {
            int idx = tid + 256 * i;
            int v = idx >> 4, kq = idx & 15;
            float4 w = __ldg((const float4*)&Wout[(size_t)v * Hd + kc + kq * 4]);
            wo[(kq * 4 + 0) * HSS + v] = w.x;
            wo[(kq * 4 + 1) * HSS + v] = w.y;
            wo[(kq * 4 + 2) * HSS + v] = w.z;
            wo[(kq * 4 + 3) * HSS + v] = w.w;
        }
        __syncthreads();
#pragma unroll 4
        for (int k = 0; k < 64; k++) {
            const float* wr = &wo[k * HSS + vq * 8];
            unsigned long long w0 = *(const unsigned long long*)&wr[0];
            unsigned long long w1 = *(const unsigned long long*)&wr[2];
            unsigned long long w2 = *(const unsigned long long*)&wr[4];
            unsigned long long w3 = *(const unsigned long long*)&wr[6];
#pragma unroll
            for (int r = 0; r < 4; r++) {
                float hvv = hs[(bl + r * 32) * HSS + k];
                unsigned long long hdp = pk2(hvv, hvv);
                fma2(acc[r][0], hdp, w0);
                fma2(acc[r][1], hdp, w1);
                fma2(acc[r][2], hdp, w2);
                fma2(acc[r][3], hdp, w3);
            }
        }
    }
#pragma unroll
    for (int r = 0; r < 4; r++) {
        int b = b0 + bl + r * 32;
        float* op = out + ((size_t)b * Tt + t) * Vv + vq * 8;
#pragma unroll
        for (int i = 0; i < 4; i++) {
            float2 v = unpk(acc[r][i]);
            float2 bo = *(const float2*)&bout[vq * 8 + i * 2];
            op[i * 2 + 0] = v.x + bo.x;
            op[i * 2 + 1] = v.y + bo.y;
        }
    }
}

// ---------------- launch ----------------
extern "C" void kernel_launch(void* const* d_in, const int* in_sizes, int n_in,
                              void* d_out, int out_size) {
    (void)in_sizes; (void)n_in; (void)out_size;
    const float* z    = (const float*)d_in[0];
    const float* c    = (const float*)d_in[1];
    const int*   seq  = (const int*)  d_in[2];
    const float* emb  = (const float*)d_in[3];
    const float* Wfch = (const float*)d_in[4];
    const float* bfch = (const float*)d_in[5];
    const float* Wih  = (const float*)d_in[6];
    const float* bih  = (const float*)d_in[7];
    const float* Whh  = (const float*)d_in[8];
    const float* bhh  = (const float*)d_in[9];
    const float* Wout = (const float*)d_in[10];
    const float* bout = (const float*)d_in[11];
    float* out = (float*)d_out;

    static int smem_set = 0;
    if (!smem_set) {
        cudaFuncSetAttribute(gru_kernel, cudaFuncAttributeMaxDynamicSharedMemorySize, SMEM_TOTAL);
        smem_set = 1;
    }

    pre_kernel<<<204, NTHREADS>>>(z, c, emb, Wfch, bfch, Wih, bih, Whh);
    gru_kernel<<<GRID, NTHREADS, SMEM_TOTAL>>>(seq, bhh);
    logits_kernel<<<Tt * 2, NTHREADS>>>(Wout, bout, out);
}

// round 16
// speedup vs baseline: 2.7415x; 1.0760x over previous
#include <cuda_runtime.h>
#include <cuda_fp16.h>
#include <cstdint>

#define Bb 256
#define Tt 256
#define Hd 1024
#define Ee 256
#define LC 320
#define EIN 576   // E + L + C
#define G3 3072
#define Vv 64

#define NGH 128
#define GRID NGH
#define NTHREADS 256

// smem: W resident [96][2048B] XOR-swizzled, then per-group double-buffered A stages.
#define W_BYTES 196608
#define SROW 272
#define GSTG 8704
#define SMEM_TOTAL (W_BYTES + 4 * GSTG)   // 231424

// ---------------- persistent device scratch ----------------
__device__ float g_ctxpart[Bb * G3];   // context @ W_ih[:,E:]^T + b_ih
__device__ float g_table[Vv * G3];     // emb @ W_ih[:,:E]^T
__device__ float g_hall[(size_t)(Tt + 1) * Bb * Hd];   // h history (slot 0 = h0)
__device__ __align__(16) __half g_ah[2 * Bb * Hd];     // fp16 h tiles [buf][b][k]
__device__ __align__(16) __half g_wf[32 * 96 * Hd];    // fp16 W [nt][p=gate*32+jl][k]
__device__ unsigned g_cnt[4 * 32];
__device__ unsigned g_ph[4 * 32];

// ---------------- helpers ----------------
__device__ __forceinline__ uint32_t smem_u32_of(const void* p) {
    uint32_t a;
    asm("{ .reg .u64 t; cvta.to.shared.u64 t, %1; cvt.u32.u64 %0, t; }" : "=r"(a) : "l"(p));
    return a;
}
__device__ __forceinline__ unsigned long long pk2(float x, float y) {
    unsigned long long r;
    asm("mov.b64 %0, {%1, %2};" : "=l"(r) : "f"(x), "f"(y));
    return r;
}
__device__ __forceinline__ float2 unpk(unsigned long long v) {
    float2 r;
    asm("mov.b64 {%0, %1}, %2;" : "=f"(r.x), "=f"(r.y) : "l"(v));
    return r;
}
__device__ __forceinline__ void fma2(unsigned long long& d, unsigned long long a, unsigned long long b) {
    asm("fma.rn.f32x2 %0, %1, %2, %0;" : "+l"(d) : "l"(a), "l"(b));
}
__device__ __forceinline__ float sigm(float x) { return 1.f / (1.f + __expf(-x)); }
__device__ __forceinline__ float tanh_f(float x) { return 2.f / (1.f + __expf(-2.f * x)) - 1.f; }

__device__ __forceinline__ void cpa16(uint32_t d, const void* s) {
    asm volatile("cp.async.cg.shared.global [%0], [%1], 16;" :: "r"(d), "l"(s) : "memory");
}
#define CP_COMMIT() asm volatile("cp.async.commit_group;" ::: "memory")
#define CP_WAIT0()  asm volatile("cp.async.wait_group 0;" ::: "memory")
#define GBAR_SYNC(id) asm volatile("bar.sync %0, 128;" :: "r"(id) : "memory")

__device__ __forceinline__ void ldsm_x4(uint32_t* r, uint32_t a) {
    asm volatile("ldmatrix.sync.aligned.m8n8.x4.shared.b16 {%0,%1,%2,%3}, [%4];"
                 : "=r"(r[0]), "=r"(r[1]), "=r"(r[2]), "=r"(r[3]) : "r"(a));
}
__device__ __forceinline__ void ldsm_x2(uint32_t* r, uint32_t a) {
    asm volatile("ldmatrix.sync.aligned.m8n8.x2.shared.b16 {%0,%1}, [%2];"
                 : "=r"(r[0]), "=r"(r[1]) : "r"(a));
}
__device__ __forceinline__ void mma16816(float* c, const uint32_t* a, const uint32_t* b) {
    asm volatile("mma.sync.aligned.m16n8k16.row.col.f32.f16.f16.f32 "
                 "{%0,%1,%2,%3}, {%4,%5,%6,%7}, {%8,%9}, {%0,%1,%2,%3};"
                 : "+f"(c[0]), "+f"(c[1]), "+f"(c[2]), "+f"(c[3])
                 : "r"(a[0]), "r"(a[1]), "r"(a[2]), "r"(a[3]), "r"(b[0]), "r"(b[1]));
}

// ---------------- per-mt group barrier (32 CTAs; no L1 flush) ----------------
__device__ __forceinline__ void gbar_grp(unsigned* cnt, unsigned* ph, unsigned target) {
    __syncthreads();
    if (threadIdx.x == 0) {
        unsigned n;
        asm volatile("atom.add.acq_rel.gpu.u32 %0, [%1], 1;"
                     : "=r"(n) : "l"(cnt) : "memory");
        if (n == 31) {
            *cnt = 0;
            asm volatile("st.release.gpu.u32 [%0], %1;"
                         :: "l"(ph), "r"(target) : "memory");
        } else {
            unsigned p;
            do {
                asm volatile("ld.acquire.gpu.u32 %0, [%1];"
                             : "=r"(p) : "l"(ph) : "memory");
            } while ((int)(p - target) < 0);
        }
    }
    __syncthreads();
}

// ---------------- precompute kernels (parallelized) ----------------
// ctx: grid 384 = 32 bc x 12 gk. Each thread: one g, 8 b's, K=320.
__global__ void ctx_kernel(const float* __restrict__ z, const float* __restrict__ c,
                           const float* __restrict__ Wih, const float* __restrict__ bih) {
    __shared__ float cs[8 * LC];
    const int bc = blockIdx.x & 31;
    const int gk = blockIdx.x >> 5;
    for (int i = threadIdx.x; i < 8 * LC; i += NTHREADS) {
        int bb = i / LC, ii = i - bb * LC;
        int b = bc * 8 + bb;
        cs[i] = (ii < 256) ? z[b * 256 + ii] : c[b * 64 + (ii - 256)];
    }
    __syncthreads();
    const int g = threadIdx.x + gk * NTHREADS;
    float acc[8];
    float bi = __ldg(&bih[g]);
#pragma unroll
    for (int bb = 0; bb < 8; bb++) acc[bb] = bi;
    const float* wr = Wih + (size_t)g * EIN + Ee;
#pragma unroll 4
    for (int ii = 0; ii < LC; ii++) {
        float w = __ldg(&wr[ii]);
#pragma unroll
        for (int bb = 0; bb < 8; bb++) acc[bb] += w * cs[bb * LC + ii];
    }
#pragma unroll
    for (int bb = 0; bb < 8; bb++) g_ctxpart[(size_t)(bc * 8 + bb) * G3 + g] = acc[bb];
}

// h0: grid 128 = 32 bc x 4 jk.
__global__ void h0_kernel(const float* __restrict__ z, const float* __restrict__ c,
                          const float* __restrict__ Wfch, const float* __restrict__ bfch) {
    __shared__ float cs[8 * LC];
    const int bc = blockIdx.x & 31;
    const int jk = blockIdx.x >> 5;
    for (int i = threadIdx.x; i < 8 * LC; i += NTHREADS) {
        int bb = i / LC, ii = i - bb * LC;
        int b = bc * 8 + bb;
        cs[i] = (ii < 256) ? z[b * 256 + ii] : c[b * 64 + (ii - 256)];
    }
    __syncthreads();
    const int j = threadIdx.x + jk * NTHREADS;
    float acc[8];
    float bj = __ldg(&bfch[j]);
#pragma unroll
    for (int bb = 0; bb < 8; bb++) acc[bb] = bj;
    const float* wr = Wfch + (size_t)j * LC;
#pragma unroll 4
    for (int ii = 0; ii < LC; ii++) {
        float w = __ldg(&wr[ii]);
#pragma unroll
        for (int bb = 0; bb < 8; bb++) acc[bb] += w * cs[bb * LC + ii];
    }
#pragma unroll
    for (int bb = 0; bb < 8; bb++) {
        int b = bc * 8 + bb;
        float v = acc[bb];
        g_hall[(size_t)b * Hd + j] = v;
        g_ah[(size_t)b * Hd + j] = __float2half_rn(v);
    }
}

__global__ void table_kernel(const float* __restrict__ emb, const float* __restrict__ Wih) {
    __shared__ float es[Vv * 64];
    int g = blockIdx.x * NTHREADS + threadIdx.x;
    float acc[Vv];
#pragma unroll
    for (int v = 0; v < Vv; v++) acc[v] = 0.f;
    for (int ec = 0; ec < Ee / 64; ec++) {
        __syncthreads();
        for (int i = threadIdx.x; i < Vv * 64; i += NTHREADS) {
            int v = i >> 6, el = i & 63;
            es[i] = emb[(size_t)v * Ee + ec * 64 + el];
        }
        __syncthreads();
        const float* wr = Wih + (size_t)g * EIN + ec * 64;
#pragma unroll 8
        for (int e = 0; e < 64; e++) {
            float w = wr[e];
#pragma unroll
            for (int v = 0; v < Vv; v++) acc[v] += w * es[v * 64 + e];
        }
    }
    for (int v = 0; v < Vv; v++) g_table[(size_t)v * G3 + g] = acc[v];
}

__global__ void wconv_kernel(const float* __restrict__ Whh) {
    const size_t total = (size_t)32 * 96 * Hd;
    size_t stride = (size_t)gridDim.x * NTHREADS;
    for (size_t i = blockIdx.x * (size_t)NTHREADS + threadIdx.x; i < total; i += stride) {
        int k = (int)(i & 1023);
        int rf = (int)(i >> 10);
        int nt = rf / 96, p = rf - nt * 96;
        int gate = p >> 5;
        int j = nt * 32 + (p & 31);
        g_wf[i] = __float2half_rn(Whh[((size_t)gate * Hd + j) * Hd + k]);
    }
}

// ---------------- persistent recurrent kernel (gh only; R15-identical) ----------------
__device__ __forceinline__ void stage_issue_grp(uint32_t stg, int buf, int browg, int s, int gtid) {
    const char* agh = (const char*)(g_ah + ((size_t)(buf * Bb + browg)) * Hd + s * 128);
#pragma unroll
    for (int i = gtid; i < 512; i += 128) {
        int r = i >> 4, q = i & 15;
        cpa16(stg + r * SROW + q * 16, agh + (size_t)r * 2048 + q * 16);
    }
    CP_COMMIT();
}

__device__ void gh_tile(int t, int mt, int nt, char* smem, uint32_t smem_b,
                        const int* __restrict__ seq, const float* __restrict__ bhh) {
    const int tid = threadIdx.x;
    const int lane = tid & 31, wid = tid >> 5;
    const int mw = wid >> 2, nw = wid & 3;
    const int gtid = tid & 127;
    const int b0 = mt * 64, j0 = nt * 32;
    const int browg = b0 + mw * 32;
    const uint32_t grpA = smem_b + W_BYTES + (uint32_t)mw * 2 * GSTG;
    const int barid = 1 + mw;

    float acc[2][3][4];
#pragma unroll
    for (int mi = 0; mi < 2; mi++)
#pragma unroll
        for (int ni = 0; ni < 3; ni++)
#pragma unroll
            for (int q = 0; q < 4; q++) acc[mi][ni][q] = 0.f;

    const int arow = lane & 15;
    const int akoff = (lane >> 4) * 16;
    const int brow = lane & 7;
    const int bhalf = (lane >> 3) & 1;
    const int wrow4 = nw * 24 + ((lane >> 4) << 3) + brow;
    const uint32_t wrow4_b = smem_b + ((uint32_t)wrow4 << 11);
    const uint32_t wrow2_b = smem_b + ((uint32_t)(nw * 24 + 16 + brow) << 11);

    stage_issue_grp(grpA, t & 1, browg, 0, gtid);

    for (int s = 0; s < 8; s++) {
        CP_WAIT0();
        GBAR_SYNC(barid);
        if (s < 7) stage_issue_grp(grpA + ((s + 1) & 1) * GSTG, t & 1, browg, s + 1, gtid);
        uint32_t aB = grpA + (s & 1) * GSTG + arow * SROW + akoff;
#pragma unroll
        for (int ks = 0; ks < 8; ks++) {
            uint32_t ah0[4], ah1[4];
            ldsm_x4(ah0, aB + ks * 32);
            ldsm_x4(ah1, aB + 16 * SROW + ks * 32);
            const uint32_t chunk = (uint32_t)(((s * 8 + ks) << 1) | bhalf);
            uint32_t bh01[4], bh2[2];
            ldsm_x4(bh01, wrow4_b + (uint32_t)((chunk ^ (uint32_t)(wrow4 & 7)) << 4));
            ldsm_x2(bh2, wrow2_b + (uint32_t)((chunk ^ (uint32_t)brow) << 4));
            mma16816(acc[0][0], ah0, bh01);
            mma16816(acc[1][0], ah1, bh01);
            mma16816(acc[0][1], ah0, bh01 + 2);
            mma16816(acc[1][1], ah1, bh01 + 2);
            mma16816(acc[0][2], ah0, bh2);
            mma16816(acc[1][2], ah1, bh2);
        }
    }

    // ---- per-group epilogue: acc -> group eg -> fused GRU gating ----
    GBAR_SYNC(barid);
    float* eg = (float*)(smem + W_BYTES + mw * 2 * GSTG);
    const int crow = lane >> 2;
    const int ccol = (lane & 3) * 2;
#pragma unroll
    for (int mi = 0; mi < 2; mi++)
#pragma unroll
        for (int ni = 0; ni < 3; ni++) {
            int rr = mi * 16 + crow;
            int cc = nw * 24 + ni * 8 + ccol;
            eg[rr * 100 + cc]       = acc[mi][ni][0];
            eg[rr * 100 + cc + 1]   = acc[mi][ni][1];
            eg[(rr + 8) * 100 + cc]     = acc[mi][ni][2];
            eg[(rr + 8) * 100 + cc + 1] = acc[mi][ni][3];
        }
    GBAR_SYNC(barid);

    const int lrow = gtid >> 2;
    const int b = browg + lrow;
    const int jq = (tid & 3) * 8;
    const int jg = j0 + jq;
    const int tok = __ldg(&seq[b * Tt + t]);
    const float* tb = g_table + (size_t)tok * G3;
    const float* cp = g_ctxpart + (size_t)b * G3;
    const float* hold = g_hall + ((size_t)t * Bb + b) * Hd;
    float* hnew = g_hall + ((size_t)(t + 1) * Bb + b) * Hd;
    const int bufn = (t + 1) & 1;
    float hv[8];
#pragma unroll
    for (int q = 0; q < 2; q++) {
        float4 er = *(const float4*)&eg[lrow * 100 + jq + q * 4];
        float4 ez = *(const float4*)&eg[lrow * 100 + 32 + jq + q * 4];
        float4 en = *(const float4*)&eg[lrow * 100 + 64 + jq + q * 4];
        float4 t_r = __ldg((const float4*)&tb[jg + q * 4]);
        float4 t_z = __ldg((const float4*)&tb[Hd + jg + q * 4]);
        float4 t_n = __ldg((const float4*)&tb[2 * Hd + jg + q * 4]);
        float4 c_r = __ldg((const float4*)&cp[jg + q * 4]);
        float4 c_z = __ldg((const float4*)&cp[Hd + jg + q * 4]);
        float4 c_n = __ldg((const float4*)&cp[2 * Hd + jg + q * 4]);
        float4 b_r = __ldg((const float4*)&bhh[jg + q * 4]);
        float4 b_z = __ldg((const float4*)&bhh[Hd + jg + q * 4]);
        float4 b_n = __ldg((const float4*)&bhh[2 * Hd + jg + q * 4]);
        float4 h_o = __ldcg((const float4*)&hold[jg + q * 4]);
#pragma unroll
        for (int e = 0; e < 4; e++) {
            float r = sigm(((const float*)&t_r)[e] + ((const float*)&c_r)[e]
                           + ((const float*)&er)[e] + ((const float*)&b_r)[e]);
            float u = sigm(((const float*)&t_z)[e] + ((const float*)&c_z)[e]
                           + ((const float*)&ez)[e] + ((const float*)&b_z)[e]);
            float n = tanh_f(((const float*)&t_n)[e] + ((const float*)&c_n)[e]
                             + r * (((const float*)&en)[e] + ((const float*)&b_n)[e]));
            hv[q * 4 + e] = (1.f - u) * n + u * ((const float*)&h_o)[e];
        }
    }
    *(float4*)&hnew[jg]     = *(float4*)&hv[0];
    *(float4*)&hnew[jg + 4] = *(float4*)&hv[4];
    uint32_t uh[4];
#pragma unroll
    for (int q = 0; q < 4; q++) {
        __half2 ph = __halves2half2(__float2half_rn(hv[q * 2]), __float2half_rn(hv[q * 2 + 1]));
        uh[q] = *(uint32_t*)&ph;
    }
    *(uint4*)&g_ah[((size_t)(bufn * Bb + b)) * Hd + jg] = make_uint4(uh[0], uh[1], uh[2], uh[3]);
}

__global__ void __launch_bounds__(NTHREADS, 1)
gru_kernel(const int* __restrict__ seq, const float* __restrict__ bhh) {
    extern __shared__ char smem[];
    __shared__ unsigned base_s;
    const int tid = threadIdx.x;
    const int bid = blockIdx.x;
    const uint32_t smem_b = smem_u32_of(smem);
    const int mt = bid & 3, nt = bid >> 2;
    unsigned* cnt = &g_cnt[mt * 32];
    unsigned* ph = &g_ph[mt * 32];

    {
        const char* wsrc = (const char*)(g_wf + (size_t)nt * 96 * Hd);
        for (int i = tid; i < 12288; i += NTHREADS) {
            int p = i >> 7, c = i & 127;
            cpa16(smem_b + (p << 11) + (((c ^ (p & 7))) << 4), wsrc + (size_t)p * 2048 + c * 16);
        }
        CP_COMMIT();
    }
    if (tid == 0) {
        unsigned p;
        asm volatile("ld.acquire.gpu.u32 %0, [%1];" : "=r"(p) : "l"(ph) : "memory");
        base_s = p;
    }
    CP_WAIT0();
    __syncthreads();
    const unsigned base = base_s;

    for (int it = 0; it < Tt; ++it) {
        gh_tile(it, mt, nt, smem, smem_b, seq, bhh);
        gbar_grp(cnt, ph, base + (unsigned)it + 1u);
    }
}

// ---------------- bulk logits GEMM over the full h history ----------------
#define HSS 68
__global__ void __launch_bounds__(NTHREADS)
logits_kernel(const float* __restrict__ Wout, const float* __restrict__ bout,
              float* __restrict__ out) {
    __shared__ float hs[128 * HSS];
    __shared__ float wo[64 * HSS];
    const int cta = blockIdx.x;
    const int t = cta >> 1;
    const int b0 = (cta & 1) * 128;
    const float* hbase = g_hall + ((size_t)(t + 1) * Bb + b0) * Hd;
    const int tid = threadIdx.x;
    const int bl = tid >> 3;
    const int vq = tid & 7;

    unsigned long long acc[4][4];
#pragma unroll
    for (int r = 0; r < 4; r++)
#pragma unroll
        for (int i = 0; i < 4; i++) acc[r][i] = 0ull;

    for (int kc = 0; kc < Hd; kc += 64) {
        __syncthreads();
#pragma unroll
        for (int i = 0; i < 8; i++) {
            int idx = tid + 256 * i;
            int row = idx >> 4, kq = idx & 15;
            *(float4*)&hs[row * HSS + kq * 4] =
                __ldcg((const float4*)&hbase[(size_t)row * Hd + kc + kq * 4]);
        }
#pragma unroll
        for (int i = 0; i < 4; i++) {
            int idx = tid + 256 * i;
            int v = idx >> 4, kq = idx & 15;
            float4 w = __ldg((const float4*)&Wout[(size_t)v * Hd + kc + kq * 4]);
            wo[(kq * 4 + 0) * HSS + v] = w.x;
            wo[(kq * 4 + 1) * HSS + v] = w.y;
            wo[(kq * 4 + 2) * HSS + v] = w.z;
            wo[(kq * 4 + 3) * HSS + v] = w.w;
        }
        __syncthreads();
#pragma unroll 4
        for (int k = 0; k < 64; k++) {
            const float* wr = &wo[k * HSS + vq * 8];
            unsigned long long w0 = *(const unsigned long long*)&wr[0];
            unsigned long long w1 = *(const unsigned long long*)&wr[2];
            unsigned long long w2 = *(const unsigned long long*)&wr[4];
            unsigned long long w3 = *(const unsigned long long*)&wr[6];
#pragma unroll
            for (int r = 0; r < 4; r++) {
                float hvv = hs[(bl + r * 32) * HSS + k];
                unsigned long long hdp = pk2(hvv, hvv);
                fma2(acc[r][0], hdp, w0);
                fma2(acc[r][1], hdp, w1);
                fma2(acc[r][2], hdp, w2);
                fma2(acc[r][3], hdp, w3);
            }
        }
    }
#pragma unroll
    for (int r = 0; r < 4; r++) {
        int b = b0 + bl + r * 32;
        float* op = out + ((size_t)b * Tt + t) * Vv + vq * 8;
#pragma unroll
        for (int i = 0; i < 4; i++) {
            float2 v = unpk(acc[r][i]);
            float2 bo = *(const float2*)&bout[vq * 8 + i * 2];
            op[i * 2 + 0] = v.x + bo.x;
            op[i * 2 + 1] = v.y + bo.y;
        }
    }
}

// ---------------- launch ----------------
extern "C" void kernel_launch(void* const* d_in, const int* in_sizes, int n_in,
                              void* d_out, int out_size) {
    (void)in_sizes; (void)n_in; (void)out_size;
    const float* z    = (const float*)d_in[0];
    const float* c    = (const float*)d_in[1];
    const int*   seq  = (const int*)  d_in[2];
    const float* emb  = (const float*)d_in[3];
    const float* Wfch = (const float*)d_in[4];
    const float* bfch = (const float*)d_in[5];
    const float* Wih  = (const float*)d_in[6];
    const float* bih  = (const float*)d_in[7];
    const float* Whh  = (const float*)d_in[8];
    const float* bhh  = (const float*)d_in[9];
    const float* Wout = (const float*)d_in[10];
    const float* bout = (const float*)d_in[11];
    float* out = (float*)d_out;

    static int smem_set = 0;
    if (!smem_set) {
        cudaFuncSetAttribute(gru_kernel, cudaFuncAttributeMaxDynamicSharedMemorySize, SMEM_TOTAL);
        smem_set = 1;
    }

    ctx_kernel<<<384, NTHREADS>>>(z, c, Wih, bih);
    h0_kernel<<<128, NTHREADS>>>(z, c, Wfch, bfch);
    table_kernel<<<12, NTHREADS>>>(emb, Wih);
    wconv_kernel<<<128, NTHREADS>>>(Whh);
    gru_kernel<<<GRID, NTHREADS, SMEM_TOTAL>>>(seq, bhh);
    logits_kernel<<<Tt * 2, NTHREADS>>>(Wout, bout, out);
}

// round 17
// speedup vs baseline: 2.8705x; 1.0470x over previous
#include <cuda_runtime.h>
#include <cuda_fp16.h>
#include <cstdint>

#define Bb 256
#define Tt 256
#define Hd 1024
#define Ee 256
#define LC 320
#define EIN 576   // E + L + C
#define G3 3072
#define Vv 64

#define NGH 128
#define NLW 20                    // logits worker CTAs
#define GRID (NGH + NLW)          // 148 = 1 CTA per SM
#define NTHREADS 256

// smem: W resident [96][2048B] XOR-swizzled, then per-group double-buffered A stages.
#define W_BYTES 196608
#define SROW 272
#define GSTG 8704
#define SMEM_TOTAL (W_BYTES + 4 * GSTG)   // 231424

// ---------------- persistent device scratch ----------------
__device__ float g_ctxpart[Bb * G3];   // context @ W_ih[:,E:]^T + b_ih
__device__ float g_table[Vv * G3];     // emb @ W_ih[:,:E]^T
__device__ float g_hall[(size_t)(Tt + 1) * Bb * Hd];   // h history (slot 0 = h0)
__device__ __align__(16) __half g_ah[2 * Bb * Hd];     // fp16 h tiles [buf][b][k]
__device__ __align__(16) __half g_wf[32 * 96 * Hd];    // fp16 W [nt][p=gate*32+jl][k]
__device__ unsigned g_cnt[4 * 32];
__device__ unsigned g_ph[4 * 32];

// ---------------- helpers ----------------
__device__ __forceinline__ uint32_t smem_u32_of(const void* p) {
    uint32_t a;
    asm("{ .reg .u64 t; cvta.to.shared.u64 t, %1; cvt.u32.u64 %0, t; }" : "=r"(a) : "l"(p));
    return a;
}
__device__ __forceinline__ unsigned long long pk2(float x, float y) {
    unsigned long long r;
    asm("mov.b64 %0, {%1, %2};" : "=l"(r) : "f"(x), "f"(y));
    return r;
}
__device__ __forceinline__ float2 unpk(unsigned long long v) {
    float2 r;
    asm("mov.b64 {%0, %1}, %2;" : "=f"(r.x), "=f"(r.y) : "l"(v));
    return r;
}
__device__ __forceinline__ void fma2(unsigned long long& d, unsigned long long a, unsigned long long b) {
    asm("fma.rn.f32x2 %0, %1, %2, %0;" : "+l"(d) : "l"(a), "l"(b));
}
__device__ __forceinline__ float sigm(float x) { return 1.f / (1.f + __expf(-x)); }
__device__ __forceinline__ float tanh_f(float x) { return 2.f / (1.f + __expf(-2.f * x)) - 1.f; }

__device__ __forceinline__ void cpa16(uint32_t d, const void* s) {
    asm volatile("cp.async.cg.shared.global [%0], [%1], 16;" :: "r"(d), "l"(s) : "memory");
}
#define CP_COMMIT() asm volatile("cp.async.commit_group;" ::: "memory")
#define CP_WAIT0()  asm volatile("cp.async.wait_group 0;" ::: "memory")
#define GBAR_SYNC(id) asm volatile("bar.sync %0, 128;" :: "r"(id) : "memory")

__device__ __forceinline__ void ldsm_x4(uint32_t* r, uint32_t a) {
    asm volatile("ldmatrix.sync.aligned.m8n8.x4.shared.b16 {%0,%1,%2,%3}, [%4];"
                 : "=r"(r[0]), "=r"(r[1]), "=r"(r[2]), "=r"(r[3]) : "r"(a));
}
__device__ __forceinline__ void ldsm_x2(uint32_t* r, uint32_t a) {
    asm volatile("ldmatrix.sync.aligned.m8n8.x2.shared.b16 {%0,%1}, [%2];"
                 : "=r"(r[0]), "=r"(r[1]) : "r"(a));
}
__device__ __forceinline__ void mma16816(float* c, const uint32_t* a, const uint32_t* b) {
    asm volatile("mma.sync.aligned.m16n8k16.row.col.f32.f16.f16.f32 "
                 "{%0,%1,%2,%3}, {%4,%5,%6,%7}, {%8,%9}, {%0,%1,%2,%3};"
                 : "+f"(c[0]), "+f"(c[1]), "+f"(c[2]), "+f"(c[3])
                 : "r"(a[0]), "r"(a[1]), "r"(a[2]), "r"(a[3]), "r"(b[0]), "r"(b[1]));
}
__device__ __forceinline__ unsigned ld_acq(const unsigned* p) {
    unsigned v;
    asm volatile("ld.acquire.gpu.u32 %0, [%1];" : "=r"(v) : "l"(p) : "memory");
    return v;
}

// ---------------- per-mt group barrier (32 CTAs; no L1 flush) ----------------
__device__ __forceinline__ void gbar_grp(unsigned* cnt, unsigned* ph, unsigned target) {
    __syncthreads();
    if (threadIdx.x == 0) {
        unsigned n;
        asm volatile("atom.add.acq_rel.gpu.u32 %0, [%1], 1;"
                     : "=r"(n) : "l"(cnt) : "memory");
        if (n == 31) {
            *cnt = 0;
            asm volatile("st.release.gpu.u32 [%0], %1;"
                         :: "l"(ph), "r"(target) : "memory");
        } else {
            unsigned p;
            do { p = ld_acq(ph); } while ((int)(p - target) < 0);
        }
    }
    __syncthreads();
}

// ---------------- precompute kernels (parallelized) ----------------
__global__ void ctx_kernel(const float* __restrict__ z, const float* __restrict__ c,
                           const float* __restrict__ Wih, const float* __restrict__ bih) {
    __shared__ float cs[8 * LC];
    const int bc = blockIdx.x & 31;
    const int gk = blockIdx.x >> 5;
    for (int i = threadIdx.x; i < 8 * LC; i += NTHREADS) {
        int bb = i / LC, ii = i - bb * LC;
        int b = bc * 8 + bb;
        cs[i] = (ii < 256) ? z[b * 256 + ii] : c[b * 64 + (ii - 256)];
    }
    __syncthreads();
    const int g = threadIdx.x + gk * NTHREADS;
    float acc[8];
    float bi = __ldg(&bih[g]);
#pragma unroll
    for (int bb = 0; bb < 8; bb++) acc[bb] = bi;
    const float* wr = Wih + (size_t)g * EIN + Ee;
#pragma unroll 4
    for (int ii = 0; ii < LC; ii++) {
        float w = __ldg(&wr[ii]);
#pragma unroll
        for (int bb = 0; bb < 8; bb++) acc[bb] += w * cs[bb * LC + ii];
    }
#pragma unroll
    for (int bb = 0; bb < 8; bb++) g_ctxpart[(size_t)(bc * 8 + bb) * G3 + g] = acc[bb];
}

__global__ void h0_kernel(const float* __restrict__ z, const float* __restrict__ c,
                          const float* __restrict__ Wfch, const float* __restrict__ bfch) {
    __shared__ float cs[8 * LC];
    const int bc = blockIdx.x & 31;
    const int jk = blockIdx.x >> 5;
    for (int i = threadIdx.x; i < 8 * LC; i += NTHREADS) {
        int bb = i / LC, ii = i - bb * LC;
        int b = bc * 8 + bb;
        cs[i] = (ii < 256) ? z[b * 256 + ii] : c[b * 64 + (ii - 256)];
    }
    __syncthreads();
    const int j = threadIdx.x + jk * NTHREADS;
    float acc[8];
    float bj = __ldg(&bfch[j]);
#pragma unroll
    for (int bb = 0; bb < 8; bb++) acc[bb] = bj;
    const float* wr = Wfch + (size_t)j * LC;
#pragma unroll 4
    for (int ii = 0; ii < LC; ii++) {
        float w = __ldg(&wr[ii]);
#pragma unroll
        for (int bb = 0; bb < 8; bb++) acc[bb] += w * cs[bb * LC + ii];
    }
#pragma unroll
    for (int bb = 0; bb < 8; bb++) {
        int b = bc * 8 + bb;
        float v = acc[bb];
        g_hall[(size_t)b * Hd + j] = v;
        g_ah[(size_t)b * Hd + j] = __float2half_rn(v);
    }
}

__global__ void table_kernel(const float* __restrict__ emb, const float* __restrict__ Wih) {
    __shared__ float es[Vv * 64];
    int g = blockIdx.x * NTHREADS + threadIdx.x;
    float acc[Vv];
#pragma unroll
    for (int v = 0; v < Vv; v++) acc[v] = 0.f;
    for (int ec = 0; ec < Ee / 64; ec++) {
        __syncthreads();
        for (int i = threadIdx.x; i < Vv * 64; i += NTHREADS) {
            int v = i >> 6, el = i & 63;
            es[i] = emb[(size_t)v * Ee + ec * 64 + el];
        }
        __syncthreads();
        const float* wr = Wih + (size_t)g * EIN + ec * 64;
#pragma unroll 8
        for (int e = 0; e < 64; e++) {
            float w = wr[e];
#pragma unroll
            for (int v = 0; v < Vv; v++) acc[v] += w * es[v * 64 + e];
        }
    }
    for (int v = 0; v < Vv; v++) g_table[(size_t)v * G3 + g] = acc[v];
}

__global__ void wconv_kernel(const float* __restrict__ Whh) {
    const size_t total = (size_t)32 * 96 * Hd;
    size_t stride = (size_t)gridDim.x * NTHREADS;
    for (size_t i = blockIdx.x * (size_t)NTHREADS + threadIdx.x; i < total; i += stride) {
        int k = (int)(i & 1023);
        int rf = (int)(i >> 10);
        int nt = rf / 96, p = rf - nt * 96;
        int gate = p >> 5;
        int j = nt * 32 + (p & 31);
        g_wf[i] = __float2half_rn(Whh[((size_t)gate * Hd + j) * Hd + k]);
    }
}

// ---------------- gh tile (R16-identical) ----------------
__device__ __forceinline__ void stage_issue_grp(uint32_t stg, int buf, int browg, int s, int gtid) {
    const char* agh = (const char*)(g_ah + ((size_t)(buf * Bb + browg)) * Hd + s * 128);
#pragma unroll
    for (int i = gtid; i < 512; i += 128) {
        int r = i >> 4, q = i & 15;
        cpa16(stg + r * SROW + q * 16, agh + (size_t)r * 2048 + q * 16);
    }
    CP_COMMIT();
}

__device__ void gh_tile(int t, int mt, int nt, char* smem, uint32_t smem_b,
                        const int* __restrict__ seq, const float* __restrict__ bhh) {
    const int tid = threadIdx.x;
    const int lane = tid & 31, wid = tid >> 5;
    const int mw = wid >> 2, nw = wid & 3;
    const int gtid = tid & 127;
    const int b0 = mt * 64, j0 = nt * 32;
    const int browg = b0 + mw * 32;
    const uint32_t grpA = smem_b + W_BYTES + (uint32_t)mw * 2 * GSTG;
    const int barid = 1 + mw;

    float acc[2][3][4];
#pragma unroll
    for (int mi = 0; mi < 2; mi++)
#pragma unroll
        for (int ni = 0; ni < 3; ni++)
#pragma unroll
            for (int q = 0; q < 4; q++) acc[mi][ni][q] = 0.f;

    const int arow = lane & 15;
    const int akoff = (lane >> 4) * 16;
    const int brow = lane & 7;
    const int bhalf = (lane >> 3) & 1;
    const int wrow4 = nw * 24 + ((lane >> 4) << 3) + brow;
    const uint32_t wrow4_b = smem_b + ((uint32_t)wrow4 << 11);
    const uint32_t wrow2_b = smem_b + ((uint32_t)(nw * 24 + 16 + brow) << 11);

    stage_issue_grp(grpA, t & 1, browg, 0, gtid);

    for (int s = 0; s < 8; s++) {
        CP_WAIT0();
        GBAR_SYNC(barid);
        if (s < 7) stage_issue_grp(grpA + ((s + 1) & 1) * GSTG, t & 1, browg, s + 1, gtid);
        uint32_t aB = grpA + (s & 1) * GSTG + arow * SROW + akoff;
#pragma unroll
        for (int ks = 0; ks < 8; ks++) {
            uint32_t ah0[4], ah1[4];
            ldsm_x4(ah0, aB + ks * 32);
            ldsm_x4(ah1, aB + 16 * SROW + ks * 32);
            const uint32_t chunk = (uint32_t)(((s * 8 + ks) << 1) | bhalf);
            uint32_t bh01[4], bh2[2];
            ldsm_x4(bh01, wrow4_b + (uint32_t)((chunk ^ (uint32_t)(wrow4 & 7)) << 4));
            ldsm_x2(bh2, wrow2_b + (uint32_t)((chunk ^ (uint32_t)brow) << 4));
            mma16816(acc[0][0], ah0, bh01);
            mma16816(acc[1][0], ah1, bh01);
            mma16816(acc[0][1], ah0, bh01 + 2);
            mma16816(acc[1][1], ah1, bh01 + 2);
            mma16816(acc[0][2], ah0, bh2);
            mma16816(acc[1][2], ah1, bh2);
        }
    }

    GBAR_SYNC(barid);
    float* eg = (float*)(smem + W_BYTES + mw * 2 * GSTG);
    const int crow = lane >> 2;
    const int ccol = (lane & 3) * 2;
#pragma unroll
    for (int mi = 0; mi < 2; mi++)
#pragma unroll
        for (int ni = 0; ni < 3; ni++) {
            int rr = mi * 16 + crow;
            int cc = nw * 24 + ni * 8 + ccol;
            eg[rr * 100 + cc]       = acc[mi][ni][0];
            eg[rr * 100 + cc + 1]   = acc[mi][ni][1];
            eg[(rr + 8) * 100 + cc]     = acc[mi][ni][2];
            eg[(rr + 8) * 100 + cc + 1] = acc[mi][ni][3];
        }
    GBAR_SYNC(barid);

    const int gtid2 = tid & 127;
    const int lrow = gtid2 >> 2;
    const int b = browg + lrow;
    const int jq = (tid & 3) * 8;
    const int jg = j0 + jq;
    const int tok = __ldg(&seq[b * Tt + t]);
    const float* tb = g_table + (size_t)tok * G3;
    const float* cp = g_ctxpart + (size_t)b * G3;
    const float* hold = g_hall + ((size_t)t * Bb + b) * Hd;
    float* hnew = g_hall + ((size_t)(t + 1) * Bb + b) * Hd;
    const int bufn = (t + 1) & 1;
    float hv[8];
#pragma unroll
    for (int q = 0; q < 2; q++) {
        float4 er = *(const float4*)&eg[lrow * 100 + jq + q * 4];
        float4 ez = *(const float4*)&eg[lrow * 100 + 32 + jq + q * 4];
        float4 en = *(const float4*)&eg[lrow * 100 + 64 + jq + q * 4];
        float4 t_r = __ldg((const float4*)&tb[jg + q * 4]);
        float4 t_z = __ldg((const float4*)&tb[Hd + jg + q * 4]);
        float4 t_n = __ldg((const float4*)&tb[2 * Hd + jg + q * 4]);
        float4 c_r = __ldg((const float4*)&cp[jg + q * 4]);
        float4 c_z = __ldg((const float4*)&cp[Hd + jg + q * 4]);
        float4 c_n = __ldg((const float4*)&cp[2 * Hd + jg + q * 4]);
        float4 b_r = __ldg((const float4*)&bhh[jg + q * 4]);
        float4 b_z = __ldg((const float4*)&bhh[Hd + jg + q * 4]);
        float4 b_n = __ldg((const float4*)&bhh[2 * Hd + jg + q * 4]);
        float4 h_o = __ldcg((const float4*)&hold[jg + q * 4]);
#pragma unroll
        for (int e = 0; e < 4; e++) {
            float r = sigm(((const float*)&t_r)[e] + ((const float*)&c_r)[e]
                           + ((const float*)&er)[e] + ((const float*)&b_r)[e]);
            float u = sigm(((const float*)&t_z)[e] + ((const float*)&c_z)[e]
                           + ((const float*)&ez)[e] + ((const float*)&b_z)[e]);
            float n = tanh_f(((const float*)&t_n)[e] + ((const float*)&c_n)[e]
                             + r * (((const float*)&en)[e] + ((const float*)&b_n)[e]));
            hv[q * 4 + e] = (1.f - u) * n + u * ((const float*)&h_o)[e];
        }
    }
    *(float4*)&hnew[jg]     = *(float4*)&hv[0];
    *(float4*)&hnew[jg + 4] = *(float4*)&hv[4];
    uint32_t uh[4];
#pragma unroll
    for (int q = 0; q < 4; q++) {
        __half2 ph = __halves2half2(__float2half_rn(hv[q * 2]), __float2half_rn(hv[q * 2 + 1]));
        uh[q] = *(uint32_t*)&ph;
    }
    *(uint4*)&g_ah[((size_t)(bufn * Bb + b)) * Hd + jg] = make_uint4(uh[0], uh[1], uh[2], uh[3]);
}

// ---------------- logits tile (FFMA2; reads h slot t+1) ----------------
#define HSS 68
__device__ void logits_tile(int t, int b0, const float* __restrict__ Wout,
                            const float* __restrict__ bout, float* __restrict__ out,
                            float* hs, float* wo) {
    const float* hbase = g_hall + ((size_t)(t + 1) * Bb + b0) * Hd;
    const int tid = threadIdx.x;
    const int bl = tid >> 3;
    const int vq = tid & 7;

    unsigned long long acc[4][4];
#pragma unroll
    for (int r = 0; r < 4; r++)
#pragma unroll
        for (int i = 0; i < 4; i++) acc[r][i] = 0ull;

    for (int kc = 0; kc < Hd; kc += 64) {
        __syncthreads();
#pragma unroll
        for (int i = 0; i < 8; i++) {
            int idx = tid + 256 * i;
            int row = idx >> 4, kq = idx & 15;
            *(float4*)&hs[row * HSS + kq * 4] =
                __ldcg((const float4*)&hbase[(size_t)row * Hd + kc + kq * 4]);
        }
#pragma unroll
        for (int i = 0; i < 4; i++) {
            int idx = tid + 256 * i;
            int v = idx >> 4, kq = idx & 15;
            float4 w = __ldg((const float4*)&Wout[(size_t)v * Hd + kc + kq * 4]);
            wo[(kq * 4 + 0) * HSS + v] = w.x;
            wo[(kq * 4 + 1) * HSS + v] = w.y;
            wo[(kq * 4 + 2) * HSS + v] = w.z;
            wo[(kq * 4 + 3) * HSS + v] = w.w;
        }
        __syncthreads();
#pragma unroll 4
        for (int k = 0; k < 64; k++) {
            const float* wr = &wo[k * HSS + vq * 8];
            unsigned long long w0 = *(const unsigned long long*)&wr[0];
            unsigned long long w1 = *(const unsigned long long*)&wr[2];
            unsigned long long w2 = *(const unsigned long long*)&wr[4];
            unsigned long long w3 = *(const unsigned long long*)&wr[6];
#pragma unroll
            for (int r = 0; r < 4; r++) {
                float hvv = hs[(bl + r * 32) * HSS + k];
                unsigned long long hdp = pk2(hvv, hvv);
                fma2(acc[r][0], hdp, w0);
                fma2(acc[r][1], hdp, w1);
                fma2(acc[r][2], hdp, w2);
                fma2(acc[r][3], hdp, w3);
            }
        }
    }
#pragma unroll
    for (int r = 0; r < 4; r++) {
        int b = b0 + bl + r * 32;
        float* op = out + ((size_t)b * Tt + t) * Vv + vq * 8;
#pragma unroll
        for (int i = 0; i < 4; i++) {
            float2 v = unpk(acc[r][i]);
            float2 bo = *(const float2*)&bout[vq * 8 + i * 2];
            op[i * 2 + 0] = v.x + bo.x;
            op[i * 2 + 1] = v.y + bo.y;
        }
    }
}

// ---------------- fused persistent kernel: 128 gh CTAs + 20 logits workers ----------------
__global__ void __launch_bounds__(NTHREADS, 1)
gru_kernel(const int* __restrict__ seq, const float* __restrict__ bhh,
           const float* __restrict__ Wout, const float* __restrict__ bout,
           float* __restrict__ out) {
    extern __shared__ char smem[];
    __shared__ unsigned base_s;
    const int tid = threadIdx.x;
    const int bid = blockIdx.x;
    const uint32_t smem_b = smem_u32_of(smem);

    if (bid < NGH) {
        // ---------------- gh CTA ----------------
        const int mt = bid & 3, nt = bid >> 2;
        unsigned* cnt = &g_cnt[mt * 32];
        unsigned* ph = &g_ph[mt * 32];

        {
            const char* wsrc = (const char*)(g_wf + (size_t)nt * 96 * Hd);
            for (int i = tid; i < 12288; i += NTHREADS) {
                int p = i >> 7, c = i & 127;
                cpa16(smem_b + (p << 11) + (((c ^ (p & 7))) << 4), wsrc + (size_t)p * 2048 + c * 16);
            }
            CP_COMMIT();
        }
        if (tid == 0) base_s = ld_acq(ph);
        CP_WAIT0();
        __syncthreads();
        const unsigned base = base_s;

        for (int it = 0; it < Tt; ++it) {
            gh_tile(it, mt, nt, smem, smem_b, seq, bhh);
            gbar_grp(cnt, ph, base + (unsigned)it + 1u);
        }
    } else {
        // ---------------- logits worker ----------------
        const int w = bid - NGH;
        float* hs = (float*)smem;            // 128*HSS floats
        float* wo = hs + 128 * HSS;          // 64*HSS floats
        // base: phases are exact multiples of 256 at run start; mask off this run's progress
        if (tid == 0) base_s = ld_acq(&g_ph[0]) & ~255u;
        __syncthreads();
        const unsigned base = base_s;

        for (int i = w; i < 2 * Tt; i += NLW) {
            const int t = i >> 1;
            const int half = i & 1;          // half 0: mt 0,1 ; half 1: mt 2,3
            const unsigned tgt = base + (unsigned)t + 1u;
            if (tid == 0) {
                unsigned* p0 = &g_ph[(half * 2) * 32];
                unsigned* p1 = &g_ph[(half * 2 + 1) * 32];
                while ((int)(ld_acq(p0) - tgt) < 0) {}
                while ((int)(ld_acq(p1) - tgt) < 0) {}
            }
            __syncthreads();
            logits_tile(t, half * 128, Wout, bout, out, hs, wo);
            __syncthreads();
        }
    }
}

// ---------------- launch ----------------
extern "C" void kernel_launch(void* const* d_in, const int* in_sizes, int n_in,
                              void* d_out, int out_size) {
    (void)in_sizes; (void)n_in; (void)out_size;
    const float* z    = (const float*)d_in[0];
    const float* c    = (const float*)d_in[1];
    const int*   seq  = (const int*)  d_in[2];
    const float* emb  = (const float*)d_in[3];
    const float* Wfch = (const float*)d_in[4];
    const float* bfch = (const float*)d_in[5];
    const float* Wih  = (const float*)d_in[6];
    const float* bih  = (const float*)d_in[7];
    const float* Whh  = (const float*)d_in[8];
    const float* bhh  = (const float*)d_in[9];
    const float* Wout = (const float*)d_in[10];
    const float* bout = (const float*)d_in[11];
    float* out = (float*)d_out;

    static int smem_set = 0;
    if (!smem_set) {
        cudaFuncSetAttribute(gru_kernel, cudaFuncAttributeMaxDynamicSharedMemorySize, SMEM_TOTAL);
        smem_set = 1;
    }

    ctx_kernel<<<384, NTHREADS>>>(z, c, Wih, bih);
    h0_kernel<<<128, NTHREADS>>>(z, c, Wfch, bfch);
    table_kernel<<<12, NTHREADS>>>(emb, Wih);
    wconv_kernel<<<128, NTHREADS>>>(Whh);
    gru_kernel<<<GRID, NTHREADS, SMEM_TOTAL>>>(seq, bhh, Wout, bout, out);
}